// round 11
// baseline (speedup 1.0000x reference)
#include <cuda_runtime.h>
#include <cuda_bf16.h>
#include <mma.h>
#include <math.h>
#include <cstdint>

using namespace nvcuda;

#define B_DIM 8
#define L_DIM 1024
#define C_DIM 512
#define NP    1243
#define NTOK  2267
#define NH    8
#define HD    64
#define LN_EPS 1e-5f
#define OFF_MX 987

// ---------------- scratch ----------------
__device__ __align__(128) float g_P0[B_DIM * NP * C_DIM];
__device__ __align__(128) float g_P1[B_DIM * NP * C_DIM];
__device__ __align__(128) __nv_bfloat16 g_P0h[B_DIM * NP * C_DIM],    g_P0l[B_DIM * NP * C_DIM];
__device__ __align__(128) __nv_bfloat16 g_P2h[B_DIM * NP * C_DIM],    g_P2l[B_DIM * NP * C_DIM];
__device__ __align__(128) __nv_bfloat16 g_mh [B_DIM * L_DIM * C_DIM], g_ml [B_DIM * L_DIM * C_DIM];
__device__ __align__(128) __nv_bfloat16 g_Qh [B_DIM * L_DIM * C_DIM], g_Ql [B_DIM * L_DIM * C_DIM];
__device__ __align__(128) __nv_bfloat16 g_KVh[B_DIM * NTOK * 2 * C_DIM], g_KVl[B_DIM * NTOK * 2 * C_DIM];
__device__ __align__(128) __nv_bfloat16 g_Oh [B_DIM * L_DIM * C_DIM], g_Ol [B_DIM * L_DIM * C_DIM];
#define WSLOT (512 * 512)
__device__ __align__(128) __nv_bfloat16 g_Wth[7 * WSLOT + 512 * 1024], g_Wtl[7 * WSLOT + 512 * 1024];

// ---------------- helpers ----------------
__device__ __forceinline__ uint32_t smem_u32(const void* p) {
    uint32_t a;
    asm("{ .reg .u64 t; cvta.to.shared.u64 t, %1; cvt.u32.u64 %0, t; }" : "=r"(a) : "l"(p));
    return a;
}
__device__ __forceinline__ void cp16(uint32_t dst, const void* src) {
    asm volatile("cp.async.cg.shared.global [%0], [%1], 16;" :: "r"(dst), "l"(src) : "memory");
}
__device__ __forceinline__ void cp16z(uint32_t dst, const void* src, int sz) {
    asm volatile("cp.async.cg.shared.global [%0], [%1], 16, %2;" :: "r"(dst), "l"(src), "r"(sz) : "memory");
}
#define CP_COMMIT() asm volatile("cp.async.commit_group;" ::: "memory")
#define CP_WAIT1()  asm volatile("cp.async.wait_group 1;" ::: "memory")
#define CP_WAIT0()  asm volatile("cp.async.wait_group 0;" ::: "memory")

__device__ __forceinline__ uint32_t pk2(float a, float b) {
    __nv_bfloat162 t(__float2bfloat16(a), __float2bfloat16(b));
    return *(uint32_t*)&t;
}
__device__ __forceinline__ void split4(const float* v, uint2& hi, uint2& lo) {
    __nv_bfloat16 h[4]; float r[4];
#pragma unroll
    for (int u = 0; u < 4; u++) { h[u] = __float2bfloat16(v[u]); r[u] = v[u] - __bfloat162float(h[u]); }
    __nv_bfloat162 h01(h[0], h[1]), h23(h[2], h[3]);
    hi.x = *(uint32_t*)&h01; hi.y = *(uint32_t*)&h23;
    lo.x = pk2(r[0], r[1]);  lo.y = pk2(r[2], r[3]);
}

// ---------------- combined weight transpose + split ----------------
__global__ void wsplit8_kernel(const float* W0, const float* W1, const float* W2, const float* W3,
                               const float* W4, const float* W5, const float* W6, const float* W7,
                               __nv_bfloat16* __restrict__ Th, __nv_bfloat16* __restrict__ Tl)
{
    __shared__ float t[32][33];
    int slot = blockIdx.z;
    const float* W = (slot == 0) ? W0 : (slot == 1) ? W1 : (slot == 2) ? W2 : (slot == 3) ? W3 :
                     (slot == 4) ? W4 : (slot == 5) ? W5 : (slot == 6) ? W6 : W7;
    int N = (slot == 7) ? 1024 : 512;
    int n0 = blockIdx.x * 32, k0 = blockIdx.y * 32;
    if (n0 >= N) return;
    __nv_bfloat16* th = Th + (size_t)slot * WSLOT;
    __nv_bfloat16* tl = Tl + (size_t)slot * WSLOT;
    int tx = threadIdx.x, ty = threadIdx.y;
    for (int i = ty; i < 32; i += 8) t[i][tx] = W[(size_t)(k0 + i) * N + n0 + tx];
    __syncthreads();
    for (int i = ty; i < 32; i += 8) {
        float v = t[tx][i];
        __nv_bfloat16 h = __float2bfloat16(v);
        size_t o = (size_t)(n0 + i) * 512 + k0 + tx;
        th[o] = h; tl[o] = __float2bfloat16(v - __bfloat162float(h));
    }
}

__global__ void mcvt_kernel(const float* __restrict__ m, __nv_bfloat16* __restrict__ mh,
                            __nv_bfloat16* __restrict__ ml)
{
    int i = (blockIdx.x * blockDim.x + threadIdx.x) * 4;
    if (i >= B_DIM * L_DIM * C_DIM) return;
    float4 v4 = *(const float4*)&m[i];
    float v[4] = { v4.x, v4.y, v4.z, v4.w };
    uint2 hi, lo;
    split4(v, hi, lo);
    *(uint2*)&mh[i] = hi;
    *(uint2*)&ml[i] = lo;
}

// ---------------- pooling (avg + max merged) ----------------
__global__ void pool_all_kernel(const float* __restrict__ x, float* __restrict__ P0,
                                __nv_bfloat16* __restrict__ Ph, __nv_bfloat16* __restrict__ Pl)
{
    int tok = blockIdx.x, b = blockIdx.y, c = threadIdx.x;
    float v;
    if (tok < 987) {
        int t = tok, n;
        if      (t < 441) { n = 21; }
        else if (t < 697) { n = 16; t -= 441; }
        else if (t < 866) { n = 13; t -= 697; }
        else              { n = 11; t -= 866; }
        int p = t / n, q = t - p * n;
        int hs = (p * 64) / n, he = ((p + 1) * 64 + n - 1) / n;
        int ws = (q * 64) / n, we = ((q + 1) * 64 + n - 1) / n;
        float s = 0.f;
        for (int h = hs; h < he; h++) {
            const float* xr = x + (((size_t)b * 4096) + (size_t)h * 64) * C_DIM + c;
            for (int w = ws; w < we; w++) s += xr[(size_t)w * C_DIM];
        }
        v = s / (float)((he - hs) * (we - ws));
    } else {
        int t = tok - 987;
        int p = t >> 4, q = t & 15;
        float mx = -1e30f;
        for (int h = p * 4; h < p * 4 + 4; h++) {
            const float* xr = x + (((size_t)b * 4096) + (size_t)h * 64) * C_DIM + c;
            for (int w = q * 4; w < q * 4 + 4; w++) mx = fmaxf(mx, xr[(size_t)w * C_DIM]);
        }
        v = mx;
    }
    size_t o = ((size_t)b * NP + tok) * C_DIM + c;
    P0[o] = v;
    __nv_bfloat16 h16 = __float2bfloat16(v);
    Ph[o] = h16; Pl[o] = __float2bfloat16(v - __bfloat162float(h16));
}

// =====================================================================
// GEMM mainloop (bf16x3, 128x128 tile, K=512)
// =====================================================================
#define STG0    4096
#define STG_SZ  40960
#define TG_SMEM (4096 + 2 * 40960)
#define CPITCH  136

// cgemm: conv-res (0..4) + Wq (5). grid = (4, 143).
__global__ __launch_bounds__(256) void cgemm_kernel(
    const __nv_bfloat16* __restrict__ P0h, const __nv_bfloat16* __restrict__ P0l,
    const __nv_bfloat16* __restrict__ mh,  const __nv_bfloat16* __restrict__ ml,
    const __nv_bfloat16* __restrict__ Wth, const __nv_bfloat16* __restrict__ Wtl,
    const float* bp0, const float* bp1, const float* bp2, const float* bp3, const float* bp4,
    const float* __restrict__ P0, float* __restrict__ P1,
    __nv_bfloat16* __restrict__ Qh, __nv_bfloat16* __restrict__ Ql)
{
    extern __shared__ char sm_raw[];
    const __nv_bfloat16** aptrs = (const __nv_bfloat16**)(sm_raw + 16);
    uint32_t sb = smem_u32(sm_raw);

    int tid = threadIdx.x;
    int ti = blockIdx.y;
    int branch, tstart;
    if      (ti < 28) { branch = 0; tstart = 0;  }
    else if (ti < 44) { branch = 1; tstart = 28; }
    else if (ti < 55) { branch = 2; tstart = 44; }
    else if (ti < 63) { branch = 3; tstart = 55; }
    else if (ti < 79) { branch = 4; tstart = 63; }
    else              { branch = 5; tstart = 79; }
    const int npx_t[6]  = { 441, 256, 169, 121, 256, 0 };
    const int toff_t[6] = { 0, 441, 697, 866, 987, 0 };
    int npx = npx_t[branch], toffc = toff_t[branch];
    int M = (branch < 5) ? 8 * npx : 8192;
    int brow = (ti - tstart) * 128;
    int bcol = blockIdx.x * 128;
    const float* bias = (branch == 0) ? bp0 : (branch == 1) ? bp1 : (branch == 2) ? bp2 :
                        (branch == 3) ? bp3 : (branch == 4) ? bp4 : nullptr;
    const __nv_bfloat16* Bh = Wth + (size_t)branch * WSLOT;
    const __nv_bfloat16* Bl = Wtl + (size_t)branch * WSLOT;

    if (tid < 128) {
        int arow = brow + tid;
        if (arow >= M) arow = M - 1;
        const __nv_bfloat16 *ph, *pl;
        if (branch < 5) {
            int b = arow / npx, t = arow - (arow / npx) * npx;
            size_t o = ((size_t)b * NP + toffc + t) * 512;
            ph = P0h + o; pl = P0l + o;
        } else {
            size_t o = (size_t)arow * 512;
            ph = mh + o; pl = ml + o;
        }
        aptrs[tid] = ph; aptrs[128 + tid] = pl;
    }
    __syncthreads();

    int wid = tid >> 5;
    int wm = wid & 1, wn = wid >> 1;

    wmma::fragment<wmma::accumulator, 16, 16, 16, float> acc[4][2];
#pragma unroll
    for (int mi = 0; mi < 4; mi++)
#pragma unroll
        for (int ni = 0; ni < 2; ni++)
            wmma::fill_fragment(acc[mi][ni], 0.f);

    {
        uint32_t st = sb + STG0;
#pragma unroll
        for (int w = 0; w < 8; w++) {
            int ci = tid + w * 256;
            int region = ci >> 9, idx = ci & 511;
            int row = idx >> 2, ch = idx & 3;
            const __nv_bfloat16* src;
            if (region < 2) src = aptrs[region * 128 + row] + ch * 8;
            else            src = ((region == 2) ? Bh : Bl) + (size_t)(bcol + row) * 512 + ch * 8;
            cp16(st + region * 10240 + row * 80 + ch * 16, src);
        }
        CP_COMMIT();
    }

    for (int j = 0; j < 16; j++) {
        if (j + 1 < 16) {
            uint32_t st = sb + STG0 + ((j + 1) & 1) * STG_SZ;
            int koff = (j + 1) * 32;
#pragma unroll
            for (int w = 0; w < 8; w++) {
                int ci = tid + w * 256;
                int region = ci >> 9, idx = ci & 511;
                int row = idx >> 2, ch = idx & 3;
                const __nv_bfloat16* src;
                if (region < 2) src = aptrs[region * 128 + row] + koff + ch * 8;
                else            src = ((region == 2) ? Bh : Bl) + (size_t)(bcol + row) * 512 + koff + ch * 8;
                cp16(st + region * 10240 + row * 80 + ch * 16, src);
            }
            CP_COMMIT();
            CP_WAIT1();
        } else {
            CP_WAIT0();
        }
        __syncthreads();

        const __nv_bfloat16* st = (const __nv_bfloat16*)(sm_raw + STG0 + (j & 1) * STG_SZ);
        const __nv_bfloat16* As_h = st;
        const __nv_bfloat16* As_l = st + 5120;
        const __nv_bfloat16* Bs_h = st + 10240;
        const __nv_bfloat16* Bs_l = st + 15360;

#pragma unroll
        for (int kk = 0; kk < 2; kk++) {
            wmma::fragment<wmma::matrix_a, 16, 16, 16, __nv_bfloat16, wmma::row_major> fah[4], fal[4];
            wmma::fragment<wmma::matrix_b, 16, 16, 16, __nv_bfloat16, wmma::col_major> fbh[2], fbl[2];
#pragma unroll
            for (int mi = 0; mi < 4; mi++) {
                int r = wm * 64 + mi * 16;
                wmma::load_matrix_sync(fah[mi], As_h + r * 40 + kk * 16, 40);
                wmma::load_matrix_sync(fal[mi], As_l + r * 40 + kk * 16, 40);
            }
#pragma unroll
            for (int ni = 0; ni < 2; ni++) {
                int c = wn * 32 + ni * 16;
                wmma::load_matrix_sync(fbh[ni], Bs_h + c * 40 + kk * 16, 40);
                wmma::load_matrix_sync(fbl[ni], Bs_l + c * 40 + kk * 16, 40);
            }
#pragma unroll
            for (int mi = 0; mi < 4; mi++)
#pragma unroll
                for (int ni = 0; ni < 2; ni++) {
                    wmma::mma_sync(acc[mi][ni], fah[mi], fbh[ni], acc[mi][ni]);
                    wmma::mma_sync(acc[mi][ni], fah[mi], fbl[ni], acc[mi][ni]);
                    wmma::mma_sync(acc[mi][ni], fal[mi], fbh[ni], acc[mi][ni]);
                }
        }
        __syncthreads();
    }

    float* Cs = (float*)(sm_raw + STG0);
#pragma unroll
    for (int mi = 0; mi < 4; mi++)
#pragma unroll
        for (int ni = 0; ni < 2; ni++)
            wmma::store_matrix_sync(Cs + (wm * 64 + mi * 16) * CPITCH + wn * 32 + ni * 16,
                                    acc[mi][ni], CPITCH, wmma::mem_row_major);
    __syncthreads();

    int lane = tid & 31, wrow = tid >> 5;
    for (int rr = wrow; rr < 128; rr += 8) {
        int r = brow + rr;
        if (r >= M) continue;
        int col0 = lane * 4;
        float4 o = *(float4*)&Cs[rr * CPITCH + col0];
        int col = bcol + col0;
        if (branch < 5) {
            o.x += bias[col];     o.y += bias[col + 1];
            o.z += bias[col + 2]; o.w += bias[col + 3];
            int b = r / npx, t = r - (r / npx) * npx;
            size_t g = ((size_t)b * NP + toffc + t) * 512;
            float4 rv = *(const float4*)&P0[g + col];
            o.x += rv.x; o.y += rv.y; o.z += rv.z; o.w += rv.w;
            *(float4*)&P1[g + col] = o;
        } else {
            size_t g = (size_t)r * 512 + col;
            float vv[4] = { o.x, o.y, o.z, o.w };
            uint2 hi, lo;
            split4(vv, hi, lo);
            *(uint2*)&Qh[g] = hi;
            *(uint2*)&Ql[g] = lo;
        }
    }
}

// tgemm: generic (Wkv mode 2, Wp mode 0)
__global__ __launch_bounds__(256) void tgemm_kernel(
    const __nv_bfloat16* __restrict__ Ah, const __nv_bfloat16* __restrict__ Al,
    const __nv_bfloat16* __restrict__ A2h, const __nv_bfloat16* __restrict__ A2l,
    const __nv_bfloat16* __restrict__ Bh, const __nv_bfloat16* __restrict__ Bl,
    const float* __restrict__ bias,
    float* __restrict__ Cout,
    __nv_bfloat16* __restrict__ outh, __nv_bfloat16* __restrict__ outl,
    int M, int N, int mode)
{
    extern __shared__ char sm_raw[];
    const __nv_bfloat16** aptrs = (const __nv_bfloat16**)(sm_raw + 16);
    uint32_t sb = smem_u32(sm_raw);

    int tid = threadIdx.x;
    int brow = blockIdx.y * 128, bcol = blockIdx.x * 128;

    if (tid < 128) {
        int arow = brow + tid;
        if (arow >= M) arow = M - 1;
        const __nv_bfloat16 *ph, *pl;
        if (mode == 0) {
            size_t o = (size_t)arow * 512; ph = Ah + o; pl = Al + o;
        } else {
            int b = arow / NTOK, t = arow - (arow / NTOK) * NTOK;
            if (t < NP) { size_t o = ((size_t)b * NP + t) * 512; ph = Ah + o; pl = Al + o; }
            else        { size_t o = ((size_t)b * L_DIM + (t - NP)) * 512; ph = A2h + o; pl = A2l + o; }
        }
        aptrs[tid] = ph; aptrs[128 + tid] = pl;
    }
    __syncthreads();

    int wid = tid >> 5;
    int wm = wid & 1, wn = wid >> 1;

    wmma::fragment<wmma::accumulator, 16, 16, 16, float> acc[4][2];
#pragma unroll
    for (int mi = 0; mi < 4; mi++)
#pragma unroll
        for (int ni = 0; ni < 2; ni++)
            wmma::fill_fragment(acc[mi][ni], 0.f);

    {
        uint32_t st = sb + STG0;
#pragma unroll
        for (int w = 0; w < 8; w++) {
            int ci = tid + w * 256;
            int region = ci >> 9, idx = ci & 511;
            int row = idx >> 2, ch = idx & 3;
            const __nv_bfloat16* src;
            if (region < 2) src = aptrs[region * 128 + row] + ch * 8;
            else            src = ((region == 2) ? Bh : Bl) + (size_t)(bcol + row) * 512 + ch * 8;
            cp16(st + region * 10240 + row * 80 + ch * 16, src);
        }
        CP_COMMIT();
    }

    for (int j = 0; j < 16; j++) {
        if (j + 1 < 16) {
            uint32_t st = sb + STG0 + ((j + 1) & 1) * STG_SZ;
            int koff = (j + 1) * 32;
#pragma unroll
            for (int w = 0; w < 8; w++) {
                int ci = tid + w * 256;
                int region = ci >> 9, idx = ci & 511;
                int row = idx >> 2, ch = idx & 3;
                const __nv_bfloat16* src;
                if (region < 2) src = aptrs[region * 128 + row] + koff + ch * 8;
                else            src = ((region == 2) ? Bh : Bl) + (size_t)(bcol + row) * 512 + koff + ch * 8;
                cp16(st + region * 10240 + row * 80 + ch * 16, src);
            }
            CP_COMMIT();
            CP_WAIT1();
        } else {
            CP_WAIT0();
        }
        __syncthreads();

        const __nv_bfloat16* st = (const __nv_bfloat16*)(sm_raw + STG0 + (j & 1) * STG_SZ);
        const __nv_bfloat16* As_h = st;
        const __nv_bfloat16* As_l = st + 5120;
        const __nv_bfloat16* Bs_h = st + 10240;
        const __nv_bfloat16* Bs_l = st + 15360;

#pragma unroll
        for (int kk = 0; kk < 2; kk++) {
            wmma::fragment<wmma::matrix_a, 16, 16, 16, __nv_bfloat16, wmma::row_major> fah[4], fal[4];
            wmma::fragment<wmma::matrix_b, 16, 16, 16, __nv_bfloat16, wmma::col_major> fbh[2], fbl[2];
#pragma unroll
            for (int mi = 0; mi < 4; mi++) {
                int r = wm * 64 + mi * 16;
                wmma::load_matrix_sync(fah[mi], As_h + r * 40 + kk * 16, 40);
                wmma::load_matrix_sync(fal[mi], As_l + r * 40 + kk * 16, 40);
            }
#pragma unroll
            for (int ni = 0; ni < 2; ni++) {
                int c = wn * 32 + ni * 16;
                wmma::load_matrix_sync(fbh[ni], Bs_h + c * 40 + kk * 16, 40);
                wmma::load_matrix_sync(fbl[ni], Bs_l + c * 40 + kk * 16, 40);
            }
#pragma unroll
            for (int mi = 0; mi < 4; mi++)
#pragma unroll
                for (int ni = 0; ni < 2; ni++) {
                    wmma::mma_sync(acc[mi][ni], fah[mi], fbh[ni], acc[mi][ni]);
                    wmma::mma_sync(acc[mi][ni], fah[mi], fbl[ni], acc[mi][ni]);
                    wmma::mma_sync(acc[mi][ni], fal[mi], fbh[ni], acc[mi][ni]);
                }
        }
        __syncthreads();
    }

    float* Cs = (float*)(sm_raw + STG0);
#pragma unroll
    for (int mi = 0; mi < 4; mi++)
#pragma unroll
        for (int ni = 0; ni < 2; ni++)
            wmma::store_matrix_sync(Cs + (wm * 64 + mi * 16) * CPITCH + wn * 32 + ni * 16,
                                    acc[mi][ni], CPITCH, wmma::mem_row_major);
    __syncthreads();

    int lane = tid & 31, wrow = tid >> 5;
    for (int rr = wrow; rr < 128; rr += 8) {
        int r = brow + rr;
        if (r >= M) continue;
        int col0 = lane * 4;
        float4 o = *(float4*)&Cs[rr * CPITCH + col0];
        int col = bcol + col0;
        if (bias) {
            o.x += bias[col];     o.y += bias[col + 1];
            o.z += bias[col + 2]; o.w += bias[col + 3];
        }
        if (outh) {
            size_t g = (size_t)r * N + col;
            float vv[4] = { o.x, o.y, o.z, o.w };
            uint2 hi, lo;
            split4(vv, hi, lo);
            *(uint2*)&outh[g] = hi;
            *(uint2*)&outl[g] = lo;
        } else {
            *(float4*)&Cout[(size_t)r * N + col] = o;
        }
    }
}

// ---------------- mx copy (SMEM-tiled transpose) ----------------
__global__ void mx_copy_kernel(const float* __restrict__ P1, float* __restrict__ out2)
{
    __shared__ float t[32][33];
    int b = blockIdx.z;
    int t0 = blockIdx.x * 32;
    int c0 = blockIdx.y * 32;
    int tx = threadIdx.x, ty = threadIdx.y;
    for (int i = ty; i < 32; i += 8)
        t[i][tx] = P1[(((size_t)b * NP) + OFF_MX + t0 + i) * 512 + c0 + tx];
    __syncthreads();
    for (int i = ty; i < 32; i += 8)
        out2[(((size_t)b * 512) + c0 + i) * 256 + t0 + tx] = t[tx][i];
}

// ---------------- layernorm -> bf16 hi/lo ----------------
__global__ void ln_kernel(const float* __restrict__ X, const float* __restrict__ g,
                          const float* __restrict__ be,
                          __nv_bfloat16* __restrict__ Yh, __nv_bfloat16* __restrict__ Yl)
{
    int row = blockIdx.x, tid = threadIdx.x;
    float4 v = ((const float4*)(X + (size_t)row * C_DIM))[tid];
    float s  = v.x + v.y + v.z + v.w;
    float s2 = v.x * v.x + v.y * v.y + v.z * v.z + v.w * v.w;
#pragma unroll
    for (int o = 16; o >= 1; o >>= 1) {
        s  += __shfl_xor_sync(0xffffffffu, s,  o);
        s2 += __shfl_xor_sync(0xffffffffu, s2, o);
    }
    __shared__ float ws[4], ws2[4];
    int wid = tid >> 5, lane = tid & 31;
    if (lane == 0) { ws[wid] = s; ws2[wid] = s2; }
    __syncthreads();
    float ts = ws[0] + ws[1] + ws[2] + ws[3], ts2 = ws2[0] + ws2[1] + ws2[2] + ws2[3];
    float mean = ts * (1.f / C_DIM);
    float var  = ts2 * (1.f / C_DIM) - mean * mean;
    float rstd = rsqrtf(var + LN_EPS);
    float4 gg = ((const float4*)g)[tid], bb = ((const float4*)be)[tid];
    float y[4] = { (v.x - mean) * rstd * gg.x + bb.x, (v.y - mean) * rstd * gg.y + bb.y,
                   (v.z - mean) * rstd * gg.z + bb.z, (v.w - mean) * rstd * gg.w + bb.w };
    size_t o = (size_t)row * C_DIM + tid * 4;
    uint2 hi, lo;
    split4(y, hi, lo);
    *(uint2*)&Yh[o] = hi;
    *(uint2*)&Yl[o] = lo;
}

// =====================================================================
// wmma flash attention: 64-q tile, 256 thr, fragment-resident O AND Q,
// rowmap rescale, K double-buffered, V single-buffered.
// SMEM = 109,824 B -> 2 blocks/SM.
// =====================================================================
#define QP 72
#define SP 68
#define ATT_SMEM (10 * 64 * QP * 2 + 64 * SP * 4 + 256)   // 109824

__global__ __launch_bounds__(256, 2) void attn_wmma_kernel(
    const __nv_bfloat16* __restrict__ Qh, const __nv_bfloat16* __restrict__ Ql,
    const __nv_bfloat16* __restrict__ KVh, const __nv_bfloat16* __restrict__ KVl,
    __nv_bfloat16* __restrict__ Oh, __nv_bfloat16* __restrict__ Ol)
{
    extern __shared__ char smc[];
    __nv_bfloat16* sQh  = (__nv_bfloat16*)smc;
    __nv_bfloat16* sQl  = sQh + 64 * QP;
    __nv_bfloat16* sK_h[2] = { sQl + 64 * QP,        sQl + 3 * 64 * QP };
    __nv_bfloat16* sK_l[2] = { sQl + 2 * 64 * QP,    sQl + 4 * 64 * QP };
    __nv_bfloat16* sVh  = sQl + 5 * 64 * QP;
    __nv_bfloat16* sVl  = sVh + 64 * QP;
    __nv_bfloat16* sPh  = sVl + 64 * QP;
    __nv_bfloat16* sPl  = sPh + 64 * QP;
    float* Ss = (float*)(sPl + 64 * QP);   // [64][68]
    float* alphaSm = Ss + 64 * SP;         // [64]

    int tid = threadIdx.x;
    int b = blockIdx.z, h = blockIdx.y, l0 = blockIdx.x * 64;
    int warp = tid >> 5;
    int wm = (warp & 1) * 32, wn = (warp >> 1) * 16;
    int ty = tid >> 4, tx = tid & 15;
    const float scale = 0.125f;

    size_t kvbase = (size_t)b * NTOK * 1024 + h * 64;

    // ---- rowmap init: learn fragment element -> row mapping ----
    for (int i = tid; i < 64 * SP; i += 256) Ss[i] = (float)(i / SP);
    __syncthreads();
    wmma::fragment<wmma::accumulator, 16, 16, 16, float> of[2];
    int rowidx0[8];
    {
        wmma::load_matrix_sync(of[0], Ss + wm * SP + wn, SP, wmma::mem_row_major);
#pragma unroll
        for (int e = 0; e < 8; e++) rowidx0[e] = (int)of[0].x[e];
        wmma::fill_fragment(of[0], 0.f);
        wmma::fill_fragment(of[1], 0.f);
    }
    __syncthreads();   // rowmap reads done before any cp.async overwrites Ss region? (Ss not a cp target; barrier orders vs first S store)

    // group 1: Q (hi/lo) + K tile 0
    {
#pragma unroll
        for (int w = 0; w < 4; w++) {
            int ci = tid + w * 256;
            int arr = ci >> 9, idx = ci & 511;
            int row = idx >> 3, ch = idx & 7;
            const __nv_bfloat16* src = (arr ? Ql : Qh) +
                (((size_t)b * L_DIM) + l0 + row) * 512 + h * 64 + ch * 8;
            cp16(smem_u32((arr ? sQl : sQh) + row * QP + ch * 8), src);
        }
#pragma unroll
        for (int w = 0; w < 4; w++) {
            int ci = tid + w * 256;
            int arr = ci >> 9, idx = ci & 511;
            int row = idx >> 3, ch = idx & 7;
            const __nv_bfloat16* src = (arr ? KVl : KVh) + kvbase + (size_t)row * 1024 + ch * 8;
            cp16(smem_u32((arr ? sK_l[0] : sK_h[0]) + row * QP + ch * 8), src);
        }
        CP_COMMIT();
    }
    // group 2: V tile 0
    {
#pragma unroll
        for (int w = 0; w < 4; w++) {
            int ci = tid + w * 256;
            int arr = ci >> 9, idx = ci & 511;
            int row = idx >> 3, ch = idx & 7;
            const __nv_bfloat16* src = (arr ? KVl : KVh) + kvbase + (size_t)row * 1024 + 512 + ch * 8;
            cp16(smem_u32((arr ? sVl : sVh) + row * QP + ch * 8), src);
        }
        CP_COMMIT();
    }

    // ---- Q fragments: load once, reuse for all 36 key tiles ----
    CP_WAIT1();            // Q + K0 landed; V0 may float
    __syncthreads();
    wmma::fragment<wmma::matrix_a, 16, 16, 16, __nv_bfloat16, wmma::row_major> fQh[4][2], fQl[4][2];
#pragma unroll
    for (int k = 0; k < 4; k++)
#pragma unroll
        for (int mi = 0; mi < 2; mi++) {
            wmma::load_matrix_sync(fQh[k][mi], sQh + (wm + mi * 16) * QP + k * 16, QP);
            wmma::load_matrix_sync(fQl[k][mi], sQl + (wm + mi * 16) * QP + k * 16, QP);
        }

    float mrow[4] = { -1e30f, -1e30f, -1e30f, -1e30f };
    float lrow[4] = {};

    for (int kt = 0; kt < 36; kt++) {
        int kbase = kt * 64;
        int kb = kt & 1;
        CP_WAIT1();            // K(t) ready; V(t) may be in flight
        __syncthreads();

        // prefetch K(t+1)
        if (kt + 1 < 36) {
            int nkb = (kt + 1) & 1;
#pragma unroll
            for (int w = 0; w < 4; w++) {
                int ci = tid + w * 256;
                int arr = ci >> 9, idx = ci & 511;
                int row = idx >> 3, ch = idx & 7;
                int kg = kbase + 64 + row;
                const __nv_bfloat16* src = (arr ? KVl : KVh) + kvbase
                    + (size_t)(kg < NTOK ? kg : 0) * 1024 + ch * 8;
                cp16z(smem_u32((arr ? sK_l[nkb] : sK_h[nkb]) + row * QP + ch * 8),
                      src, (kg < NTOK) ? 16 : 0);
            }
            CP_COMMIT();
        }

        // ---- S = Q K^T (Q from registers) ----
        {
            wmma::fragment<wmma::accumulator, 16, 16, 16, float> sf[2];
            wmma::fill_fragment(sf[0], 0.f);
            wmma::fill_fragment(sf[1], 0.f);
#pragma unroll
            for (int k = 0; k < 4; k++) {
                wmma::fragment<wmma::matrix_b, 16, 16, 16, __nv_bfloat16, wmma::col_major> fbh, fbl;
                wmma::load_matrix_sync(fbh, sK_h[kb] + wn * QP + k * 16, QP);
                wmma::load_matrix_sync(fbl, sK_l[kb] + wn * QP + k * 16, QP);
#pragma unroll
                for (int mi = 0; mi < 2; mi++) {
                    wmma::mma_sync(sf[mi], fQh[k][mi], fbh, sf[mi]);
                    wmma::mma_sync(sf[mi], fQh[k][mi], fbl, sf[mi]);
                    wmma::mma_sync(sf[mi], fQl[k][mi], fbh, sf[mi]);
                }
            }
            wmma::store_matrix_sync(Ss + wm * SP + wn, sf[0], SP, wmma::mem_row_major);
            wmma::store_matrix_sync(Ss + (wm + 16) * SP + wn, sf[1], SP, wmma::mem_row_major);
        }
        __syncthreads();

        // ---- scalar online softmax ----
        float s[4][4], tmax[4];
#pragma unroll
        for (int i = 0; i < 4; i++) {
            float4 sv = *(const float4*)&Ss[(ty * 4 + i) * SP + tx * 4];
            s[i][0] = sv.x; s[i][1] = sv.y; s[i][2] = sv.z; s[i][3] = sv.w;
            tmax[i] = -1e30f;
#pragma unroll
            for (int j = 0; j < 4; j++) {
                int cg = kbase + tx * 4 + j;
                s[i][j] = (cg < NTOK) ? s[i][j] * scale : -1e30f;
                tmax[i] = fmaxf(tmax[i], s[i][j]);
            }
        }
#pragma unroll
        for (int i = 0; i < 4; i++)
#pragma unroll
            for (int o = 8; o >= 1; o >>= 1)
                tmax[i] = fmaxf(tmax[i], __shfl_xor_sync(0xffffffffu, tmax[i], o));
        float alpha[4], rsum[4];
#pragma unroll
        for (int i = 0; i < 4; i++) {
            float mnew = fmaxf(mrow[i], tmax[i]);
            alpha[i] = __expf(mrow[i] - mnew);
            mrow[i] = mnew;
            float rs = 0.f;
#pragma unroll
            for (int j = 0; j < 4; j++) {
                float p = (s[i][j] > -1e29f) ? __expf(s[i][j] - mnew) : 0.f;
                s[i][j] = p; rs += p;
            }
            rsum[i] = rs;
            lrow[i] = lrow[i] * alpha[i];
        }
#pragma unroll
        for (int i = 0; i < 4; i++) {
#pragma unroll
            for (int o = 8; o >= 1; o >>= 1)
                rsum[i] += __shfl_xor_sync(0xffffffffu, rsum[i], o);
            lrow[i] += rsum[i];
        }
        if (tx == 0) {
#pragma unroll
            for (int i = 0; i < 4; i++) alphaSm[ty * 4 + i] = alpha[i];
        }
#pragma unroll
        for (int i = 0; i < 4; i++) {
            int r = ty * 4 + i;
            uint2 hi, lo;
            split4(s[i], hi, lo);
            *(uint2*)&sPh[r * QP + tx * 4] = hi;
            *(uint2*)&sPl[r * QP + tx * 4] = lo;
        }
        if (kt + 1 < 36) { CP_WAIT1(); } else { CP_WAIT0(); }
        __syncthreads();

        // ---- rescale fragment-resident O, PV accumulate in place ----
#pragma unroll
        for (int e = 0; e < 8; e++) {
            float a0 = alphaSm[rowidx0[e]];
            float a1 = alphaSm[rowidx0[e] + 16];
            of[0].x[e] *= a0;
            of[1].x[e] *= a1;
        }
        {
#pragma unroll
            for (int k = 0; k < 4; k++) {
                wmma::fragment<wmma::matrix_b, 16, 16, 16, __nv_bfloat16, wmma::row_major> fbh, fbl;
                wmma::load_matrix_sync(fbh, sVh + k * 16 * QP + wn, QP);
                wmma::load_matrix_sync(fbl, sVl + k * 16 * QP + wn, QP);
#pragma unroll
                for (int mi = 0; mi < 2; mi++) {
                    wmma::fragment<wmma::matrix_a, 16, 16, 16, __nv_bfloat16, wmma::row_major> fah, fal;
                    wmma::load_matrix_sync(fah, sPh + (wm + mi * 16) * QP + k * 16, QP);
                    wmma::load_matrix_sync(fal, sPl + (wm + mi * 16) * QP + k * 16, QP);
                    wmma::mma_sync(of[mi], fah, fbh, of[mi]);
                    wmma::mma_sync(of[mi], fah, fbl, of[mi]);
                    wmma::mma_sync(of[mi], fal, fbh, of[mi]);
                }
            }
        }
        __syncthreads();

        // prefetch V(t+1)
        if (kt + 1 < 36) {
            int nbase = kbase + 64;
#pragma unroll
            for (int w = 0; w < 4; w++) {
                int ci = tid + w * 256;
                int arr = ci >> 9, idx = ci & 511;
                int row = idx >> 3, ch = idx & 7;
                int kg = nbase + row;
                const __nv_bfloat16* src = (arr ? KVl : KVh) + kvbase
                    + (size_t)(kg < NTOK ? kg : 0) * 1024 + 512 + ch * 8;
                cp16z(smem_u32((arr ? sVl : sVh) + row * QP + ch * 8),
                      src, (kg < NTOK) ? 16 : 0);
            }
            CP_COMMIT();
        }
    }

    // ---- epilogue ----
#pragma unroll
    for (int mi = 0; mi < 2; mi++)
        wmma::store_matrix_sync(Ss + (wm + mi * 16) * SP + wn, of[mi], SP, wmma::mem_row_major);
    __syncthreads();
#pragma unroll
    for (int i = 0; i < 4; i++) {
        float inv = 1.f / lrow[i];
        int r = ty * 4 + i;
        size_t o = (((size_t)b * L_DIM) + l0 + r) * C_DIM + h * HD + tx * 4;
        float4 tv = *(const float4*)&Ss[r * SP + tx * 4];
        float vv[4] = { tv.x * inv, tv.y * inv, tv.z * inv, tv.w * inv };
        uint2 hi, lo;
        split4(vv, hi, lo);
        *(uint2*)&Oh[o] = hi;
        *(uint2*)&Ol[o] = lo;
    }
}

// ---------------- launch ----------------
extern "C" void kernel_launch(void* const* d_in, const int* in_sizes, int n_in,
                              void* d_out, int out_size)
{
    const float* x    = (const float*)d_in[0];
    const float* m    = (const float*)d_in[1];
    const float* wsrc5[5] = { (const float*)d_in[2], (const float*)d_in[4], (const float*)d_in[6],
                              (const float*)d_in[8], (const float*)d_in[10] };
    const float* bsrc5[5] = { (const float*)d_in[3], (const float*)d_in[5], (const float*)d_in[7],
                              (const float*)d_in[9], (const float*)d_in[11] };
    const float* ln_g = (const float*)d_in[12];
    const float* ln_b = (const float*)d_in[13];
    const float* Wq   = (const float*)d_in[14];
    const float* Wkv  = (const float*)d_in[15];
    const float* Wp   = (const float*)d_in[16];
    const float* bp   = (const float*)d_in[17];
    float* out  = (float*)d_out;
    float* out2 = (float*)d_out + (size_t)B_DIM * L_DIM * C_DIM;

    float *P0, *P1;
    __nv_bfloat16 *P0h, *P0l, *P2h, *P2l, *mh, *ml, *Qh, *Ql, *KVh, *KVl, *Oh, *Ol, *Wth, *Wtl;
    cudaGetSymbolAddress((void**)&P0,  g_P0);
    cudaGetSymbolAddress((void**)&P1,  g_P1);
    cudaGetSymbolAddress((void**)&P0h, g_P0h);
    cudaGetSymbolAddress((void**)&P0l, g_P0l);
    cudaGetSymbolAddress((void**)&P2h, g_P2h);
    cudaGetSymbolAddress((void**)&P2l, g_P2l);
    cudaGetSymbolAddress((void**)&mh,  g_mh);
    cudaGetSymbolAddress((void**)&ml,  g_ml);
    cudaGetSymbolAddress((void**)&Qh,  g_Qh);
    cudaGetSymbolAddress((void**)&Ql,  g_Ql);
    cudaGetSymbolAddress((void**)&KVh, g_KVh);
    cudaGetSymbolAddress((void**)&KVl, g_KVl);
    cudaGetSymbolAddress((void**)&Oh,  g_Oh);
    cudaGetSymbolAddress((void**)&Ol,  g_Ol);
    cudaGetSymbolAddress((void**)&Wth, g_Wth);
    cudaGetSymbolAddress((void**)&Wtl, g_Wtl);

    cudaFuncSetAttribute(cgemm_kernel,     cudaFuncAttributeMaxDynamicSharedMemorySize, TG_SMEM);
    cudaFuncSetAttribute(tgemm_kernel,     cudaFuncAttributeMaxDynamicSharedMemorySize, TG_SMEM);
    cudaFuncSetAttribute(attn_wmma_kernel, cudaFuncAttributeMaxDynamicSharedMemorySize, ATT_SMEM);

    wsplit8_kernel<<<dim3(32, 16, 8), dim3(32, 8)>>>(
        wsrc5[0], wsrc5[1], wsrc5[2], wsrc5[3], wsrc5[4], Wq, Wp, Wkv, Wth, Wtl);
    mcvt_kernel<<<(B_DIM * L_DIM * C_DIM / 4 + 255) / 256, 256>>>(m, mh, ml);

    pool_all_kernel<<<dim3(NP, B_DIM), 512>>>(x, P0, P0h, P0l);

    cgemm_kernel<<<dim3(4, 143), 256, TG_SMEM>>>(
        P0h, P0l, mh, ml, Wth, Wtl,
        bsrc5[0], bsrc5[1], bsrc5[2], bsrc5[3], bsrc5[4],
        P0, P1, Qh, Ql);

    mx_copy_kernel<<<dim3(8, 16, B_DIM), dim3(32, 8)>>>(P1, out2);
    ln_kernel<<<B_DIM * NP, 128>>>(P1, ln_g, ln_b, P2h, P2l);

    tgemm_kernel<<<dim3(8, (B_DIM * NTOK + 127) / 128), 256, TG_SMEM>>>(
        P2h, P2l, mh, ml, Wth + 7 * (size_t)WSLOT, Wtl + 7 * (size_t)WSLOT,
        nullptr, nullptr, KVh, KVl, B_DIM * NTOK, 1024, 2);

    attn_wmma_kernel<<<dim3(L_DIM / 64, NH, B_DIM), 256, ATT_SMEM>>>(Qh, Ql, KVh, KVl, Oh, Ol);

    tgemm_kernel<<<dim3(4, 64), 256, TG_SMEM>>>(
        Oh, Ol, nullptr, nullptr, Wth + 6 * (size_t)WSLOT, Wtl + 6 * (size_t)WSLOT,
        bp, out, nullptr, nullptr, B_DIM * L_DIM, 512, 0);
}

// round 12
// speedup vs baseline: 1.1567x; 1.1567x over previous
#include <cuda_runtime.h>
#include <cuda_bf16.h>
#include <mma.h>
#include <math.h>
#include <cstdint>

using namespace nvcuda;

#define B_DIM 8
#define L_DIM 1024
#define C_DIM 512
#define NP    1243
#define NTOK  2267
#define NH    8
#define HD    64
#define LN_EPS 1e-5f
#define OFF_MX 987

// ---------------- scratch ----------------
__device__ __align__(128) float g_P0[B_DIM * NP * C_DIM];
__device__ __align__(128) float g_P1[B_DIM * NP * C_DIM];
__device__ __align__(128) __nv_bfloat16 g_P0h[B_DIM * NP * C_DIM],    g_P0l[B_DIM * NP * C_DIM];
__device__ __align__(128) __nv_bfloat16 g_P2h[B_DIM * NP * C_DIM],    g_P2l[B_DIM * NP * C_DIM];
__device__ __align__(128) __nv_bfloat16 g_mh [B_DIM * L_DIM * C_DIM], g_ml [B_DIM * L_DIM * C_DIM];
__device__ __align__(128) __nv_bfloat16 g_Qh [B_DIM * L_DIM * C_DIM], g_Ql [B_DIM * L_DIM * C_DIM];
__device__ __align__(128) __nv_bfloat16 g_KVh[B_DIM * NTOK * 2 * C_DIM], g_KVl[B_DIM * NTOK * 2 * C_DIM];
__device__ __align__(128) __nv_bfloat16 g_Oh [B_DIM * L_DIM * C_DIM], g_Ol [B_DIM * L_DIM * C_DIM];
#define WSLOT (512 * 512)
__device__ __align__(128) __nv_bfloat16 g_Wth[7 * WSLOT + 512 * 1024], g_Wtl[7 * WSLOT + 512 * 1024];

// ---------------- helpers ----------------
__device__ __forceinline__ uint32_t smem_u32(const void* p) {
    uint32_t a;
    asm("{ .reg .u64 t; cvta.to.shared.u64 t, %1; cvt.u32.u64 %0, t; }" : "=r"(a) : "l"(p));
    return a;
}
__device__ __forceinline__ void cp16(uint32_t dst, const void* src) {
    asm volatile("cp.async.cg.shared.global [%0], [%1], 16;" :: "r"(dst), "l"(src) : "memory");
}
__device__ __forceinline__ void cp16z(uint32_t dst, const void* src, int sz) {
    asm volatile("cp.async.cg.shared.global [%0], [%1], 16, %2;" :: "r"(dst), "l"(src), "r"(sz) : "memory");
}
#define CP_COMMIT() asm volatile("cp.async.commit_group;" ::: "memory")
#define CP_WAIT1()  asm volatile("cp.async.wait_group 1;" ::: "memory")
#define CP_WAIT0()  asm volatile("cp.async.wait_group 0;" ::: "memory")

__device__ __forceinline__ uint32_t pk2(float a, float b) {
    __nv_bfloat162 t(__float2bfloat16(a), __float2bfloat16(b));
    return *(uint32_t*)&t;
}
__device__ __forceinline__ void split4(const float* v, uint2& hi, uint2& lo) {
    __nv_bfloat16 h[4]; float r[4];
#pragma unroll
    for (int u = 0; u < 4; u++) { h[u] = __float2bfloat16(v[u]); r[u] = v[u] - __bfloat162float(h[u]); }
    __nv_bfloat162 h01(h[0], h[1]), h23(h[2], h[3]);
    hi.x = *(uint32_t*)&h01; hi.y = *(uint32_t*)&h23;
    lo.x = pk2(r[0], r[1]);  lo.y = pk2(r[2], r[3]);
}

// ---------------- combined weight transpose + split ----------------
__global__ void wsplit8_kernel(const float* W0, const float* W1, const float* W2, const float* W3,
                               const float* W4, const float* W5, const float* W6, const float* W7,
                               __nv_bfloat16* __restrict__ Th, __nv_bfloat16* __restrict__ Tl)
{
    __shared__ float t[32][33];
    int slot = blockIdx.z;
    const float* W = (slot == 0) ? W0 : (slot == 1) ? W1 : (slot == 2) ? W2 : (slot == 3) ? W3 :
                     (slot == 4) ? W4 : (slot == 5) ? W5 : (slot == 6) ? W6 : W7;
    int N = (slot == 7) ? 1024 : 512;
    int n0 = blockIdx.x * 32, k0 = blockIdx.y * 32;
    if (n0 >= N) return;
    __nv_bfloat16* th = Th + (size_t)slot * WSLOT;
    __nv_bfloat16* tl = Tl + (size_t)slot * WSLOT;
    int tx = threadIdx.x, ty = threadIdx.y;
    for (int i = ty; i < 32; i += 8) t[i][tx] = W[(size_t)(k0 + i) * N + n0 + tx];
    __syncthreads();
    for (int i = ty; i < 32; i += 8) {
        float v = t[tx][i];
        __nv_bfloat16 h = __float2bfloat16(v);
        size_t o = (size_t)(n0 + i) * 512 + k0 + tx;
        th[o] = h; tl[o] = __float2bfloat16(v - __bfloat162float(h));
    }
}

__global__ void mcvt_kernel(const float* __restrict__ m, __nv_bfloat16* __restrict__ mh,
                            __nv_bfloat16* __restrict__ ml)
{
    int i = (blockIdx.x * blockDim.x + threadIdx.x) * 4;
    if (i >= B_DIM * L_DIM * C_DIM) return;
    float4 v4 = *(const float4*)&m[i];
    float v[4] = { v4.x, v4.y, v4.z, v4.w };
    uint2 hi, lo;
    split4(v, hi, lo);
    *(uint2*)&mh[i] = hi;
    *(uint2*)&ml[i] = lo;
}

// ---------------- pooling (avg + max merged) ----------------
__global__ void pool_all_kernel(const float* __restrict__ x, float* __restrict__ P0,
                                __nv_bfloat16* __restrict__ Ph, __nv_bfloat16* __restrict__ Pl)
{
    int tok = blockIdx.x, b = blockIdx.y, c = threadIdx.x;
    float v;
    if (tok < 987) {
        int t = tok, n;
        if      (t < 441) { n = 21; }
        else if (t < 697) { n = 16; t -= 441; }
        else if (t < 866) { n = 13; t -= 697; }
        else              { n = 11; t -= 866; }
        int p = t / n, q = t - p * n;
        int hs = (p * 64) / n, he = ((p + 1) * 64 + n - 1) / n;
        int ws = (q * 64) / n, we = ((q + 1) * 64 + n - 1) / n;
        float s = 0.f;
        for (int h = hs; h < he; h++) {
            const float* xr = x + (((size_t)b * 4096) + (size_t)h * 64) * C_DIM + c;
            for (int w = ws; w < we; w++) s += xr[(size_t)w * C_DIM];
        }
        v = s / (float)((he - hs) * (we - ws));
    } else {
        int t = tok - 987;
        int p = t >> 4, q = t & 15;
        float mx = -1e30f;
        for (int h = p * 4; h < p * 4 + 4; h++) {
            const float* xr = x + (((size_t)b * 4096) + (size_t)h * 64) * C_DIM + c;
            for (int w = q * 4; w < q * 4 + 4; w++) mx = fmaxf(mx, xr[(size_t)w * C_DIM]);
        }
        v = mx;
    }
    size_t o = ((size_t)b * NP + tok) * C_DIM + c;
    P0[o] = v;
    __nv_bfloat16 h16 = __float2bfloat16(v);
    Ph[o] = h16; Pl[o] = __float2bfloat16(v - __bfloat162float(h16));
}

// =====================================================================
// GEMM mainloop (bf16x3, 128x128 tile, K=512); 2 blocks/SM via lb(256,2)
// =====================================================================
#define STG0    4096
#define STG_SZ  40960
#define TG_SMEM (4096 + 2 * 40960)
#define CPITCH  136

// cgemm: conv-res (0..4) + Wq (5). grid = (4, 143).
__global__ __launch_bounds__(256, 2) void cgemm_kernel(
    const __nv_bfloat16* __restrict__ P0h, const __nv_bfloat16* __restrict__ P0l,
    const __nv_bfloat16* __restrict__ mh,  const __nv_bfloat16* __restrict__ ml,
    const __nv_bfloat16* __restrict__ Wth, const __nv_bfloat16* __restrict__ Wtl,
    const float* bp0, const float* bp1, const float* bp2, const float* bp3, const float* bp4,
    const float* __restrict__ P0, float* __restrict__ P1,
    __nv_bfloat16* __restrict__ Qh, __nv_bfloat16* __restrict__ Ql)
{
    extern __shared__ char sm_raw[];
    const __nv_bfloat16** aptrs = (const __nv_bfloat16**)(sm_raw + 16);
    uint32_t sb = smem_u32(sm_raw);

    int tid = threadIdx.x;
    int ti = blockIdx.y;
    int branch, tstart;
    if      (ti < 28) { branch = 0; tstart = 0;  }
    else if (ti < 44) { branch = 1; tstart = 28; }
    else if (ti < 55) { branch = 2; tstart = 44; }
    else if (ti < 63) { branch = 3; tstart = 55; }
    else if (ti < 79) { branch = 4; tstart = 63; }
    else              { branch = 5; tstart = 79; }
    const int npx_t[6]  = { 441, 256, 169, 121, 256, 0 };
    const int toff_t[6] = { 0, 441, 697, 866, 987, 0 };
    int npx = npx_t[branch], toffc = toff_t[branch];
    int M = (branch < 5) ? 8 * npx : 8192;
    int brow = (ti - tstart) * 128;
    int bcol = blockIdx.x * 128;
    const float* bias = (branch == 0) ? bp0 : (branch == 1) ? bp1 : (branch == 2) ? bp2 :
                        (branch == 3) ? bp3 : (branch == 4) ? bp4 : nullptr;
    const __nv_bfloat16* Bh = Wth + (size_t)branch * WSLOT;
    const __nv_bfloat16* Bl = Wtl + (size_t)branch * WSLOT;

    if (tid < 128) {
        int arow = brow + tid;
        if (arow >= M) arow = M - 1;
        const __nv_bfloat16 *ph, *pl;
        if (branch < 5) {
            int b = arow / npx, t = arow - (arow / npx) * npx;
            size_t o = ((size_t)b * NP + toffc + t) * 512;
            ph = P0h + o; pl = P0l + o;
        } else {
            size_t o = (size_t)arow * 512;
            ph = mh + o; pl = ml + o;
        }
        aptrs[tid] = ph; aptrs[128 + tid] = pl;
    }
    __syncthreads();

    int wid = tid >> 5;
    int wm = wid & 1, wn = wid >> 1;

    wmma::fragment<wmma::accumulator, 16, 16, 16, float> acc[4][2];
#pragma unroll
    for (int mi = 0; mi < 4; mi++)
#pragma unroll
        for (int ni = 0; ni < 2; ni++)
            wmma::fill_fragment(acc[mi][ni], 0.f);

    {
        uint32_t st = sb + STG0;
#pragma unroll
        for (int w = 0; w < 8; w++) {
            int ci = tid + w * 256;
            int region = ci >> 9, idx = ci & 511;
            int row = idx >> 2, ch = idx & 3;
            const __nv_bfloat16* src;
            if (region < 2) src = aptrs[region * 128 + row] + ch * 8;
            else            src = ((region == 2) ? Bh : Bl) + (size_t)(bcol + row) * 512 + ch * 8;
            cp16(st + region * 10240 + row * 80 + ch * 16, src);
        }
        CP_COMMIT();
    }

    for (int j = 0; j < 16; j++) {
        if (j + 1 < 16) {
            uint32_t st = sb + STG0 + ((j + 1) & 1) * STG_SZ;
            int koff = (j + 1) * 32;
#pragma unroll
            for (int w = 0; w < 8; w++) {
                int ci = tid + w * 256;
                int region = ci >> 9, idx = ci & 511;
                int row = idx >> 2, ch = idx & 3;
                const __nv_bfloat16* src;
                if (region < 2) src = aptrs[region * 128 + row] + koff + ch * 8;
                else            src = ((region == 2) ? Bh : Bl) + (size_t)(bcol + row) * 512 + koff + ch * 8;
                cp16(st + region * 10240 + row * 80 + ch * 16, src);
            }
            CP_COMMIT();
            CP_WAIT1();
        } else {
            CP_WAIT0();
        }
        __syncthreads();

        const __nv_bfloat16* st = (const __nv_bfloat16*)(sm_raw + STG0 + (j & 1) * STG_SZ);
        const __nv_bfloat16* As_h = st;
        const __nv_bfloat16* As_l = st + 5120;
        const __nv_bfloat16* Bs_h = st + 10240;
        const __nv_bfloat16* Bs_l = st + 15360;

#pragma unroll
        for (int kk = 0; kk < 2; kk++) {
            wmma::fragment<wmma::matrix_a, 16, 16, 16, __nv_bfloat16, wmma::row_major> fah[4], fal[4];
            wmma::fragment<wmma::matrix_b, 16, 16, 16, __nv_bfloat16, wmma::col_major> fbh[2], fbl[2];
#pragma unroll
            for (int mi = 0; mi < 4; mi++) {
                int r = wm * 64 + mi * 16;
                wmma::load_matrix_sync(fah[mi], As_h + r * 40 + kk * 16, 40);
                wmma::load_matrix_sync(fal[mi], As_l + r * 40 + kk * 16, 40);
            }
#pragma unroll
            for (int ni = 0; ni < 2; ni++) {
                int c = wn * 32 + ni * 16;
                wmma::load_matrix_sync(fbh[ni], Bs_h + c * 40 + kk * 16, 40);
                wmma::load_matrix_sync(fbl[ni], Bs_l + c * 40 + kk * 16, 40);
            }
#pragma unroll
            for (int mi = 0; mi < 4; mi++)
#pragma unroll
                for (int ni = 0; ni < 2; ni++) {
                    wmma::mma_sync(acc[mi][ni], fah[mi], fbh[ni], acc[mi][ni]);
                    wmma::mma_sync(acc[mi][ni], fah[mi], fbl[ni], acc[mi][ni]);
                    wmma::mma_sync(acc[mi][ni], fal[mi], fbh[ni], acc[mi][ni]);
                }
        }
        __syncthreads();
    }

    float* Cs = (float*)(sm_raw + STG0);
#pragma unroll
    for (int mi = 0; mi < 4; mi++)
#pragma unroll
        for (int ni = 0; ni < 2; ni++)
            wmma::store_matrix_sync(Cs + (wm * 64 + mi * 16) * CPITCH + wn * 32 + ni * 16,
                                    acc[mi][ni], CPITCH, wmma::mem_row_major);
    __syncthreads();

    int lane = tid & 31, wrow = tid >> 5;
    for (int rr = wrow; rr < 128; rr += 8) {
        int r = brow + rr;
        if (r >= M) continue;
        int col0 = lane * 4;
        float4 o = *(float4*)&Cs[rr * CPITCH + col0];
        int col = bcol + col0;
        if (branch < 5) {
            o.x += bias[col];     o.y += bias[col + 1];
            o.z += bias[col + 2]; o.w += bias[col + 3];
            int b = r / npx, t = r - (r / npx) * npx;
            size_t g = ((size_t)b * NP + toffc + t) * 512;
            float4 rv = *(const float4*)&P0[g + col];
            o.x += rv.x; o.y += rv.y; o.z += rv.z; o.w += rv.w;
            *(float4*)&P1[g + col] = o;
        } else {
            size_t g = (size_t)r * 512 + col;
            float vv[4] = { o.x, o.y, o.z, o.w };
            uint2 hi, lo;
            split4(vv, hi, lo);
            *(uint2*)&Qh[g] = hi;
            *(uint2*)&Ql[g] = lo;
        }
    }
}

// tgemm: generic (Wkv mode 2, Wp mode 0)
__global__ __launch_bounds__(256, 2) void tgemm_kernel(
    const __nv_bfloat16* __restrict__ Ah, const __nv_bfloat16* __restrict__ Al,
    const __nv_bfloat16* __restrict__ A2h, const __nv_bfloat16* __restrict__ A2l,
    const __nv_bfloat16* __restrict__ Bh, const __nv_bfloat16* __restrict__ Bl,
    const float* __restrict__ bias,
    float* __restrict__ Cout,
    __nv_bfloat16* __restrict__ outh, __nv_bfloat16* __restrict__ outl,
    int M, int N, int mode)
{
    extern __shared__ char sm_raw[];
    const __nv_bfloat16** aptrs = (const __nv_bfloat16**)(sm_raw + 16);
    uint32_t sb = smem_u32(sm_raw);

    int tid = threadIdx.x;
    int brow = blockIdx.y * 128, bcol = blockIdx.x * 128;

    if (tid < 128) {
        int arow = brow + tid;
        if (arow >= M) arow = M - 1;
        const __nv_bfloat16 *ph, *pl;
        if (mode == 0) {
            size_t o = (size_t)arow * 512; ph = Ah + o; pl = Al + o;
        } else {
            int b = arow / NTOK, t = arow - (arow / NTOK) * NTOK;
            if (t < NP) { size_t o = ((size_t)b * NP + t) * 512; ph = Ah + o; pl = Al + o; }
            else        { size_t o = ((size_t)b * L_DIM + (t - NP)) * 512; ph = A2h + o; pl = A2l + o; }
        }
        aptrs[tid] = ph; aptrs[128 + tid] = pl;
    }
    __syncthreads();

    int wid = tid >> 5;
    int wm = wid & 1, wn = wid >> 1;

    wmma::fragment<wmma::accumulator, 16, 16, 16, float> acc[4][2];
#pragma unroll
    for (int mi = 0; mi < 4; mi++)
#pragma unroll
        for (int ni = 0; ni < 2; ni++)
            wmma::fill_fragment(acc[mi][ni], 0.f);

    {
        uint32_t st = sb + STG0;
#pragma unroll
        for (int w = 0; w < 8; w++) {
            int ci = tid + w * 256;
            int region = ci >> 9, idx = ci & 511;
            int row = idx >> 2, ch = idx & 3;
            const __nv_bfloat16* src;
            if (region < 2) src = aptrs[region * 128 + row] + ch * 8;
            else            src = ((region == 2) ? Bh : Bl) + (size_t)(bcol + row) * 512 + ch * 8;
            cp16(st + region * 10240 + row * 80 + ch * 16, src);
        }
        CP_COMMIT();
    }

    for (int j = 0; j < 16; j++) {
        if (j + 1 < 16) {
            uint32_t st = sb + STG0 + ((j + 1) & 1) * STG_SZ;
            int koff = (j + 1) * 32;
#pragma unroll
            for (int w = 0; w < 8; w++) {
                int ci = tid + w * 256;
                int region = ci >> 9, idx = ci & 511;
                int row = idx >> 2, ch = idx & 3;
                const __nv_bfloat16* src;
                if (region < 2) src = aptrs[region * 128 + row] + koff + ch * 8;
                else            src = ((region == 2) ? Bh : Bl) + (size_t)(bcol + row) * 512 + koff + ch * 8;
                cp16(st + region * 10240 + row * 80 + ch * 16, src);
            }
            CP_COMMIT();
            CP_WAIT1();
        } else {
            CP_WAIT0();
        }
        __syncthreads();

        const __nv_bfloat16* st = (const __nv_bfloat16*)(sm_raw + STG0 + (j & 1) * STG_SZ);
        const __nv_bfloat16* As_h = st;
        const __nv_bfloat16* As_l = st + 5120;
        const __nv_bfloat16* Bs_h = st + 10240;
        const __nv_bfloat16* Bs_l = st + 15360;

#pragma unroll
        for (int kk = 0; kk < 2; kk++) {
            wmma::fragment<wmma::matrix_a, 16, 16, 16, __nv_bfloat16, wmma::row_major> fah[4], fal[4];
            wmma::fragment<wmma::matrix_b, 16, 16, 16, __nv_bfloat16, wmma::col_major> fbh[2], fbl[2];
#pragma unroll
            for (int mi = 0; mi < 4; mi++) {
                int r = wm * 64 + mi * 16;
                wmma::load_matrix_sync(fah[mi], As_h + r * 40 + kk * 16, 40);
                wmma::load_matrix_sync(fal[mi], As_l + r * 40 + kk * 16, 40);
            }
#pragma unroll
            for (int ni = 0; ni < 2; ni++) {
                int c = wn * 32 + ni * 16;
                wmma::load_matrix_sync(fbh[ni], Bs_h + c * 40 + kk * 16, 40);
                wmma::load_matrix_sync(fbl[ni], Bs_l + c * 40 + kk * 16, 40);
            }
#pragma unroll
            for (int mi = 0; mi < 4; mi++)
#pragma unroll
                for (int ni = 0; ni < 2; ni++) {
                    wmma::mma_sync(acc[mi][ni], fah[mi], fbh[ni], acc[mi][ni]);
                    wmma::mma_sync(acc[mi][ni], fah[mi], fbl[ni], acc[mi][ni]);
                    wmma::mma_sync(acc[mi][ni], fal[mi], fbh[ni], acc[mi][ni]);
                }
        }
        __syncthreads();
    }

    float* Cs = (float*)(sm_raw + STG0);
#pragma unroll
    for (int mi = 0; mi < 4; mi++)
#pragma unroll
        for (int ni = 0; ni < 2; ni++)
            wmma::store_matrix_sync(Cs + (wm * 64 + mi * 16) * CPITCH + wn * 32 + ni * 16,
                                    acc[mi][ni], CPITCH, wmma::mem_row_major);
    __syncthreads();

    int lane = tid & 31, wrow = tid >> 5;
    for (int rr = wrow; rr < 128; rr += 8) {
        int r = brow + rr;
        if (r >= M) continue;
        int col0 = lane * 4;
        float4 o = *(float4*)&Cs[rr * CPITCH + col0];
        int col = bcol + col0;
        if (bias) {
            o.x += bias[col];     o.y += bias[col + 1];
            o.z += bias[col + 2]; o.w += bias[col + 3];
        }
        if (outh) {
            size_t g = (size_t)r * N + col;
            float vv[4] = { o.x, o.y, o.z, o.w };
            uint2 hi, lo;
            split4(vv, hi, lo);
            *(uint2*)&outh[g] = hi;
            *(uint2*)&outl[g] = lo;
        } else {
            *(float4*)&Cout[(size_t)r * N + col] = o;
        }
    }
}

// ---------------- mx copy (SMEM-tiled transpose) ----------------
__global__ void mx_copy_kernel(const float* __restrict__ P1, float* __restrict__ out2)
{
    __shared__ float t[32][33];
    int b = blockIdx.z;
    int t0 = blockIdx.x * 32;
    int c0 = blockIdx.y * 32;
    int tx = threadIdx.x, ty = threadIdx.y;
    for (int i = ty; i < 32; i += 8)
        t[i][tx] = P1[(((size_t)b * NP) + OFF_MX + t0 + i) * 512 + c0 + tx];
    __syncthreads();
    for (int i = ty; i < 32; i += 8)
        out2[(((size_t)b * 512) + c0 + i) * 256 + t0 + tx] = t[tx][i];
}

// ---------------- layernorm -> bf16 hi/lo ----------------
__global__ void ln_kernel(const float* __restrict__ X, const float* __restrict__ g,
                          const float* __restrict__ be,
                          __nv_bfloat16* __restrict__ Yh, __nv_bfloat16* __restrict__ Yl)
{
    int row = blockIdx.x, tid = threadIdx.x;
    float4 v = ((const float4*)(X + (size_t)row * C_DIM))[tid];
    float s  = v.x + v.y + v.z + v.w;
    float s2 = v.x * v.x + v.y * v.y + v.z * v.z + v.w * v.w;
#pragma unroll
    for (int o = 16; o >= 1; o >>= 1) {
        s  += __shfl_xor_sync(0xffffffffu, s,  o);
        s2 += __shfl_xor_sync(0xffffffffu, s2, o);
    }
    __shared__ float ws[4], ws2[4];
    int wid = tid >> 5, lane = tid & 31;
    if (lane == 0) { ws[wid] = s; ws2[wid] = s2; }
    __syncthreads();
    float ts = ws[0] + ws[1] + ws[2] + ws[3], ts2 = ws2[0] + ws2[1] + ws2[2] + ws2[3];
    float mean = ts * (1.f / C_DIM);
    float var  = ts2 * (1.f / C_DIM) - mean * mean;
    float rstd = rsqrtf(var + LN_EPS);
    float4 gg = ((const float4*)g)[tid], bb = ((const float4*)be)[tid];
    float y[4] = { (v.x - mean) * rstd * gg.x + bb.x, (v.y - mean) * rstd * gg.y + bb.y,
                   (v.z - mean) * rstd * gg.z + bb.z, (v.w - mean) * rstd * gg.w + bb.w };
    size_t o = (size_t)row * C_DIM + tid * 4;
    uint2 hi, lo;
    split4(y, hi, lo);
    *(uint2*)&Yh[o] = hi;
    *(uint2*)&Yl[o] = lo;
}

// =====================================================================
// wmma flash attention (R10 config): 64-q tile, 256 thr, fragment-
// resident O + rowmap rescale, K double-buffered, V single-buffered.
// SMEM = 109,824 B -> 2 blocks/SM.
// =====================================================================
#define QP 72
#define SP 68
#define ATT_SMEM (10 * 64 * QP * 2 + 64 * SP * 4 + 256)   // 109824

__global__ __launch_bounds__(256, 2) void attn_wmma_kernel(
    const __nv_bfloat16* __restrict__ Qh, const __nv_bfloat16* __restrict__ Ql,
    const __nv_bfloat16* __restrict__ KVh, const __nv_bfloat16* __restrict__ KVl,
    __nv_bfloat16* __restrict__ Oh, __nv_bfloat16* __restrict__ Ol)
{
    extern __shared__ char smc[];
    __nv_bfloat16* sQh  = (__nv_bfloat16*)smc;
    __nv_bfloat16* sQl  = sQh + 64 * QP;
    __nv_bfloat16* sK_h[2] = { sQl + 64 * QP,        sQl + 3 * 64 * QP };
    __nv_bfloat16* sK_l[2] = { sQl + 2 * 64 * QP,    sQl + 4 * 64 * QP };
    __nv_bfloat16* sVh  = sQl + 5 * 64 * QP;
    __nv_bfloat16* sVl  = sVh + 64 * QP;
    __nv_bfloat16* sPh  = sVl + 64 * QP;
    __nv_bfloat16* sPl  = sPh + 64 * QP;
    float* Ss = (float*)(sPl + 64 * QP);   // [64][68]
    float* alphaSm = Ss + 64 * SP;         // [64]

    int tid = threadIdx.x;
    int b = blockIdx.z, h = blockIdx.y, l0 = blockIdx.x * 64;
    int warp = tid >> 5;
    int wm = (warp & 1) * 32, wn = (warp >> 1) * 16;
    int ty = tid >> 4, tx = tid & 15;
    const float scale = 0.125f;

    size_t kvbase = (size_t)b * NTOK * 1024 + h * 64;

    // rowmap init
    for (int i = tid; i < 64 * SP; i += 256) Ss[i] = (float)(i / SP);
    __syncthreads();
    wmma::fragment<wmma::accumulator, 16, 16, 16, float> of[2];
    int rowidx0[8];
    {
        wmma::load_matrix_sync(of[0], Ss + wm * SP + wn, SP, wmma::mem_row_major);
#pragma unroll
        for (int e = 0; e < 8; e++) rowidx0[e] = (int)of[0].x[e];
        wmma::fill_fragment(of[0], 0.f);
        wmma::fill_fragment(of[1], 0.f);
    }
    __syncthreads();

    // group 1: Q (hi/lo) + K tile 0
    {
#pragma unroll
        for (int w = 0; w < 4; w++) {
            int ci = tid + w * 256;
            int arr = ci >> 9, idx = ci & 511;
            int row = idx >> 3, ch = idx & 7;
            const __nv_bfloat16* src = (arr ? Ql : Qh) +
                (((size_t)b * L_DIM) + l0 + row) * 512 + h * 64 + ch * 8;
            cp16(smem_u32((arr ? sQl : sQh) + row * QP + ch * 8), src);
        }
#pragma unroll
        for (int w = 0; w < 4; w++) {
            int ci = tid + w * 256;
            int arr = ci >> 9, idx = ci & 511;
            int row = idx >> 3, ch = idx & 7;
            const __nv_bfloat16* src = (arr ? KVl : KVh) + kvbase + (size_t)row * 1024 + ch * 8;
            cp16(smem_u32((arr ? sK_l[0] : sK_h[0]) + row * QP + ch * 8), src);
        }
        CP_COMMIT();
    }
    // group 2: V tile 0
    {
#pragma unroll
        for (int w = 0; w < 4; w++) {
            int ci = tid + w * 256;
            int arr = ci >> 9, idx = ci & 511;
            int row = idx >> 3, ch = idx & 7;
            const __nv_bfloat16* src = (arr ? KVl : KVh) + kvbase + (size_t)row * 1024 + 512 + ch * 8;
            cp16(smem_u32((arr ? sVl : sVh) + row * QP + ch * 8), src);
        }
        CP_COMMIT();
    }

    float mrow[4] = { -1e30f, -1e30f, -1e30f, -1e30f };
    float lrow[4] = {};

    for (int kt = 0; kt < 36; kt++) {
        int kbase = kt * 64;
        int kb = kt & 1;
        CP_WAIT1();
        __syncthreads();

        // prefetch K(t+1)
        if (kt + 1 < 36) {
            int nkb = (kt + 1) & 1;
#pragma unroll
            for (int w = 0; w < 4; w++) {
                int ci = tid + w * 256;
                int arr = ci >> 9, idx = ci & 511;
                int row = idx >> 3, ch = idx & 7;
                int kg = kbase + 64 + row;
                const __nv_bfloat16* src = (arr ? KVl : KVh) + kvbase
                    + (size_t)(kg < NTOK ? kg : 0) * 1024 + ch * 8;
                cp16z(smem_u32((arr ? sK_l[nkb] : sK_h[nkb]) + row * QP + ch * 8),
                      src, (kg < NTOK) ? 16 : 0);
            }
            CP_COMMIT();
        }

        // ---- S = Q K^T ----
        {
            wmma::fragment<wmma::accumulator, 16, 16, 16, float> sf[2];
            wmma::fill_fragment(sf[0], 0.f);
            wmma::fill_fragment(sf[1], 0.f);
#pragma unroll
            for (int k = 0; k < 4; k++) {
                wmma::fragment<wmma::matrix_b, 16, 16, 16, __nv_bfloat16, wmma::col_major> fbh, fbl;
                wmma::load_matrix_sync(fbh, sK_h[kb] + wn * QP + k * 16, QP);
                wmma::load_matrix_sync(fbl, sK_l[kb] + wn * QP + k * 16, QP);
#pragma unroll
                for (int mi = 0; mi < 2; mi++) {
                    wmma::fragment<wmma::matrix_a, 16, 16, 16, __nv_bfloat16, wmma::row_major> fah, fal;
                    wmma::load_matrix_sync(fah, sQh + (wm + mi * 16) * QP + k * 16, QP);
                    wmma::load_matrix_sync(fal, sQl + (wm + mi * 16) * QP + k * 16, QP);
                    wmma::mma_sync(sf[mi], fah, fbh, sf[mi]);
                    wmma::mma_sync(sf[mi], fah, fbl, sf[mi]);
                    wmma::mma_sync(sf[mi], fal, fbh, sf[mi]);
                }
            }
            wmma::store_matrix_sync(Ss + wm * SP + wn, sf[0], SP, wmma::mem_row_major);
            wmma::store_matrix_sync(Ss + (wm + 16) * SP + wn, sf[1], SP, wmma::mem_row_major);
        }
        __syncthreads();

        // ---- scalar online softmax ----
        float s[4][4], tmax[4];
#pragma unroll
        for (int i = 0; i < 4; i++) {
            float4 sv = *(const float4*)&Ss[(ty * 4 + i) * SP + tx * 4];
            s[i][0] = sv.x; s[i][1] = sv.y; s[i][2] = sv.z; s[i][3] = sv.w;
            tmax[i] = -1e30f;
#pragma unroll
            for (int j = 0; j < 4; j++) {
                int cg = kbase + tx * 4 + j;
                s[i][j] = (cg < NTOK) ? s[i][j] * scale : -1e30f;
                tmax[i] = fmaxf(tmax[i], s[i][j]);
            }
        }
#pragma unroll
        for (int i = 0; i < 4; i++)
#pragma unroll
            for (int o = 8; o >= 1; o >>= 1)
                tmax[i] = fmaxf(tmax[i], __shfl_xor_sync(0xffffffffu, tmax[i], o));
        float alpha[4], rsum[4];
#pragma unroll
        for (int i = 0; i < 4; i++) {
            float mnew = fmaxf(mrow[i], tmax[i]);
            alpha[i] = __expf(mrow[i] - mnew);
            mrow[i] = mnew;
            float rs = 0.f;
#pragma unroll
            for (int j = 0; j < 4; j++) {
                float p = (s[i][j] > -1e29f) ? __expf(s[i][j] - mnew) : 0.f;
                s[i][j] = p; rs += p;
            }
            rsum[i] = rs;
            lrow[i] = lrow[i] * alpha[i];
        }
#pragma unroll
        for (int i = 0; i < 4; i++) {
#pragma unroll
            for (int o = 8; o >= 1; o >>= 1)
                rsum[i] += __shfl_xor_sync(0xffffffffu, rsum[i], o);
            lrow[i] += rsum[i];
        }
        if (tx == 0) {
#pragma unroll
            for (int i = 0; i < 4; i++) alphaSm[ty * 4 + i] = alpha[i];
        }
#pragma unroll
        for (int i = 0; i < 4; i++) {
            int r = ty * 4 + i;
            uint2 hi, lo;
            split4(s[i], hi, lo);
            *(uint2*)&sPh[r * QP + tx * 4] = hi;
            *(uint2*)&sPl[r * QP + tx * 4] = lo;
        }
        if (kt + 1 < 36) { CP_WAIT1(); } else { CP_WAIT0(); }
        __syncthreads();

        // ---- rescale fragment-resident O, PV accumulate in place ----
#pragma unroll
        for (int e = 0; e < 8; e++) {
            of[0].x[e] *= alphaSm[rowidx0[e]];
            of[1].x[e] *= alphaSm[rowidx0[e] + 16];
        }
        {
#pragma unroll
            for (int k = 0; k < 4; k++) {
                wmma::fragment<wmma::matrix_b, 16, 16, 16, __nv_bfloat16, wmma::row_major> fbh, fbl;
                wmma::load_matrix_sync(fbh, sVh + k * 16 * QP + wn, QP);
                wmma::load_matrix_sync(fbl, sVl + k * 16 * QP + wn, QP);
#pragma unroll
                for (int mi = 0; mi < 2; mi++) {
                    wmma::fragment<wmma::matrix_a, 16, 16, 16, __nv_bfloat16, wmma::row_major> fah, fal;
                    wmma::load_matrix_sync(fah, sPh + (wm + mi * 16) * QP + k * 16, QP);
                    wmma::load_matrix_sync(fal, sPl + (wm + mi * 16) * QP + k * 16, QP);
                    wmma::mma_sync(of[mi], fah, fbh, of[mi]);
                    wmma::mma_sync(of[mi], fah, fbl, of[mi]);
                    wmma::mma_sync(of[mi], fal, fbh, of[mi]);
                }
            }
        }
        __syncthreads();

        // prefetch V(t+1)
        if (kt + 1 < 36) {
            int nbase = kbase + 64;
#pragma unroll
            for (int w = 0; w < 4; w++) {
                int ci = tid + w * 256;
                int arr = ci >> 9, idx = ci & 511;
                int row = idx >> 3, ch = idx & 7;
                int kg = nbase + row;
                const __nv_bfloat16* src = (arr ? KVl : KVh) + kvbase
                    + (size_t)(kg < NTOK ? kg : 0) * 1024 + 512 + ch * 8;
                cp16z(smem_u32((arr ? sVl : sVh) + row * QP + ch * 8),
                      src, (kg < NTOK) ? 16 : 0);
            }
            CP_COMMIT();
        }
    }

    // ---- epilogue ----
#pragma unroll
    for (int mi = 0; mi < 2; mi++)
        wmma::store_matrix_sync(Ss + (wm + mi * 16) * SP + wn, of[mi], SP, wmma::mem_row_major);
    __syncthreads();
#pragma unroll
    for (int i = 0; i < 4; i++) {
        float inv = 1.f / lrow[i];
        int r = ty * 4 + i;
        size_t o = (((size_t)b * L_DIM) + l0 + r) * C_DIM + h * HD + tx * 4;
        float4 tv = *(const float4*)&Ss[r * SP + tx * 4];
        float vv[4] = { tv.x * inv, tv.y * inv, tv.z * inv, tv.w * inv };
        uint2 hi, lo;
        split4(vv, hi, lo);
        *(uint2*)&Oh[o] = hi;
        *(uint2*)&Ol[o] = lo;
    }
}

// ---------------- launch ----------------
extern "C" void kernel_launch(void* const* d_in, const int* in_sizes, int n_in,
                              void* d_out, int out_size)
{
    const float* x    = (const float*)d_in[0];
    const float* m    = (const float*)d_in[1];
    const float* wsrc5[5] = { (const float*)d_in[2], (const float*)d_in[4], (const float*)d_in[6],
                              (const float*)d_in[8], (const float*)d_in[10] };
    const float* bsrc5[5] = { (const float*)d_in[3], (const float*)d_in[5], (const float*)d_in[7],
                              (const float*)d_in[9], (const float*)d_in[11] };
    const float* ln_g = (const float*)d_in[12];
    const float* ln_b = (const float*)d_in[13];
    const float* Wq   = (const float*)d_in[14];
    const float* Wkv  = (const float*)d_in[15];
    const float* Wp   = (const float*)d_in[16];
    const float* bp   = (const float*)d_in[17];
    float* out  = (float*)d_out;
    float* out2 = (float*)d_out + (size_t)B_DIM * L_DIM * C_DIM;

    float *P0, *P1;
    __nv_bfloat16 *P0h, *P0l, *P2h, *P2l, *mh, *ml, *Qh, *Ql, *KVh, *KVl, *Oh, *Ol, *Wth, *Wtl;
    cudaGetSymbolAddress((void**)&P0,  g_P0);
    cudaGetSymbolAddress((void**)&P1,  g_P1);
    cudaGetSymbolAddress((void**)&P0h, g_P0h);
    cudaGetSymbolAddress((void**)&P0l, g_P0l);
    cudaGetSymbolAddress((void**)&P2h, g_P2h);
    cudaGetSymbolAddress((void**)&P2l, g_P2l);
    cudaGetSymbolAddress((void**)&mh,  g_mh);
    cudaGetSymbolAddress((void**)&ml,  g_ml);
    cudaGetSymbolAddress((void**)&Qh,  g_Qh);
    cudaGetSymbolAddress((void**)&Ql,  g_Ql);
    cudaGetSymbolAddress((void**)&KVh, g_KVh);
    cudaGetSymbolAddress((void**)&KVl, g_KVl);
    cudaGetSymbolAddress((void**)&Oh,  g_Oh);
    cudaGetSymbolAddress((void**)&Ol,  g_Ol);
    cudaGetSymbolAddress((void**)&Wth, g_Wth);
    cudaGetSymbolAddress((void**)&Wtl, g_Wtl);

    cudaFuncSetAttribute(cgemm_kernel,     cudaFuncAttributeMaxDynamicSharedMemorySize, TG_SMEM);
    cudaFuncSetAttribute(tgemm_kernel,     cudaFuncAttributeMaxDynamicSharedMemorySize, TG_SMEM);
    cudaFuncSetAttribute(attn_wmma_kernel, cudaFuncAttributeMaxDynamicSharedMemorySize, ATT_SMEM);

    wsplit8_kernel<<<dim3(32, 16, 8), dim3(32, 8)>>>(
        wsrc5[0], wsrc5[1], wsrc5[2], wsrc5[3], wsrc5[4], Wq, Wp, Wkv, Wth, Wtl);
    mcvt_kernel<<<(B_DIM * L_DIM * C_DIM / 4 + 255) / 256, 256>>>(m, mh, ml);

    pool_all_kernel<<<dim3(NP, B_DIM), 512>>>(x, P0, P0h, P0l);

    cgemm_kernel<<<dim3(4, 143), 256, TG_SMEM>>>(
        P0h, P0l, mh, ml, Wth, Wtl,
        bsrc5[0], bsrc5[1], bsrc5[2], bsrc5[3], bsrc5[4],
        P0, P1, Qh, Ql);

    mx_copy_kernel<<<dim3(8, 16, B_DIM), dim3(32, 8)>>>(P1, out2);
    ln_kernel<<<B_DIM * NP, 128>>>(P1, ln_g, ln_b, P2h, P2l);

    tgemm_kernel<<<dim3(8, (B_DIM * NTOK + 127) / 128), 256, TG_SMEM>>>(
        P2h, P2l, mh, ml, Wth + 7 * (size_t)WSLOT, Wtl + 7 * (size_t)WSLOT,
        nullptr, nullptr, KVh, KVl, B_DIM * NTOK, 1024, 2);

    attn_wmma_kernel<<<dim3(L_DIM / 64, NH, B_DIM), 256, ATT_SMEM>>>(Qh, Ql, KVh, KVl, Oh, Ol);

    tgemm_kernel<<<dim3(4, 64), 256, TG_SMEM>>>(
        Oh, Ol, nullptr, nullptr, Wth + 6 * (size_t)WSLOT, Wtl + 6 * (size_t)WSLOT,
        bp, out, nullptr, nullptr, B_DIM * L_DIM, 512, 0);
}

// round 13
// speedup vs baseline: 1.1751x; 1.0159x over previous
#include <cuda_runtime.h>
#include <cuda_bf16.h>
#include <mma.h>
#include <math.h>
#include <cstdint>

using namespace nvcuda;

#define B_DIM 8
#define L_DIM 1024
#define C_DIM 512
#define NP    1243
#define NTOK  2267
#define NH    8
#define HD    64
#define LN_EPS 1e-5f
#define OFF_MX 987
#define QSCALE 0.18033688f   // 0.125 * log2(e); folded into Q for exp2 softmax

// ---------------- scratch ----------------
__device__ __align__(128) float g_P0[B_DIM * NP * C_DIM];
__device__ __align__(128) float g_P1[B_DIM * NP * C_DIM];
__device__ __align__(128) __nv_bfloat16 g_P0h[B_DIM * NP * C_DIM],    g_P0l[B_DIM * NP * C_DIM];
__device__ __align__(128) __nv_bfloat16 g_P2h[B_DIM * NP * C_DIM],    g_P2l[B_DIM * NP * C_DIM];
__device__ __align__(128) __nv_bfloat16 g_mh [B_DIM * L_DIM * C_DIM], g_ml [B_DIM * L_DIM * C_DIM];
__device__ __align__(128) __nv_bfloat16 g_Qh [B_DIM * L_DIM * C_DIM], g_Ql [B_DIM * L_DIM * C_DIM];
__device__ __align__(128) __nv_bfloat16 g_KVh[B_DIM * NTOK * 2 * C_DIM], g_KVl[B_DIM * NTOK * 2 * C_DIM];
__device__ __align__(128) __nv_bfloat16 g_Oh [B_DIM * L_DIM * C_DIM], g_Ol [B_DIM * L_DIM * C_DIM];
#define WSLOT (512 * 512)
__device__ __align__(128) __nv_bfloat16 g_Wth[7 * WSLOT + 512 * 1024], g_Wtl[7 * WSLOT + 512 * 1024];

// ---------------- helpers ----------------
__device__ __forceinline__ uint32_t smem_u32(const void* p) {
    uint32_t a;
    asm("{ .reg .u64 t; cvta.to.shared.u64 t, %1; cvt.u32.u64 %0, t; }" : "=r"(a) : "l"(p));
    return a;
}
__device__ __forceinline__ void cp16(uint32_t dst, const void* src) {
    asm volatile("cp.async.cg.shared.global [%0], [%1], 16;" :: "r"(dst), "l"(src) : "memory");
}
__device__ __forceinline__ void cp16z(uint32_t dst, const void* src, int sz) {
    asm volatile("cp.async.cg.shared.global [%0], [%1], 16, %2;" :: "r"(dst), "l"(src), "r"(sz) : "memory");
}
#define CP_COMMIT() asm volatile("cp.async.commit_group;" ::: "memory")
#define CP_WAIT1()  asm volatile("cp.async.wait_group 1;" ::: "memory")
#define CP_WAIT0()  asm volatile("cp.async.wait_group 0;" ::: "memory")

__device__ __forceinline__ uint32_t pk2(float a, float b) {
    __nv_bfloat162 t(__float2bfloat16(a), __float2bfloat16(b));
    return *(uint32_t*)&t;
}
__device__ __forceinline__ void split4(const float* v, uint2& hi, uint2& lo) {
    __nv_bfloat16 h[4]; float r[4];
#pragma unroll
    for (int u = 0; u < 4; u++) { h[u] = __float2bfloat16(v[u]); r[u] = v[u] - __bfloat162float(h[u]); }
    __nv_bfloat162 h01(h[0], h[1]), h23(h[2], h[3]);
    hi.x = *(uint32_t*)&h01; hi.y = *(uint32_t*)&h23;
    lo.x = pk2(r[0], r[1]);  lo.y = pk2(r[2], r[3]);
}

// ---------------- combined weight transpose + split ----------------
__global__ void wsplit8_kernel(const float* W0, const float* W1, const float* W2, const float* W3,
                               const float* W4, const float* W5, const float* W6, const float* W7,
                               __nv_bfloat16* __restrict__ Th, __nv_bfloat16* __restrict__ Tl)
{
    __shared__ float t[32][33];
    int slot = blockIdx.z;
    const float* W = (slot == 0) ? W0 : (slot == 1) ? W1 : (slot == 2) ? W2 : (slot == 3) ? W3 :
                     (slot == 4) ? W4 : (slot == 5) ? W5 : (slot == 6) ? W6 : W7;
    int N = (slot == 7) ? 1024 : 512;
    int n0 = blockIdx.x * 32, k0 = blockIdx.y * 32;
    if (n0 >= N) return;
    __nv_bfloat16* th = Th + (size_t)slot * WSLOT;
    __nv_bfloat16* tl = Tl + (size_t)slot * WSLOT;
    int tx = threadIdx.x, ty = threadIdx.y;
    for (int i = ty; i < 32; i += 8) t[i][tx] = W[(size_t)(k0 + i) * N + n0 + tx];
    __syncthreads();
    for (int i = ty; i < 32; i += 8) {
        float v = t[tx][i];
        __nv_bfloat16 h = __float2bfloat16(v);
        size_t o = (size_t)(n0 + i) * 512 + k0 + tx;
        th[o] = h; tl[o] = __float2bfloat16(v - __bfloat162float(h));
    }
}

__global__ void mcvt_kernel(const float* __restrict__ m, __nv_bfloat16* __restrict__ mh,
                            __nv_bfloat16* __restrict__ ml)
{
    int i = (blockIdx.x * blockDim.x + threadIdx.x) * 4;
    if (i >= B_DIM * L_DIM * C_DIM) return;
    float4 v4 = *(const float4*)&m[i];
    float v[4] = { v4.x, v4.y, v4.z, v4.w };
    uint2 hi, lo;
    split4(v, hi, lo);
    *(uint2*)&mh[i] = hi;
    *(uint2*)&ml[i] = lo;
}

// ---------------- pooling (avg + max merged) ----------------
__global__ void pool_all_kernel(const float* __restrict__ x, float* __restrict__ P0,
                                __nv_bfloat16* __restrict__ Ph, __nv_bfloat16* __restrict__ Pl)
{
    int tok = blockIdx.x, b = blockIdx.y, c = threadIdx.x;
    float v;
    if (tok < 987) {
        int t = tok, n;
        if      (t < 441) { n = 21; }
        else if (t < 697) { n = 16; t -= 441; }
        else if (t < 866) { n = 13; t -= 697; }
        else              { n = 11; t -= 866; }
        int p = t / n, q = t - p * n;
        int hs = (p * 64) / n, he = ((p + 1) * 64 + n - 1) / n;
        int ws = (q * 64) / n, we = ((q + 1) * 64 + n - 1) / n;
        float s = 0.f;
        for (int h = hs; h < he; h++) {
            const float* xr = x + (((size_t)b * 4096) + (size_t)h * 64) * C_DIM + c;
            for (int w = ws; w < we; w++) s += xr[(size_t)w * C_DIM];
        }
        v = s / (float)((he - hs) * (we - ws));
    } else {
        int t = tok - 987;
        int p = t >> 4, q = t & 15;
        float mx = -1e30f;
        for (int h = p * 4; h < p * 4 + 4; h++) {
            const float* xr = x + (((size_t)b * 4096) + (size_t)h * 64) * C_DIM + c;
            for (int w = q * 4; w < q * 4 + 4; w++) mx = fmaxf(mx, xr[(size_t)w * C_DIM]);
        }
        v = mx;
    }
    size_t o = ((size_t)b * NP + tok) * C_DIM + c;
    P0[o] = v;
    __nv_bfloat16 h16 = __float2bfloat16(v);
    Ph[o] = h16; Pl[o] = __float2bfloat16(v - __bfloat162float(h16));
}

// =====================================================================
// GEMM mainloop (bf16x3, 128x128 tile, K=512); 2 blocks/SM via lb(256,2)
// =====================================================================
#define STG0    4096
#define STG_SZ  40960
#define TG_SMEM (4096 + 2 * 40960)
#define CPITCH  136

// cgemm: conv-res (0..4) + Wq (5, pre-scaled by QSCALE). grid = (4, 143).
__global__ __launch_bounds__(256, 2) void cgemm_kernel(
    const __nv_bfloat16* __restrict__ P0h, const __nv_bfloat16* __restrict__ P0l,
    const __nv_bfloat16* __restrict__ mh,  const __nv_bfloat16* __restrict__ ml,
    const __nv_bfloat16* __restrict__ Wth, const __nv_bfloat16* __restrict__ Wtl,
    const float* bp0, const float* bp1, const float* bp2, const float* bp3, const float* bp4,
    const float* __restrict__ P0, float* __restrict__ P1,
    __nv_bfloat16* __restrict__ Qh, __nv_bfloat16* __restrict__ Ql)
{
    extern __shared__ char sm_raw[];
    const __nv_bfloat16** aptrs = (const __nv_bfloat16**)(sm_raw + 16);
    uint32_t sb = smem_u32(sm_raw);

    int tid = threadIdx.x;
    int ti = blockIdx.y;
    int branch, tstart;
    if      (ti < 28) { branch = 0; tstart = 0;  }
    else if (ti < 44) { branch = 1; tstart = 28; }
    else if (ti < 55) { branch = 2; tstart = 44; }
    else if (ti < 63) { branch = 3; tstart = 55; }
    else if (ti < 79) { branch = 4; tstart = 63; }
    else              { branch = 5; tstart = 79; }
    const int npx_t[6]  = { 441, 256, 169, 121, 256, 0 };
    const int toff_t[6] = { 0, 441, 697, 866, 987, 0 };
    int npx = npx_t[branch], toffc = toff_t[branch];
    int M = (branch < 5) ? 8 * npx : 8192;
    int brow = (ti - tstart) * 128;
    int bcol = blockIdx.x * 128;
    const float* bias = (branch == 0) ? bp0 : (branch == 1) ? bp1 : (branch == 2) ? bp2 :
                        (branch == 3) ? bp3 : (branch == 4) ? bp4 : nullptr;
    const __nv_bfloat16* Bh = Wth + (size_t)branch * WSLOT;
    const __nv_bfloat16* Bl = Wtl + (size_t)branch * WSLOT;

    if (tid < 128) {
        int arow = brow + tid;
        if (arow >= M) arow = M - 1;
        const __nv_bfloat16 *ph, *pl;
        if (branch < 5) {
            int b = arow / npx, t = arow - (arow / npx) * npx;
            size_t o = ((size_t)b * NP + toffc + t) * 512;
            ph = P0h + o; pl = P0l + o;
        } else {
            size_t o = (size_t)arow * 512;
            ph = mh + o; pl = ml + o;
        }
        aptrs[tid] = ph; aptrs[128 + tid] = pl;
    }
    __syncthreads();

    int wid = tid >> 5;
    int wm = wid & 1, wn = wid >> 1;

    wmma::fragment<wmma::accumulator, 16, 16, 16, float> acc[4][2];
#pragma unroll
    for (int mi = 0; mi < 4; mi++)
#pragma unroll
        for (int ni = 0; ni < 2; ni++)
            wmma::fill_fragment(acc[mi][ni], 0.f);

    {
        uint32_t st = sb + STG0;
#pragma unroll
        for (int w = 0; w < 8; w++) {
            int ci = tid + w * 256;
            int region = ci >> 9, idx = ci & 511;
            int row = idx >> 2, ch = idx & 3;
            const __nv_bfloat16* src;
            if (region < 2) src = aptrs[region * 128 + row] + ch * 8;
            else            src = ((region == 2) ? Bh : Bl) + (size_t)(bcol + row) * 512 + ch * 8;
            cp16(st + region * 10240 + row * 80 + ch * 16, src);
        }
        CP_COMMIT();
    }

    for (int j = 0; j < 16; j++) {
        if (j + 1 < 16) {
            uint32_t st = sb + STG0 + ((j + 1) & 1) * STG_SZ;
            int koff = (j + 1) * 32;
#pragma unroll
            for (int w = 0; w < 8; w++) {
                int ci = tid + w * 256;
                int region = ci >> 9, idx = ci & 511;
                int row = idx >> 2, ch = idx & 3;
                const __nv_bfloat16* src;
                if (region < 2) src = aptrs[region * 128 + row] + koff + ch * 8;
                else            src = ((region == 2) ? Bh : Bl) + (size_t)(bcol + row) * 512 + koff + ch * 8;
                cp16(st + region * 10240 + row * 80 + ch * 16, src);
            }
            CP_COMMIT();
            CP_WAIT1();
        } else {
            CP_WAIT0();
        }
        __syncthreads();

        const __nv_bfloat16* st = (const __nv_bfloat16*)(sm_raw + STG0 + (j & 1) * STG_SZ);
        const __nv_bfloat16* As_h = st;
        const __nv_bfloat16* As_l = st + 5120;
        const __nv_bfloat16* Bs_h = st + 10240;
        const __nv_bfloat16* Bs_l = st + 15360;

#pragma unroll
        for (int kk = 0; kk < 2; kk++) {
            wmma::fragment<wmma::matrix_a, 16, 16, 16, __nv_bfloat16, wmma::row_major> fah[4], fal[4];
            wmma::fragment<wmma::matrix_b, 16, 16, 16, __nv_bfloat16, wmma::col_major> fbh[2], fbl[2];
#pragma unroll
            for (int mi = 0; mi < 4; mi++) {
                int r = wm * 64 + mi * 16;
                wmma::load_matrix_sync(fah[mi], As_h + r * 40 + kk * 16, 40);
                wmma::load_matrix_sync(fal[mi], As_l + r * 40 + kk * 16, 40);
            }
#pragma unroll
            for (int ni = 0; ni < 2; ni++) {
                int c = wn * 32 + ni * 16;
                wmma::load_matrix_sync(fbh[ni], Bs_h + c * 40 + kk * 16, 40);
                wmma::load_matrix_sync(fbl[ni], Bs_l + c * 40 + kk * 16, 40);
            }
#pragma unroll
            for (int mi = 0; mi < 4; mi++)
#pragma unroll
                for (int ni = 0; ni < 2; ni++) {
                    wmma::mma_sync(acc[mi][ni], fah[mi], fbh[ni], acc[mi][ni]);
                    wmma::mma_sync(acc[mi][ni], fah[mi], fbl[ni], acc[mi][ni]);
                    wmma::mma_sync(acc[mi][ni], fal[mi], fbh[ni], acc[mi][ni]);
                }
        }
        __syncthreads();
    }

    float* Cs = (float*)(sm_raw + STG0);
#pragma unroll
    for (int mi = 0; mi < 4; mi++)
#pragma unroll
        for (int ni = 0; ni < 2; ni++)
            wmma::store_matrix_sync(Cs + (wm * 64 + mi * 16) * CPITCH + wn * 32 + ni * 16,
                                    acc[mi][ni], CPITCH, wmma::mem_row_major);
    __syncthreads();

    int lane = tid & 31, wrow = tid >> 5;
    for (int rr = wrow; rr < 128; rr += 8) {
        int r = brow + rr;
        if (r >= M) continue;
        int col0 = lane * 4;
        float4 o = *(float4*)&Cs[rr * CPITCH + col0];
        int col = bcol + col0;
        if (branch < 5) {
            o.x += bias[col];     o.y += bias[col + 1];
            o.z += bias[col + 2]; o.w += bias[col + 3];
            int b = r / npx, t = r - (r / npx) * npx;
            size_t g = ((size_t)b * NP + toffc + t) * 512;
            float4 rv = *(const float4*)&P0[g + col];
            o.x += rv.x; o.y += rv.y; o.z += rv.z; o.w += rv.w;
            *(float4*)&P1[g + col] = o;
        } else {
            size_t g = (size_t)r * 512 + col;
            float vv[4] = { o.x * QSCALE, o.y * QSCALE, o.z * QSCALE, o.w * QSCALE };
            uint2 hi, lo;
            split4(vv, hi, lo);
            *(uint2*)&Qh[g] = hi;
            *(uint2*)&Ql[g] = lo;
        }
    }
}

// tgemm: generic (Wkv mode 2, Wp mode 0)
__global__ __launch_bounds__(256, 2) void tgemm_kernel(
    const __nv_bfloat16* __restrict__ Ah, const __nv_bfloat16* __restrict__ Al,
    const __nv_bfloat16* __restrict__ A2h, const __nv_bfloat16* __restrict__ A2l,
    const __nv_bfloat16* __restrict__ Bh, const __nv_bfloat16* __restrict__ Bl,
    const float* __restrict__ bias,
    float* __restrict__ Cout,
    __nv_bfloat16* __restrict__ outh, __nv_bfloat16* __restrict__ outl,
    int M, int N, int mode)
{
    extern __shared__ char sm_raw[];
    const __nv_bfloat16** aptrs = (const __nv_bfloat16**)(sm_raw + 16);
    uint32_t sb = smem_u32(sm_raw);

    int tid = threadIdx.x;
    int brow = blockIdx.y * 128, bcol = blockIdx.x * 128;

    if (tid < 128) {
        int arow = brow + tid;
        if (arow >= M) arow = M - 1;
        const __nv_bfloat16 *ph, *pl;
        if (mode == 0) {
            size_t o = (size_t)arow * 512; ph = Ah + o; pl = Al + o;
        } else {
            int b = arow / NTOK, t = arow - (arow / NTOK) * NTOK;
            if (t < NP) { size_t o = ((size_t)b * NP + t) * 512; ph = Ah + o; pl = Al + o; }
            else        { size_t o = ((size_t)b * L_DIM + (t - NP)) * 512; ph = A2h + o; pl = A2l + o; }
        }
        aptrs[tid] = ph; aptrs[128 + tid] = pl;
    }
    __syncthreads();

    int wid = tid >> 5;
    int wm = wid & 1, wn = wid >> 1;

    wmma::fragment<wmma::accumulator, 16, 16, 16, float> acc[4][2];
#pragma unroll
    for (int mi = 0; mi < 4; mi++)
#pragma unroll
        for (int ni = 0; ni < 2; ni++)
            wmma::fill_fragment(acc[mi][ni], 0.f);

    {
        uint32_t st = sb + STG0;
#pragma unroll
        for (int w = 0; w < 8; w++) {
            int ci = tid + w * 256;
            int region = ci >> 9, idx = ci & 511;
            int row = idx >> 2, ch = idx & 3;
            const __nv_bfloat16* src;
            if (region < 2) src = aptrs[region * 128 + row] + ch * 8;
            else            src = ((region == 2) ? Bh : Bl) + (size_t)(bcol + row) * 512 + ch * 8;
            cp16(st + region * 10240 + row * 80 + ch * 16, src);
        }
        CP_COMMIT();
    }

    for (int j = 0; j < 16; j++) {
        if (j + 1 < 16) {
            uint32_t st = sb + STG0 + ((j + 1) & 1) * STG_SZ;
            int koff = (j + 1) * 32;
#pragma unroll
            for (int w = 0; w < 8; w++) {
                int ci = tid + w * 256;
                int region = ci >> 9, idx = ci & 511;
                int row = idx >> 2, ch = idx & 3;
                const __nv_bfloat16* src;
                if (region < 2) src = aptrs[region * 128 + row] + koff + ch * 8;
                else            src = ((region == 2) ? Bh : Bl) + (size_t)(bcol + row) * 512 + koff + ch * 8;
                cp16(st + region * 10240 + row * 80 + ch * 16, src);
            }
            CP_COMMIT();
            CP_WAIT1();
        } else {
            CP_WAIT0();
        }
        __syncthreads();

        const __nv_bfloat16* st = (const __nv_bfloat16*)(sm_raw + STG0 + (j & 1) * STG_SZ);
        const __nv_bfloat16* As_h = st;
        const __nv_bfloat16* As_l = st + 5120;
        const __nv_bfloat16* Bs_h = st + 10240;
        const __nv_bfloat16* Bs_l = st + 15360;

#pragma unroll
        for (int kk = 0; kk < 2; kk++) {
            wmma::fragment<wmma::matrix_a, 16, 16, 16, __nv_bfloat16, wmma::row_major> fah[4], fal[4];
            wmma::fragment<wmma::matrix_b, 16, 16, 16, __nv_bfloat16, wmma::col_major> fbh[2], fbl[2];
#pragma unroll
            for (int mi = 0; mi < 4; mi++) {
                int r = wm * 64 + mi * 16;
                wmma::load_matrix_sync(fah[mi], As_h + r * 40 + kk * 16, 40);
                wmma::load_matrix_sync(fal[mi], As_l + r * 40 + kk * 16, 40);
            }
#pragma unroll
            for (int ni = 0; ni < 2; ni++) {
                int c = wn * 32 + ni * 16;
                wmma::load_matrix_sync(fbh[ni], Bs_h + c * 40 + kk * 16, 40);
                wmma::load_matrix_sync(fbl[ni], Bs_l + c * 40 + kk * 16, 40);
            }
#pragma unroll
            for (int mi = 0; mi < 4; mi++)
#pragma unroll
                for (int ni = 0; ni < 2; ni++) {
                    wmma::mma_sync(acc[mi][ni], fah[mi], fbh[ni], acc[mi][ni]);
                    wmma::mma_sync(acc[mi][ni], fah[mi], fbl[ni], acc[mi][ni]);
                    wmma::mma_sync(acc[mi][ni], fal[mi], fbh[ni], acc[mi][ni]);
                }
        }
        __syncthreads();
    }

    float* Cs = (float*)(sm_raw + STG0);
#pragma unroll
    for (int mi = 0; mi < 4; mi++)
#pragma unroll
        for (int ni = 0; ni < 2; ni++)
            wmma::store_matrix_sync(Cs + (wm * 64 + mi * 16) * CPITCH + wn * 32 + ni * 16,
                                    acc[mi][ni], CPITCH, wmma::mem_row_major);
    __syncthreads();

    int lane = tid & 31, wrow = tid >> 5;
    for (int rr = wrow; rr < 128; rr += 8) {
        int r = brow + rr;
        if (r >= M) continue;
        int col0 = lane * 4;
        float4 o = *(float4*)&Cs[rr * CPITCH + col0];
        int col = bcol + col0;
        if (bias) {
            o.x += bias[col];     o.y += bias[col + 1];
            o.z += bias[col + 2]; o.w += bias[col + 3];
        }
        if (outh) {
            size_t g = (size_t)r * N + col;
            float vv[4] = { o.x, o.y, o.z, o.w };
            uint2 hi, lo;
            split4(vv, hi, lo);
            *(uint2*)&outh[g] = hi;
            *(uint2*)&outl[g] = lo;
        } else {
            *(float4*)&Cout[(size_t)r * N + col] = o;
        }
    }
}

// ---------------- mx copy (SMEM-tiled transpose) ----------------
__global__ void mx_copy_kernel(const float* __restrict__ P1, float* __restrict__ out2)
{
    __shared__ float t[32][33];
    int b = blockIdx.z;
    int t0 = blockIdx.x * 32;
    int c0 = blockIdx.y * 32;
    int tx = threadIdx.x, ty = threadIdx.y;
    for (int i = ty; i < 32; i += 8)
        t[i][tx] = P1[(((size_t)b * NP) + OFF_MX + t0 + i) * 512 + c0 + tx];
    __syncthreads();
    for (int i = ty; i < 32; i += 8)
        out2[(((size_t)b * 512) + c0 + i) * 256 + t0 + tx] = t[tx][i];
}

// ---------------- layernorm -> bf16 hi/lo ----------------
__global__ void ln_kernel(const float* __restrict__ X, const float* __restrict__ g,
                          const float* __restrict__ be,
                          __nv_bfloat16* __restrict__ Yh, __nv_bfloat16* __restrict__ Yl)
{
    int row = blockIdx.x, tid = threadIdx.x;
    float4 v = ((const float4*)(X + (size_t)row * C_DIM))[tid];
    float s  = v.x + v.y + v.z + v.w;
    float s2 = v.x * v.x + v.y * v.y + v.z * v.z + v.w * v.w;
#pragma unroll
    for (int o = 16; o >= 1; o >>= 1) {
        s  += __shfl_xor_sync(0xffffffffu, s,  o);
        s2 += __shfl_xor_sync(0xffffffffu, s2, o);
    }
    __shared__ float ws[4], ws2[4];
    int wid = tid >> 5, lane = tid & 31;
    if (lane == 0) { ws[wid] = s; ws2[wid] = s2; }
    __syncthreads();
    float ts = ws[0] + ws[1] + ws[2] + ws[3], ts2 = ws2[0] + ws2[1] + ws2[2] + ws2[3];
    float mean = ts * (1.f / C_DIM);
    float var  = ts2 * (1.f / C_DIM) - mean * mean;
    float rstd = rsqrtf(var + LN_EPS);
    float4 gg = ((const float4*)g)[tid], bb = ((const float4*)be)[tid];
    float y[4] = { (v.x - mean) * rstd * gg.x + bb.x, (v.y - mean) * rstd * gg.y + bb.y,
                   (v.z - mean) * rstd * gg.z + bb.z, (v.w - mean) * rstd * gg.w + bb.w };
    size_t o = (size_t)row * C_DIM + tid * 4;
    uint2 hi, lo;
    split4(y, hi, lo);
    *(uint2*)&Yh[o] = hi;
    *(uint2*)&Yl[o] = lo;
}

// =====================================================================
// wmma flash attention: 64-q tile, 256 thr, fragment-resident O,
// 3 syncs/iter (V+K prefetch at top), exp2 softmax (scale folded into Q).
// SMEM = 109,824 B -> 2 blocks/SM.
// =====================================================================
#define QP 72
#define SP 68
#define ATT_SMEM (10 * 64 * QP * 2 + 64 * SP * 4 + 256)   // 109824

__global__ __launch_bounds__(256, 2) void attn_wmma_kernel(
    const __nv_bfloat16* __restrict__ Qh, const __nv_bfloat16* __restrict__ Ql,
    const __nv_bfloat16* __restrict__ KVh, const __nv_bfloat16* __restrict__ KVl,
    __nv_bfloat16* __restrict__ Oh, __nv_bfloat16* __restrict__ Ol)
{
    extern __shared__ char smc[];
    __nv_bfloat16* sQh  = (__nv_bfloat16*)smc;
    __nv_bfloat16* sQl  = sQh + 64 * QP;
    __nv_bfloat16* sK_h[2] = { sQl + 64 * QP,        sQl + 3 * 64 * QP };
    __nv_bfloat16* sK_l[2] = { sQl + 2 * 64 * QP,    sQl + 4 * 64 * QP };
    __nv_bfloat16* sVh  = sQl + 5 * 64 * QP;
    __nv_bfloat16* sVl  = sVh + 64 * QP;
    __nv_bfloat16* sPh  = sVl + 64 * QP;
    __nv_bfloat16* sPl  = sPh + 64 * QP;
    float* Ss = (float*)(sPl + 64 * QP);   // [64][68]
    float* alphaSm = Ss + 64 * SP;         // [64]

    int tid = threadIdx.x;
    int b = blockIdx.z, h = blockIdx.y, l0 = blockIdx.x * 64;
    int warp = tid >> 5;
    int wm = (warp & 1) * 32, wn = (warp >> 1) * 16;
    int ty = tid >> 4, tx = tid & 15;

    size_t kvbase = (size_t)b * NTOK * 1024 + h * 64;

    // rowmap init
    for (int i = tid; i < 64 * SP; i += 256) Ss[i] = (float)(i / SP);
    __syncthreads();
    wmma::fragment<wmma::accumulator, 16, 16, 16, float> of[2];
    int rowidx0[8];
    {
        wmma::load_matrix_sync(of[0], Ss + wm * SP + wn, SP, wmma::mem_row_major);
#pragma unroll
        for (int e = 0; e < 8; e++) rowidx0[e] = (int)of[0].x[e];
        wmma::fill_fragment(of[0], 0.f);
        wmma::fill_fragment(of[1], 0.f);
    }
    __syncthreads();

    // pre-loop: group {Q hi/lo + K tile 0}
    {
#pragma unroll
        for (int w = 0; w < 4; w++) {
            int ci = tid + w * 256;
            int arr = ci >> 9, idx = ci & 511;
            int row = idx >> 3, ch = idx & 7;
            const __nv_bfloat16* src = (arr ? Ql : Qh) +
                (((size_t)b * L_DIM) + l0 + row) * 512 + h * 64 + ch * 8;
            cp16(smem_u32((arr ? sQl : sQh) + row * QP + ch * 8), src);
        }
#pragma unroll
        for (int w = 0; w < 4; w++) {
            int ci = tid + w * 256;
            int arr = ci >> 9, idx = ci & 511;
            int row = idx >> 3, ch = idx & 7;
            const __nv_bfloat16* src = (arr ? KVl : KVh) + kvbase + (size_t)row * 1024 + ch * 8;
            cp16(smem_u32((arr ? sK_l[0] : sK_h[0]) + row * QP + ch * 8), src);
        }
        CP_COMMIT();
    }

    float mrow[4] = { -1e30f, -1e30f, -1e30f, -1e30f };
    float lrow[4] = {};

    for (int kt = 0; kt < 36; kt++) {
        int kbase = kt * 64;
        int kb = kt & 1;
        CP_WAIT0();            // K(kt) landed (and Q on kt=0); all older groups done
        __syncthreads();       // orders PV(kt-1) reads of sV before V(kt) writes below

        // prefetch V(kt) (group 1) — covered by S-MMA + softmax
        {
#pragma unroll
            for (int w = 0; w < 4; w++) {
                int ci = tid + w * 256;
                int arr = ci >> 9, idx = ci & 511;
                int row = idx >> 3, ch = idx & 7;
                int kg = kbase + row;
                const __nv_bfloat16* src = (arr ? KVl : KVh) + kvbase
                    + (size_t)(kg < NTOK ? kg : 0) * 1024 + 512 + ch * 8;
                cp16z(smem_u32((arr ? sVl : sVh) + row * QP + ch * 8),
                      src, (kg < NTOK) ? 16 : 0);
            }
            CP_COMMIT();
        }
        // prefetch K(kt+1) (group 2) — covered by full iteration
        if (kt + 1 < 36) {
            int nkb = (kt + 1) & 1;
#pragma unroll
            for (int w = 0; w < 4; w++) {
                int ci = tid + w * 256;
                int arr = ci >> 9, idx = ci & 511;
                int row = idx >> 3, ch = idx & 7;
                int kg = kbase + 64 + row;
                const __nv_bfloat16* src = (arr ? KVl : KVh) + kvbase
                    + (size_t)(kg < NTOK ? kg : 0) * 1024 + ch * 8;
                cp16z(smem_u32((arr ? sK_l[nkb] : sK_h[nkb]) + row * QP + ch * 8),
                      src, (kg < NTOK) ? 16 : 0);
            }
            CP_COMMIT();
        }

        // ---- S = Q K^T (Q pre-scaled by 0.125*log2e) ----
        {
            wmma::fragment<wmma::accumulator, 16, 16, 16, float> sf[2];
            wmma::fill_fragment(sf[0], 0.f);
            wmma::fill_fragment(sf[1], 0.f);
#pragma unroll
            for (int k = 0; k < 4; k++) {
                wmma::fragment<wmma::matrix_b, 16, 16, 16, __nv_bfloat16, wmma::col_major> fbh, fbl;
                wmma::load_matrix_sync(fbh, sK_h[kb] + wn * QP + k * 16, QP);
                wmma::load_matrix_sync(fbl, sK_l[kb] + wn * QP + k * 16, QP);
#pragma unroll
                for (int mi = 0; mi < 2; mi++) {
                    wmma::fragment<wmma::matrix_a, 16, 16, 16, __nv_bfloat16, wmma::row_major> fah, fal;
                    wmma::load_matrix_sync(fah, sQh + (wm + mi * 16) * QP + k * 16, QP);
                    wmma::load_matrix_sync(fal, sQl + (wm + mi * 16) * QP + k * 16, QP);
                    wmma::mma_sync(sf[mi], fah, fbh, sf[mi]);
                    wmma::mma_sync(sf[mi], fah, fbl, sf[mi]);
                    wmma::mma_sync(sf[mi], fal, fbh, sf[mi]);
                }
            }
            wmma::store_matrix_sync(Ss + wm * SP + wn, sf[0], SP, wmma::mem_row_major);
            wmma::store_matrix_sync(Ss + (wm + 16) * SP + wn, sf[1], SP, wmma::mem_row_major);
        }
        __syncthreads();

        // ---- scalar online softmax (log2 domain, exp2) ----
        float s[4][4], tmax[4];
#pragma unroll
        for (int i = 0; i < 4; i++) {
            float4 sv = *(const float4*)&Ss[(ty * 4 + i) * SP + tx * 4];
            s[i][0] = sv.x; s[i][1] = sv.y; s[i][2] = sv.z; s[i][3] = sv.w;
            tmax[i] = -1e30f;
#pragma unroll
            for (int j = 0; j < 4; j++) {
                int cg = kbase + tx * 4 + j;
                if (cg >= NTOK) s[i][j] = -1e30f;
                tmax[i] = fmaxf(tmax[i], s[i][j]);
            }
        }
#pragma unroll
        for (int i = 0; i < 4; i++)
#pragma unroll
            for (int o = 8; o >= 1; o >>= 1)
                tmax[i] = fmaxf(tmax[i], __shfl_xor_sync(0xffffffffu, tmax[i], o));
        float alpha[4], rsum[4];
#pragma unroll
        for (int i = 0; i < 4; i++) {
            float mnew = fmaxf(mrow[i], tmax[i]);
            alpha[i] = exp2f(mrow[i] - mnew);
            mrow[i] = mnew;
            float rs = 0.f;
#pragma unroll
            for (int j = 0; j < 4; j++) {
                float p = (s[i][j] > -1e29f) ? exp2f(s[i][j] - mnew) : 0.f;
                s[i][j] = p; rs += p;
            }
            rsum[i] = rs;
            lrow[i] = lrow[i] * alpha[i];
        }
#pragma unroll
        for (int i = 0; i < 4; i++) {
#pragma unroll
            for (int o = 8; o >= 1; o >>= 1)
                rsum[i] += __shfl_xor_sync(0xffffffffu, rsum[i], o);
            lrow[i] += rsum[i];
        }
        if (tx == 0) {
#pragma unroll
            for (int i = 0; i < 4; i++) alphaSm[ty * 4 + i] = alpha[i];
        }
#pragma unroll
        for (int i = 0; i < 4; i++) {
            int r = ty * 4 + i;
            uint2 hi, lo;
            split4(s[i], hi, lo);
            *(uint2*)&sPh[r * QP + tx * 4] = hi;
            *(uint2*)&sPl[r * QP + tx * 4] = lo;
        }
        // retire V(kt): pending {V(kt), K(kt+1)} -> wait1; last tile: wait0
        if (kt + 1 < 36) { CP_WAIT1(); } else { CP_WAIT0(); }
        __syncthreads();

        // ---- rescale fragment-resident O, PV accumulate in place ----
#pragma unroll
        for (int e = 0; e < 8; e++) {
            of[0].x[e] *= alphaSm[rowidx0[e]];
            of[1].x[e] *= alphaSm[rowidx0[e] + 16];
        }
        {
#pragma unroll
            for (int k = 0; k < 4; k++) {
                wmma::fragment<wmma::matrix_b, 16, 16, 16, __nv_bfloat16, wmma::row_major> fbh, fbl;
                wmma::load_matrix_sync(fbh, sVh + k * 16 * QP + wn, QP);
                wmma::load_matrix_sync(fbl, sVl + k * 16 * QP + wn, QP);
#pragma unroll
                for (int mi = 0; mi < 2; mi++) {
                    wmma::fragment<wmma::matrix_a, 16, 16, 16, __nv_bfloat16, wmma::row_major> fah, fal;
                    wmma::load_matrix_sync(fah, sPh + (wm + mi * 16) * QP + k * 16, QP);
                    wmma::load_matrix_sync(fal, sPl + (wm + mi * 16) * QP + k * 16, QP);
                    wmma::mma_sync(of[mi], fah, fbh, of[mi]);
                    wmma::mma_sync(of[mi], fah, fbl, of[mi]);
                    wmma::mma_sync(of[mi], fal, fbh, of[mi]);
                }
            }
        }
        // no post-PV sync: next iteration's top sync orders sV/sP reads
        // before the next V prefetch writes (issued post-top-sync).
    }

    // ---- epilogue ----
    __syncthreads();
#pragma unroll
    for (int mi = 0; mi < 2; mi++)
        wmma::store_matrix_sync(Ss + (wm + mi * 16) * SP + wn, of[mi], SP, wmma::mem_row_major);
    __syncthreads();
#pragma unroll
    for (int i = 0; i < 4; i++) {
        float inv = 1.f / lrow[i];
        int r = ty * 4 + i;
        size_t o = (((size_t)b * L_DIM) + l0 + r) * C_DIM + h * HD + tx * 4;
        float4 tv = *(const float4*)&Ss[r * SP + tx * 4];
        float vv[4] = { tv.x * inv, tv.y * inv, tv.z * inv, tv.w * inv };
        uint2 hi, lo;
        split4(vv, hi, lo);
        *(uint2*)&Oh[o] = hi;
        *(uint2*)&Ol[o] = lo;
    }
}

// ---------------- launch ----------------
extern "C" void kernel_launch(void* const* d_in, const int* in_sizes, int n_in,
                              void* d_out, int out_size)
{
    const float* x    = (const float*)d_in[0];
    const float* m    = (const float*)d_in[1];
    const float* wsrc5[5] = { (const float*)d_in[2], (const float*)d_in[4], (const float*)d_in[6],
                              (const float*)d_in[8], (const float*)d_in[10] };
    const float* bsrc5[5] = { (const float*)d_in[3], (const float*)d_in[5], (const float*)d_in[7],
                              (const float*)d_in[9], (const float*)d_in[11] };
    const float* ln_g = (const float*)d_in[12];
    const float* ln_b = (const float*)d_in[13];
    const float* Wq   = (const float*)d_in[14];
    const float* Wkv  = (const float*)d_in[15];
    const float* Wp   = (const float*)d_in[16];
    const float* bp   = (const float*)d_in[17];
    float* out  = (float*)d_out;
    float* out2 = (float*)d_out + (size_t)B_DIM * L_DIM * C_DIM;

    float *P0, *P1;
    __nv_bfloat16 *P0h, *P0l, *P2h, *P2l, *mh, *ml, *Qh, *Ql, *KVh, *KVl, *Oh, *Ol, *Wth, *Wtl;
    cudaGetSymbolAddress((void**)&P0,  g_P0);
    cudaGetSymbolAddress((void**)&P1,  g_P1);
    cudaGetSymbolAddress((void**)&P0h, g_P0h);
    cudaGetSymbolAddress((void**)&P0l, g_P0l);
    cudaGetSymbolAddress((void**)&P2h, g_P2h);
    cudaGetSymbolAddress((void**)&P2l, g_P2l);
    cudaGetSymbolAddress((void**)&mh,  g_mh);
    cudaGetSymbolAddress((void**)&ml,  g_ml);
    cudaGetSymbolAddress((void**)&Qh,  g_Qh);
    cudaGetSymbolAddress((void**)&Ql,  g_Ql);
    cudaGetSymbolAddress((void**)&KVh, g_KVh);
    cudaGetSymbolAddress((void**)&KVl, g_KVl);
    cudaGetSymbolAddress((void**)&Oh,  g_Oh);
    cudaGetSymbolAddress((void**)&Ol,  g_Ol);
    cudaGetSymbolAddress((void**)&Wth, g_Wth);
    cudaGetSymbolAddress((void**)&Wtl, g_Wtl);

    cudaFuncSetAttribute(cgemm_kernel,     cudaFuncAttributeMaxDynamicSharedMemorySize, TG_SMEM);
    cudaFuncSetAttribute(tgemm_kernel,     cudaFuncAttributeMaxDynamicSharedMemorySize, TG_SMEM);
    cudaFuncSetAttribute(attn_wmma_kernel, cudaFuncAttributeMaxDynamicSharedMemorySize, ATT_SMEM);

    wsplit8_kernel<<<dim3(32, 16, 8), dim3(32, 8)>>>(
        wsrc5[0], wsrc5[1], wsrc5[2], wsrc5[3], wsrc5[4], Wq, Wp, Wkv, Wth, Wtl);
    mcvt_kernel<<<(B_DIM * L_DIM * C_DIM / 4 + 255) / 256, 256>>>(m, mh, ml);

    pool_all_kernel<<<dim3(NP, B_DIM), 512>>>(x, P0, P0h, P0l);

    cgemm_kernel<<<dim3(4, 143), 256, TG_SMEM>>>(
        P0h, P0l, mh, ml, Wth, Wtl,
        bsrc5[0], bsrc5[1], bsrc5[2], bsrc5[3], bsrc5[4],
        P0, P1, Qh, Ql);

    mx_copy_kernel<<<dim3(8, 16, B_DIM), dim3(32, 8)>>>(P1, out2);
    ln_kernel<<<B_DIM * NP, 128>>>(P1, ln_g, ln_b, P2h, P2l);

    tgemm_kernel<<<dim3(8, (B_DIM * NTOK + 127) / 128), 256, TG_SMEM>>>(
        P2h, P2l, mh, ml, Wth + 7 * (size_t)WSLOT, Wtl + 7 * (size_t)WSLOT,
        nullptr, nullptr, KVh, KVl, B_DIM * NTOK, 1024, 2);

    attn_wmma_kernel<<<dim3(L_DIM / 64, NH, B_DIM), 256, ATT_SMEM>>>(Qh, Ql, KVh, KVl, Oh, Ol);

    tgemm_kernel<<<dim3(4, 64), 256, TG_SMEM>>>(
        Oh, Ol, nullptr, nullptr, Wth + 6 * (size_t)WSLOT, Wtl + 6 * (size_t)WSLOT,
        bp, out, nullptr, nullptr, B_DIM * L_DIM, 512, 0);
}

// round 14
// speedup vs baseline: 1.2367x; 1.0525x over previous
#include <cuda_runtime.h>
#include <cuda_bf16.h>
#include <mma.h>
#include <math.h>
#include <cstdint>

using namespace nvcuda;

#define B_DIM 8
#define L_DIM 1024
#define C_DIM 512
#define NP    1243
#define NTOK  2267
#define NH    8
#define HD    64
#define LN_EPS 1e-5f
#define OFF_MX 987
#define QSCALE 0.18033688f   // 0.125 * log2(e)

// ---------------- scratch ----------------
__device__ __align__(128) float g_P0[B_DIM * NP * C_DIM];
__device__ __align__(128) float g_P1[B_DIM * NP * C_DIM];
__device__ __align__(128) __nv_bfloat16 g_P0h[B_DIM * NP * C_DIM],    g_P0l[B_DIM * NP * C_DIM];
__device__ __align__(128) __nv_bfloat16 g_P2h[B_DIM * NP * C_DIM],    g_P2l[B_DIM * NP * C_DIM];
__device__ __align__(128) __nv_bfloat16 g_mh [B_DIM * L_DIM * C_DIM], g_ml [B_DIM * L_DIM * C_DIM];
__device__ __align__(128) __nv_bfloat16 g_Qh [B_DIM * L_DIM * C_DIM];
__device__ __align__(128) __nv_bfloat16 g_KVh[B_DIM * NTOK * 2 * C_DIM], g_KVl[B_DIM * NTOK * 2 * C_DIM];
__device__ __align__(128) __nv_bfloat16 g_Oh [B_DIM * L_DIM * C_DIM], g_Ol [B_DIM * L_DIM * C_DIM];
#define WSLOT (512 * 512)
__device__ __align__(128) __nv_bfloat16 g_Wth[7 * WSLOT + 512 * 1024], g_Wtl[7 * WSLOT + 512 * 1024];

// ---------------- helpers ----------------
__device__ __forceinline__ uint32_t smem_u32(const void* p) {
    uint32_t a;
    asm("{ .reg .u64 t; cvta.to.shared.u64 t, %1; cvt.u32.u64 %0, t; }" : "=r"(a) : "l"(p));
    return a;
}
__device__ __forceinline__ void cp16(uint32_t dst, const void* src) {
    asm volatile("cp.async.cg.shared.global [%0], [%1], 16;" :: "r"(dst), "l"(src) : "memory");
}
__device__ __forceinline__ void cp16z(uint32_t dst, const void* src, int sz) {
    asm volatile("cp.async.cg.shared.global [%0], [%1], 16, %2;" :: "r"(dst), "l"(src), "r"(sz) : "memory");
}
#define CP_COMMIT() asm volatile("cp.async.commit_group;" ::: "memory")
#define CP_WAIT1()  asm volatile("cp.async.wait_group 1;" ::: "memory")
#define CP_WAIT0()  asm volatile("cp.async.wait_group 0;" ::: "memory")

__device__ __forceinline__ uint32_t pk2(float a, float b) {
    __nv_bfloat162 t(__float2bfloat16(a), __float2bfloat16(b));
    return *(uint32_t*)&t;
}
__device__ __forceinline__ void split4(const float* v, uint2& hi, uint2& lo) {
    __nv_bfloat16 h[4]; float r[4];
#pragma unroll
    for (int u = 0; u < 4; u++) { h[u] = __float2bfloat16(v[u]); r[u] = v[u] - __bfloat162float(h[u]); }
    __nv_bfloat162 h01(h[0], h[1]), h23(h[2], h[3]);
    hi.x = *(uint32_t*)&h01; hi.y = *(uint32_t*)&h23;
    lo.x = pk2(r[0], r[1]);  lo.y = pk2(r[2], r[3]);
}

// ---------------- combined weight transpose + split ----------------
__global__ void wsplit8_kernel(const float* W0, const float* W1, const float* W2, const float* W3,
                               const float* W4, const float* W5, const float* W6, const float* W7,
                               __nv_bfloat16* __restrict__ Th, __nv_bfloat16* __restrict__ Tl)
{
    __shared__ float t[32][33];
    int slot = blockIdx.z;
    const float* W = (slot == 0) ? W0 : (slot == 1) ? W1 : (slot == 2) ? W2 : (slot == 3) ? W3 :
                     (slot == 4) ? W4 : (slot == 5) ? W5 : (slot == 6) ? W6 : W7;
    int N = (slot == 7) ? 1024 : 512;
    int n0 = blockIdx.x * 32, k0 = blockIdx.y * 32;
    if (n0 >= N) return;
    __nv_bfloat16* th = Th + (size_t)slot * WSLOT;
    __nv_bfloat16* tl = Tl + (size_t)slot * WSLOT;
    int tx = threadIdx.x, ty = threadIdx.y;
    for (int i = ty; i < 32; i += 8) t[i][tx] = W[(size_t)(k0 + i) * N + n0 + tx];
    __syncthreads();
    for (int i = ty; i < 32; i += 8) {
        float v = t[tx][i];
        __nv_bfloat16 h = __float2bfloat16(v);
        size_t o = (size_t)(n0 + i) * 512 + k0 + tx;
        th[o] = h; tl[o] = __float2bfloat16(v - __bfloat162float(h));
    }
}

__global__ void mcvt_kernel(const float* __restrict__ m, __nv_bfloat16* __restrict__ mh,
                            __nv_bfloat16* __restrict__ ml)
{
    int i = (blockIdx.x * blockDim.x + threadIdx.x) * 4;
    if (i >= B_DIM * L_DIM * C_DIM) return;
    float4 v4 = *(const float4*)&m[i];
    float v[4] = { v4.x, v4.y, v4.z, v4.w };
    uint2 hi, lo;
    split4(v, hi, lo);
    *(uint2*)&mh[i] = hi;
    *(uint2*)&ml[i] = lo;
}

// ---------------- pooling (avg + max merged) ----------------
__global__ void pool_all_kernel(const float* __restrict__ x, float* __restrict__ P0,
                                __nv_bfloat16* __restrict__ Ph, __nv_bfloat16* __restrict__ Pl)
{
    int tok = blockIdx.x, b = blockIdx.y, c = threadIdx.x;
    float v;
    if (tok < 987) {
        int t = tok, n;
        if      (t < 441) { n = 21; }
        else if (t < 697) { n = 16; t -= 441; }
        else if (t < 866) { n = 13; t -= 697; }
        else              { n = 11; t -= 866; }
        int p = t / n, q = t - p * n;
        int hs = (p * 64) / n, he = ((p + 1) * 64 + n - 1) / n;
        int ws = (q * 64) / n, we = ((q + 1) * 64 + n - 1) / n;
        float s = 0.f;
        for (int h = hs; h < he; h++) {
            const float* xr = x + (((size_t)b * 4096) + (size_t)h * 64) * C_DIM + c;
            for (int w = ws; w < we; w++) s += xr[(size_t)w * C_DIM];
        }
        v = s / (float)((he - hs) * (we - ws));
    } else {
        int t = tok - 987;
        int p = t >> 4, q = t & 15;
        float mx = -1e30f;
        for (int h = p * 4; h < p * 4 + 4; h++) {
            const float* xr = x + (((size_t)b * 4096) + (size_t)h * 64) * C_DIM + c;
            for (int w = q * 4; w < q * 4 + 4; w++) mx = fmaxf(mx, xr[(size_t)w * C_DIM]);
        }
        v = mx;
    }
    size_t o = ((size_t)b * NP + tok) * C_DIM + c;
    P0[o] = v;
    __nv_bfloat16 h16 = __float2bfloat16(v);
    Ph[o] = h16; Pl[o] = __float2bfloat16(v - __bfloat162float(h16));
}

// =====================================================================
// GEMM mainloop (bf16x3, 128x128 tile, K=512); 2 blocks/SM
// =====================================================================
#define STG0    4096
#define STG_SZ  40960
#define TG_SMEM (4096 + 2 * 40960)
#define CPITCH  136

// cgemm: conv-res (0..4) + Wq (5, pre-scaled, hi-only out). grid = (4, 143).
__global__ __launch_bounds__(256, 2) void cgemm_kernel(
    const __nv_bfloat16* __restrict__ P0h, const __nv_bfloat16* __restrict__ P0l,
    const __nv_bfloat16* __restrict__ mh,  const __nv_bfloat16* __restrict__ ml,
    const __nv_bfloat16* __restrict__ Wth, const __nv_bfloat16* __restrict__ Wtl,
    const float* bp0, const float* bp1, const float* bp2, const float* bp3, const float* bp4,
    const float* __restrict__ P0, float* __restrict__ P1,
    __nv_bfloat16* __restrict__ Qh)
{
    extern __shared__ char sm_raw[];
    const __nv_bfloat16** aptrs = (const __nv_bfloat16**)(sm_raw + 16);
    uint32_t sb = smem_u32(sm_raw);

    int tid = threadIdx.x;
    int ti = blockIdx.y;
    int branch, tstart;
    if      (ti < 28) { branch = 0; tstart = 0;  }
    else if (ti < 44) { branch = 1; tstart = 28; }
    else if (ti < 55) { branch = 2; tstart = 44; }
    else if (ti < 63) { branch = 3; tstart = 55; }
    else if (ti < 79) { branch = 4; tstart = 63; }
    else              { branch = 5; tstart = 79; }
    const int npx_t[6]  = { 441, 256, 169, 121, 256, 0 };
    const int toff_t[6] = { 0, 441, 697, 866, 987, 0 };
    int npx = npx_t[branch], toffc = toff_t[branch];
    int M = (branch < 5) ? 8 * npx : 8192;
    int brow = (ti - tstart) * 128;
    int bcol = blockIdx.x * 128;
    const float* bias = (branch == 0) ? bp0 : (branch == 1) ? bp1 : (branch == 2) ? bp2 :
                        (branch == 3) ? bp3 : (branch == 4) ? bp4 : nullptr;
    const __nv_bfloat16* Bh = Wth + (size_t)branch * WSLOT;
    const __nv_bfloat16* Bl = Wtl + (size_t)branch * WSLOT;

    if (tid < 128) {
        int arow = brow + tid;
        if (arow >= M) arow = M - 1;
        const __nv_bfloat16 *ph, *pl;
        if (branch < 5) {
            int b = arow / npx, t = arow - (arow / npx) * npx;
            size_t o = ((size_t)b * NP + toffc + t) * 512;
            ph = P0h + o; pl = P0l + o;
        } else {
            size_t o = (size_t)arow * 512;
            ph = mh + o; pl = ml + o;
        }
        aptrs[tid] = ph; aptrs[128 + tid] = pl;
    }
    __syncthreads();

    int wid = tid >> 5;
    int wm = wid & 1, wn = wid >> 1;

    wmma::fragment<wmma::accumulator, 16, 16, 16, float> acc[4][2];
#pragma unroll
    for (int mi = 0; mi < 4; mi++)
#pragma unroll
        for (int ni = 0; ni < 2; ni++)
            wmma::fill_fragment(acc[mi][ni], 0.f);

    {
        uint32_t st = sb + STG0;
#pragma unroll
        for (int w = 0; w < 8; w++) {
            int ci = tid + w * 256;
            int region = ci >> 9, idx = ci & 511;
            int row = idx >> 2, ch = idx & 3;
            const __nv_bfloat16* src;
            if (region < 2) src = aptrs[region * 128 + row] + ch * 8;
            else            src = ((region == 2) ? Bh : Bl) + (size_t)(bcol + row) * 512 + ch * 8;
            cp16(st + region * 10240 + row * 80 + ch * 16, src);
        }
        CP_COMMIT();
    }

    for (int j = 0; j < 16; j++) {
        if (j + 1 < 16) {
            uint32_t st = sb + STG0 + ((j + 1) & 1) * STG_SZ;
            int koff = (j + 1) * 32;
#pragma unroll
            for (int w = 0; w < 8; w++) {
                int ci = tid + w * 256;
                int region = ci >> 9, idx = ci & 511;
                int row = idx >> 2, ch = idx & 3;
                const __nv_bfloat16* src;
                if (region < 2) src = aptrs[region * 128 + row] + koff + ch * 8;
                else            src = ((region == 2) ? Bh : Bl) + (size_t)(bcol + row) * 512 + koff + ch * 8;
                cp16(st + region * 10240 + row * 80 + ch * 16, src);
            }
            CP_COMMIT();
            CP_WAIT1();
        } else {
            CP_WAIT0();
        }
        __syncthreads();

        const __nv_bfloat16* st = (const __nv_bfloat16*)(sm_raw + STG0 + (j & 1) * STG_SZ);
        const __nv_bfloat16* As_h = st;
        const __nv_bfloat16* As_l = st + 5120;
        const __nv_bfloat16* Bs_h = st + 10240;
        const __nv_bfloat16* Bs_l = st + 15360;

#pragma unroll
        for (int kk = 0; kk < 2; kk++) {
            wmma::fragment<wmma::matrix_a, 16, 16, 16, __nv_bfloat16, wmma::row_major> fah[4], fal[4];
            wmma::fragment<wmma::matrix_b, 16, 16, 16, __nv_bfloat16, wmma::col_major> fbh[2], fbl[2];
#pragma unroll
            for (int mi = 0; mi < 4; mi++) {
                int r = wm * 64 + mi * 16;
                wmma::load_matrix_sync(fah[mi], As_h + r * 40 + kk * 16, 40);
                wmma::load_matrix_sync(fal[mi], As_l + r * 40 + kk * 16, 40);
            }
#pragma unroll
            for (int ni = 0; ni < 2; ni++) {
                int c = wn * 32 + ni * 16;
                wmma::load_matrix_sync(fbh[ni], Bs_h + c * 40 + kk * 16, 40);
                wmma::load_matrix_sync(fbl[ni], Bs_l + c * 40 + kk * 16, 40);
            }
#pragma unroll
            for (int mi = 0; mi < 4; mi++)
#pragma unroll
                for (int ni = 0; ni < 2; ni++) {
                    wmma::mma_sync(acc[mi][ni], fah[mi], fbh[ni], acc[mi][ni]);
                    wmma::mma_sync(acc[mi][ni], fah[mi], fbl[ni], acc[mi][ni]);
                    wmma::mma_sync(acc[mi][ni], fal[mi], fbh[ni], acc[mi][ni]);
                }
        }
        __syncthreads();
    }

    float* Cs = (float*)(sm_raw + STG0);
#pragma unroll
    for (int mi = 0; mi < 4; mi++)
#pragma unroll
        for (int ni = 0; ni < 2; ni++)
            wmma::store_matrix_sync(Cs + (wm * 64 + mi * 16) * CPITCH + wn * 32 + ni * 16,
                                    acc[mi][ni], CPITCH, wmma::mem_row_major);
    __syncthreads();

    int lane = tid & 31, wrow = tid >> 5;
    for (int rr = wrow; rr < 128; rr += 8) {
        int r = brow + rr;
        if (r >= M) continue;
        int col0 = lane * 4;
        float4 o = *(float4*)&Cs[rr * CPITCH + col0];
        int col = bcol + col0;
        if (branch < 5) {
            o.x += bias[col];     o.y += bias[col + 1];
            o.z += bias[col + 2]; o.w += bias[col + 3];
            int b = r / npx, t = r - (r / npx) * npx;
            size_t g = ((size_t)b * NP + toffc + t) * 512;
            float4 rv = *(const float4*)&P0[g + col];
            o.x += rv.x; o.y += rv.y; o.z += rv.z; o.w += rv.w;
            *(float4*)&P1[g + col] = o;
        } else {
            size_t g = (size_t)r * 512 + col;
            __nv_bfloat162 h01(__float2bfloat16(o.x * QSCALE), __float2bfloat16(o.y * QSCALE));
            __nv_bfloat162 h23(__float2bfloat16(o.z * QSCALE), __float2bfloat16(o.w * QSCALE));
            uint2 hi;
            hi.x = *(uint32_t*)&h01; hi.y = *(uint32_t*)&h23;
            *(uint2*)&Qh[g] = hi;
        }
    }
}

// tgemm: generic (Wkv mode 2, Wp mode 0)
__global__ __launch_bounds__(256, 2) void tgemm_kernel(
    const __nv_bfloat16* __restrict__ Ah, const __nv_bfloat16* __restrict__ Al,
    const __nv_bfloat16* __restrict__ A2h, const __nv_bfloat16* __restrict__ A2l,
    const __nv_bfloat16* __restrict__ Bh, const __nv_bfloat16* __restrict__ Bl,
    const float* __restrict__ bias,
    float* __restrict__ Cout,
    __nv_bfloat16* __restrict__ outh, __nv_bfloat16* __restrict__ outl,
    int M, int N, int mode)
{
    extern __shared__ char sm_raw[];
    const __nv_bfloat16** aptrs = (const __nv_bfloat16**)(sm_raw + 16);
    uint32_t sb = smem_u32(sm_raw);

    int tid = threadIdx.x;
    int brow = blockIdx.y * 128, bcol = blockIdx.x * 128;

    if (tid < 128) {
        int arow = brow + tid;
        if (arow >= M) arow = M - 1;
        const __nv_bfloat16 *ph, *pl;
        if (mode == 0) {
            size_t o = (size_t)arow * 512; ph = Ah + o; pl = Al + o;
        } else {
            int b = arow / NTOK, t = arow - (arow / NTOK) * NTOK;
            if (t < NP) { size_t o = ((size_t)b * NP + t) * 512; ph = Ah + o; pl = Al + o; }
            else        { size_t o = ((size_t)b * L_DIM + (t - NP)) * 512; ph = A2h + o; pl = A2l + o; }
        }
        aptrs[tid] = ph; aptrs[128 + tid] = pl;
    }
    __syncthreads();

    int wid = tid >> 5;
    int wm = wid & 1, wn = wid >> 1;

    wmma::fragment<wmma::accumulator, 16, 16, 16, float> acc[4][2];
#pragma unroll
    for (int mi = 0; mi < 4; mi++)
#pragma unroll
        for (int ni = 0; ni < 2; ni++)
            wmma::fill_fragment(acc[mi][ni], 0.f);

    {
        uint32_t st = sb + STG0;
#pragma unroll
        for (int w = 0; w < 8; w++) {
            int ci = tid + w * 256;
            int region = ci >> 9, idx = ci & 511;
            int row = idx >> 2, ch = idx & 3;
            const __nv_bfloat16* src;
            if (region < 2) src = aptrs[region * 128 + row] + ch * 8;
            else            src = ((region == 2) ? Bh : Bl) + (size_t)(bcol + row) * 512 + ch * 8;
            cp16(st + region * 10240 + row * 80 + ch * 16, src);
        }
        CP_COMMIT();
    }

    for (int j = 0; j < 16; j++) {
        if (j + 1 < 16) {
            uint32_t st = sb + STG0 + ((j + 1) & 1) * STG_SZ;
            int koff = (j + 1) * 32;
#pragma unroll
            for (int w = 0; w < 8; w++) {
                int ci = tid + w * 256;
                int region = ci >> 9, idx = ci & 511;
                int row = idx >> 2, ch = idx & 3;
                const __nv_bfloat16* src;
                if (region < 2) src = aptrs[region * 128 + row] + koff + ch * 8;
                else            src = ((region == 2) ? Bh : Bl) + (size_t)(bcol + row) * 512 + koff + ch * 8;
                cp16(st + region * 10240 + row * 80 + ch * 16, src);
            }
            CP_COMMIT();
            CP_WAIT1();
        } else {
            CP_WAIT0();
        }
        __syncthreads();

        const __nv_bfloat16* st = (const __nv_bfloat16*)(sm_raw + STG0 + (j & 1) * STG_SZ);
        const __nv_bfloat16* As_h = st;
        const __nv_bfloat16* As_l = st + 5120;
        const __nv_bfloat16* Bs_h = st + 10240;
        const __nv_bfloat16* Bs_l = st + 15360;

#pragma unroll
        for (int kk = 0; kk < 2; kk++) {
            wmma::fragment<wmma::matrix_a, 16, 16, 16, __nv_bfloat16, wmma::row_major> fah[4], fal[4];
            wmma::fragment<wmma::matrix_b, 16, 16, 16, __nv_bfloat16, wmma::col_major> fbh[2], fbl[2];
#pragma unroll
            for (int mi = 0; mi < 4; mi++) {
                int r = wm * 64 + mi * 16;
                wmma::load_matrix_sync(fah[mi], As_h + r * 40 + kk * 16, 40);
                wmma::load_matrix_sync(fal[mi], As_l + r * 40 + kk * 16, 40);
            }
#pragma unroll
            for (int ni = 0; ni < 2; ni++) {
                int c = wn * 32 + ni * 16;
                wmma::load_matrix_sync(fbh[ni], Bs_h + c * 40 + kk * 16, 40);
                wmma::load_matrix_sync(fbl[ni], Bs_l + c * 40 + kk * 16, 40);
            }
#pragma unroll
            for (int mi = 0; mi < 4; mi++)
#pragma unroll
                for (int ni = 0; ni < 2; ni++) {
                    wmma::mma_sync(acc[mi][ni], fah[mi], fbh[ni], acc[mi][ni]);
                    wmma::mma_sync(acc[mi][ni], fah[mi], fbl[ni], acc[mi][ni]);
                    wmma::mma_sync(acc[mi][ni], fal[mi], fbh[ni], acc[mi][ni]);
                }
        }
        __syncthreads();
    }

    float* Cs = (float*)(sm_raw + STG0);
#pragma unroll
    for (int mi = 0; mi < 4; mi++)
#pragma unroll
        for (int ni = 0; ni < 2; ni++)
            wmma::store_matrix_sync(Cs + (wm * 64 + mi * 16) * CPITCH + wn * 32 + ni * 16,
                                    acc[mi][ni], CPITCH, wmma::mem_row_major);
    __syncthreads();

    int lane = tid & 31, wrow = tid >> 5;
    for (int rr = wrow; rr < 128; rr += 8) {
        int r = brow + rr;
        if (r >= M) continue;
        int col0 = lane * 4;
        float4 o = *(float4*)&Cs[rr * CPITCH + col0];
        int col = bcol + col0;
        if (bias) {
            o.x += bias[col];     o.y += bias[col + 1];
            o.z += bias[col + 2]; o.w += bias[col + 3];
        }
        if (outh) {
            size_t g = (size_t)r * N + col;
            float vv[4] = { o.x, o.y, o.z, o.w };
            uint2 hi, lo;
            split4(vv, hi, lo);
            *(uint2*)&outh[g] = hi;
            *(uint2*)&outl[g] = lo;
        } else {
            *(float4*)&Cout[(size_t)r * N + col] = o;
        }
    }
}

// ---------------- mx copy (SMEM-tiled transpose) ----------------
__global__ void mx_copy_kernel(const float* __restrict__ P1, float* __restrict__ out2)
{
    __shared__ float t[32][33];
    int b = blockIdx.z;
    int t0 = blockIdx.x * 32;
    int c0 = blockIdx.y * 32;
    int tx = threadIdx.x, ty = threadIdx.y;
    for (int i = ty; i < 32; i += 8)
        t[i][tx] = P1[(((size_t)b * NP) + OFF_MX + t0 + i) * 512 + c0 + tx];
    __syncthreads();
    for (int i = ty; i < 32; i += 8)
        out2[(((size_t)b * 512) + c0 + i) * 256 + t0 + tx] = t[tx][i];
}

// ---------------- layernorm -> bf16 hi/lo ----------------
__global__ void ln_kernel(const float* __restrict__ X, const float* __restrict__ g,
                          const float* __restrict__ be,
                          __nv_bfloat16* __restrict__ Yh, __nv_bfloat16* __restrict__ Yl)
{
    int row = blockIdx.x, tid = threadIdx.x;
    float4 v = ((const float4*)(X + (size_t)row * C_DIM))[tid];
    float s  = v.x + v.y + v.z + v.w;
    float s2 = v.x * v.x + v.y * v.y + v.z * v.z + v.w * v.w;
#pragma unroll
    for (int o = 16; o >= 1; o >>= 1) {
        s  += __shfl_xor_sync(0xffffffffu, s,  o);
        s2 += __shfl_xor_sync(0xffffffffu, s2, o);
    }
    __shared__ float ws[4], ws2[4];
    int wid = tid >> 5, lane = tid & 31;
    if (lane == 0) { ws[wid] = s; ws2[wid] = s2; }
    __syncthreads();
    float ts = ws[0] + ws[1] + ws[2] + ws[3], ts2 = ws2[0] + ws2[1] + ws2[2] + ws2[3];
    float mean = ts * (1.f / C_DIM);
    float var  = ts2 * (1.f / C_DIM) - mean * mean;
    float rstd = rsqrtf(var + LN_EPS);
    float4 gg = ((const float4*)g)[tid], bb = ((const float4*)be)[tid];
    float y[4] = { (v.x - mean) * rstd * gg.x + bb.x, (v.y - mean) * rstd * gg.y + bb.y,
                   (v.z - mean) * rstd * gg.z + bb.z, (v.w - mean) * rstd * gg.w + bb.w };
    size_t o = (size_t)row * C_DIM + tid * 4;
    uint2 hi, lo;
    split4(y, hi, lo);
    *(uint2*)&Yh[o] = hi;
    *(uint2*)&Yl[o] = lo;
}

// =====================================================================
// wmma flash attention: 64-q tile, 256 thr, fragment-resident O,
// S phase bf16x2 (Q hi only), PV phase bf16x3, 3 syncs/iter,
// exp2 softmax. SMEM = 100,608 B -> 2 blocks/SM.
// =====================================================================
#define QP 72
#define SP 68
#define ATT_SMEM (9 * 64 * QP * 2 + 64 * SP * 4 + 256)   // 82944 + 17408 + 256 = 100608

__global__ __launch_bounds__(256, 2) void attn_wmma_kernel(
    const __nv_bfloat16* __restrict__ Qh,
    const __nv_bfloat16* __restrict__ KVh, const __nv_bfloat16* __restrict__ KVl,
    __nv_bfloat16* __restrict__ Oh, __nv_bfloat16* __restrict__ Ol)
{
    extern __shared__ char smc[];
    __nv_bfloat16* sQh  = (__nv_bfloat16*)smc;
    __nv_bfloat16* sK_h[2] = { sQh + 64 * QP,       sQh + 3 * 64 * QP };
    __nv_bfloat16* sK_l[2] = { sQh + 2 * 64 * QP,   sQh + 4 * 64 * QP };
    __nv_bfloat16* sVh  = sQh + 5 * 64 * QP;
    __nv_bfloat16* sVl  = sVh + 64 * QP;
    __nv_bfloat16* sPh  = sVl + 64 * QP;
    __nv_bfloat16* sPl  = sPh + 64 * QP;
    float* Ss = (float*)(sPl + 64 * QP);   // [64][68]
    float* alphaSm = Ss + 64 * SP;         // [64]

    int tid = threadIdx.x;
    int b = blockIdx.z, h = blockIdx.y, l0 = blockIdx.x * 64;
    int warp = tid >> 5;
    int wm = (warp & 1) * 32, wn = (warp >> 1) * 16;
    int ty = tid >> 4, tx = tid & 15;

    size_t kvbase = (size_t)b * NTOK * 1024 + h * 64;

    // rowmap init
    for (int i = tid; i < 64 * SP; i += 256) Ss[i] = (float)(i / SP);
    __syncthreads();
    wmma::fragment<wmma::accumulator, 16, 16, 16, float> of[2];
    int rowidx0[8];
    {
        wmma::load_matrix_sync(of[0], Ss + wm * SP + wn, SP, wmma::mem_row_major);
#pragma unroll
        for (int e = 0; e < 8; e++) rowidx0[e] = (int)of[0].x[e];
        wmma::fill_fragment(of[0], 0.f);
        wmma::fill_fragment(of[1], 0.f);
    }
    __syncthreads();

    // pre-loop: group {Q hi + K tile 0}
    {
#pragma unroll
        for (int w = 0; w < 2; w++) {
            int ci = tid + w * 256;              // 0..511
            int row = ci >> 3, ch = ci & 7;
            const __nv_bfloat16* src = Qh +
                (((size_t)b * L_DIM) + l0 + row) * 512 + h * 64 + ch * 8;
            cp16(smem_u32(sQh + row * QP + ch * 8), src);
        }
#pragma unroll
        for (int w = 0; w < 4; w++) {
            int ci = tid + w * 256;
            int arr = ci >> 9, idx = ci & 511;
            int row = idx >> 3, ch = idx & 7;
            const __nv_bfloat16* src = (arr ? KVl : KVh) + kvbase + (size_t)row * 1024 + ch * 8;
            cp16(smem_u32((arr ? sK_l[0] : sK_h[0]) + row * QP + ch * 8), src);
        }
        CP_COMMIT();
    }

    float mrow[4] = { -1e30f, -1e30f, -1e30f, -1e30f };
    float lrow[4] = {};

    for (int kt = 0; kt < 36; kt++) {
        int kbase = kt * 64;
        int kb = kt & 1;
        CP_WAIT0();
        __syncthreads();

        // prefetch V(kt) (group 1)
        {
#pragma unroll
            for (int w = 0; w < 4; w++) {
                int ci = tid + w * 256;
                int arr = ci >> 9, idx = ci & 511;
                int row = idx >> 3, ch = idx & 7;
                int kg = kbase + row;
                const __nv_bfloat16* src = (arr ? KVl : KVh) + kvbase
                    + (size_t)(kg < NTOK ? kg : 0) * 1024 + 512 + ch * 8;
                cp16z(smem_u32((arr ? sVl : sVh) + row * QP + ch * 8),
                      src, (kg < NTOK) ? 16 : 0);
            }
            CP_COMMIT();
        }
        // prefetch K(kt+1) (group 2)
        if (kt + 1 < 36) {
            int nkb = (kt + 1) & 1;
#pragma unroll
            for (int w = 0; w < 4; w++) {
                int ci = tid + w * 256;
                int arr = ci >> 9, idx = ci & 511;
                int row = idx >> 3, ch = idx & 7;
                int kg = kbase + 64 + row;
                const __nv_bfloat16* src = (arr ? KVl : KVh) + kvbase
                    + (size_t)(kg < NTOK ? kg : 0) * 1024 + ch * 8;
                cp16z(smem_u32((arr ? sK_l[nkb] : sK_h[nkb]) + row * QP + ch * 8),
                      src, (kg < NTOK) ? 16 : 0);
            }
            CP_COMMIT();
        }

        // ---- S = Qh (Kh + Kl)  [bf16x2] ----
        {
            wmma::fragment<wmma::accumulator, 16, 16, 16, float> sf[2];
            wmma::fill_fragment(sf[0], 0.f);
            wmma::fill_fragment(sf[1], 0.f);
#pragma unroll
            for (int k = 0; k < 4; k++) {
                wmma::fragment<wmma::matrix_b, 16, 16, 16, __nv_bfloat16, wmma::col_major> fbh, fbl;
                wmma::load_matrix_sync(fbh, sK_h[kb] + wn * QP + k * 16, QP);
                wmma::load_matrix_sync(fbl, sK_l[kb] + wn * QP + k * 16, QP);
#pragma unroll
                for (int mi = 0; mi < 2; mi++) {
                    wmma::fragment<wmma::matrix_a, 16, 16, 16, __nv_bfloat16, wmma::row_major> fah;
                    wmma::load_matrix_sync(fah, sQh + (wm + mi * 16) * QP + k * 16, QP);
                    wmma::mma_sync(sf[mi], fah, fbh, sf[mi]);
                    wmma::mma_sync(sf[mi], fah, fbl, sf[mi]);
                }
            }
            wmma::store_matrix_sync(Ss + wm * SP + wn, sf[0], SP, wmma::mem_row_major);
            wmma::store_matrix_sync(Ss + (wm + 16) * SP + wn, sf[1], SP, wmma::mem_row_major);
        }
        __syncthreads();

        // ---- scalar online softmax (exp2 domain) ----
        float s[4][4], tmax[4];
#pragma unroll
        for (int i = 0; i < 4; i++) {
            float4 sv = *(const float4*)&Ss[(ty * 4 + i) * SP + tx * 4];
            s[i][0] = sv.x; s[i][1] = sv.y; s[i][2] = sv.z; s[i][3] = sv.w;
            tmax[i] = -1e30f;
#pragma unroll
            for (int j = 0; j < 4; j++) {
                int cg = kbase + tx * 4 + j;
                if (cg >= NTOK) s[i][j] = -1e30f;
                tmax[i] = fmaxf(tmax[i], s[i][j]);
            }
        }
#pragma unroll
        for (int i = 0; i < 4; i++)
#pragma unroll
            for (int o = 8; o >= 1; o >>= 1)
                tmax[i] = fmaxf(tmax[i], __shfl_xor_sync(0xffffffffu, tmax[i], o));
        float alpha[4], rsum[4];
#pragma unroll
        for (int i = 0; i < 4; i++) {
            float mnew = fmaxf(mrow[i], tmax[i]);
            alpha[i] = exp2f(mrow[i] - mnew);
            mrow[i] = mnew;
            float rs = 0.f;
#pragma unroll
            for (int j = 0; j < 4; j++) {
                float p = (s[i][j] > -1e29f) ? exp2f(s[i][j] - mnew) : 0.f;
                s[i][j] = p; rs += p;
            }
            rsum[i] = rs;
            lrow[i] = lrow[i] * alpha[i];
        }
#pragma unroll
        for (int i = 0; i < 4; i++) {
#pragma unroll
            for (int o = 8; o >= 1; o >>= 1)
                rsum[i] += __shfl_xor_sync(0xffffffffu, rsum[i], o);
            lrow[i] += rsum[i];
        }
        if (tx == 0) {
#pragma unroll
            for (int i = 0; i < 4; i++) alphaSm[ty * 4 + i] = alpha[i];
        }
#pragma unroll
        for (int i = 0; i < 4; i++) {
            int r = ty * 4 + i;
            uint2 hi, lo;
            split4(s[i], hi, lo);
            *(uint2*)&sPh[r * QP + tx * 4] = hi;
            *(uint2*)&sPl[r * QP + tx * 4] = lo;
        }
        if (kt + 1 < 36) { CP_WAIT1(); } else { CP_WAIT0(); }
        __syncthreads();

        // ---- rescale O, PV accumulate in place (bf16x3) ----
#pragma unroll
        for (int e = 0; e < 8; e++) {
            of[0].x[e] *= alphaSm[rowidx0[e]];
            of[1].x[e] *= alphaSm[rowidx0[e] + 16];
        }
        {
#pragma unroll
            for (int k = 0; k < 4; k++) {
                wmma::fragment<wmma::matrix_b, 16, 16, 16, __nv_bfloat16, wmma::row_major> fbh, fbl;
                wmma::load_matrix_sync(fbh, sVh + k * 16 * QP + wn, QP);
                wmma::load_matrix_sync(fbl, sVl + k * 16 * QP + wn, QP);
#pragma unroll
                for (int mi = 0; mi < 2; mi++) {
                    wmma::fragment<wmma::matrix_a, 16, 16, 16, __nv_bfloat16, wmma::row_major> fah, fal;
                    wmma::load_matrix_sync(fah, sPh + (wm + mi * 16) * QP + k * 16, QP);
                    wmma::load_matrix_sync(fal, sPl + (wm + mi * 16) * QP + k * 16, QP);
                    wmma::mma_sync(of[mi], fah, fbh, of[mi]);
                    wmma::mma_sync(of[mi], fah, fbl, of[mi]);
                    wmma::mma_sync(of[mi], fal, fbh, of[mi]);
                }
            }
        }
        // next iteration's top sync orders sV/sP reads before next V prefetch
    }

    // ---- epilogue ----
    __syncthreads();
#pragma unroll
    for (int mi = 0; mi < 2; mi++)
        wmma::store_matrix_sync(Ss + (wm + mi * 16) * SP + wn, of[mi], SP, wmma::mem_row_major);
    __syncthreads();
#pragma unroll
    for (int i = 0; i < 4; i++) {
        float inv = 1.f / lrow[i];
        int r = ty * 4 + i;
        size_t o = (((size_t)b * L_DIM) + l0 + r) * C_DIM + h * HD + tx * 4;
        float4 tv = *(const float4*)&Ss[r * SP + tx * 4];
        float vv[4] = { tv.x * inv, tv.y * inv, tv.z * inv, tv.w * inv };
        uint2 hi, lo;
        split4(vv, hi, lo);
        *(uint2*)&Oh[o] = hi;
        *(uint2*)&Ol[o] = lo;
    }
}

// ---------------- launch ----------------
extern "C" void kernel_launch(void* const* d_in, const int* in_sizes, int n_in,
                              void* d_out, int out_size)
{
    const float* x    = (const float*)d_in[0];
    const float* m    = (const float*)d_in[1];
    const float* wsrc5[5] = { (const float*)d_in[2], (const float*)d_in[4], (const float*)d_in[6],
                              (const float*)d_in[8], (const float*)d_in[10] };
    const float* bsrc5[5] = { (const float*)d_in[3], (const float*)d_in[5], (const float*)d_in[7],
                              (const float*)d_in[9], (const float*)d_in[11] };
    const float* ln_g = (const float*)d_in[12];
    const float* ln_b = (const float*)d_in[13];
    const float* Wq   = (const float*)d_in[14];
    const float* Wkv  = (const float*)d_in[15];
    const float* Wp   = (const float*)d_in[16];
    const float* bp   = (const float*)d_in[17];
    float* out  = (float*)d_out;
    float* out2 = (float*)d_out + (size_t)B_DIM * L_DIM * C_DIM;

    float *P0, *P1;
    __nv_bfloat16 *P0h, *P0l, *P2h, *P2l, *mh, *ml, *Qh, *KVh, *KVl, *Oh, *Ol, *Wth, *Wtl;
    cudaGetSymbolAddress((void**)&P0,  g_P0);
    cudaGetSymbolAddress((void**)&P1,  g_P1);
    cudaGetSymbolAddress((void**)&P0h, g_P0h);
    cudaGetSymbolAddress((void**)&P0l, g_P0l);
    cudaGetSymbolAddress((void**)&P2h, g_P2h);
    cudaGetSymbolAddress((void**)&P2l, g_P2l);
    cudaGetSymbolAddress((void**)&mh,  g_mh);
    cudaGetSymbolAddress((void**)&ml,  g_ml);
    cudaGetSymbolAddress((void**)&Qh,  g_Qh);
    cudaGetSymbolAddress((void**)&KVh, g_KVh);
    cudaGetSymbolAddress((void**)&KVl, g_KVl);
    cudaGetSymbolAddress((void**)&Oh,  g_Oh);
    cudaGetSymbolAddress((void**)&Ol,  g_Ol);
    cudaGetSymbolAddress((void**)&Wth, g_Wth);
    cudaGetSymbolAddress((void**)&Wtl, g_Wtl);

    cudaFuncSetAttribute(cgemm_kernel,     cudaFuncAttributeMaxDynamicSharedMemorySize, TG_SMEM);
    cudaFuncSetAttribute(tgemm_kernel,     cudaFuncAttributeMaxDynamicSharedMemorySize, TG_SMEM);
    cudaFuncSetAttribute(attn_wmma_kernel, cudaFuncAttributeMaxDynamicSharedMemorySize, ATT_SMEM);

    wsplit8_kernel<<<dim3(32, 16, 8), dim3(32, 8)>>>(
        wsrc5[0], wsrc5[1], wsrc5[2], wsrc5[3], wsrc5[4], Wq, Wp, Wkv, Wth, Wtl);
    mcvt_kernel<<<(B_DIM * L_DIM * C_DIM / 4 + 255) / 256, 256>>>(m, mh, ml);

    pool_all_kernel<<<dim3(NP, B_DIM), 512>>>(x, P0, P0h, P0l);

    cgemm_kernel<<<dim3(4, 143), 256, TG_SMEM>>>(
        P0h, P0l, mh, ml, Wth, Wtl,
        bsrc5[0], bsrc5[1], bsrc5[2], bsrc5[3], bsrc5[4],
        P0, P1, Qh);

    mx_copy_kernel<<<dim3(8, 16, B_DIM), dim3(32, 8)>>>(P1, out2);
    ln_kernel<<<B_DIM * NP, 128>>>(P1, ln_g, ln_b, P2h, P2l);

    tgemm_kernel<<<dim3(8, (B_DIM * NTOK + 127) / 128), 256, TG_SMEM>>>(
        P2h, P2l, mh, ml, Wth + 7 * (size_t)WSLOT, Wtl + 7 * (size_t)WSLOT,
        nullptr, nullptr, KVh, KVl, B_DIM * NTOK, 1024, 2);

    attn_wmma_kernel<<<dim3(L_DIM / 64, NH, B_DIM), 256, ATT_SMEM>>>(Qh, KVh, KVl, Oh, Ol);

    tgemm_kernel<<<dim3(4, 64), 256, TG_SMEM>>>(
        Oh, Ol, nullptr, nullptr, Wth + 6 * (size_t)WSLOT, Wtl + 6 * (size_t)WSLOT,
        bp, out, nullptr, nullptr, B_DIM * L_DIM, 512, 0);
}

// round 15
// speedup vs baseline: 1.3131x; 1.0617x over previous
#include <cuda_runtime.h>
#include <cuda_bf16.h>
#include <mma.h>
#include <math.h>
#include <cstdint>

using namespace nvcuda;

#define B_DIM 8
#define L_DIM 1024
#define C_DIM 512
#define NP    1243
#define NTOK  2267
#define NH    8
#define HD    64
#define LN_EPS 1e-5f
#define OFF_MX 987
#define QSCALE 0.18033688f   // 0.125 * log2(e)

// ---------------- scratch ----------------
__device__ __align__(128) float g_P0[B_DIM * NP * C_DIM];
__device__ __align__(128) float g_P1[B_DIM * NP * C_DIM];
__device__ __align__(128) __nv_bfloat16 g_P0h[B_DIM * NP * C_DIM],    g_P0l[B_DIM * NP * C_DIM];
__device__ __align__(128) __nv_bfloat16 g_P2h[B_DIM * NP * C_DIM],    g_P2l[B_DIM * NP * C_DIM];
__device__ __align__(128) __nv_bfloat16 g_mh [B_DIM * L_DIM * C_DIM], g_ml [B_DIM * L_DIM * C_DIM];
__device__ __align__(128) __nv_bfloat16 g_Qh [B_DIM * L_DIM * C_DIM];
__device__ __align__(128) __nv_bfloat16 g_KVh[B_DIM * NTOK * 2 * C_DIM], g_KVl[B_DIM * NTOK * 2 * C_DIM];
__device__ __align__(128) __nv_bfloat16 g_Oh [B_DIM * L_DIM * C_DIM], g_Ol [B_DIM * L_DIM * C_DIM];
#define WSLOT (512 * 512)
__device__ __align__(128) __nv_bfloat16 g_Wth[7 * WSLOT + 512 * 1024], g_Wtl[7 * WSLOT + 512 * 1024];

// ---------------- helpers ----------------
__device__ __forceinline__ uint32_t smem_u32(const void* p) {
    uint32_t a;
    asm("{ .reg .u64 t; cvta.to.shared.u64 t, %1; cvt.u32.u64 %0, t; }" : "=r"(a) : "l"(p));
    return a;
}
__device__ __forceinline__ void cp16(uint32_t dst, const void* src) {
    asm volatile("cp.async.cg.shared.global [%0], [%1], 16;" :: "r"(dst), "l"(src) : "memory");
}
__device__ __forceinline__ void cp16z(uint32_t dst, const void* src, int sz) {
    asm volatile("cp.async.cg.shared.global [%0], [%1], 16, %2;" :: "r"(dst), "l"(src), "r"(sz) : "memory");
}
#define CP_COMMIT() asm volatile("cp.async.commit_group;" ::: "memory")
#define CP_WAIT1()  asm volatile("cp.async.wait_group 1;" ::: "memory")
#define CP_WAIT0()  asm volatile("cp.async.wait_group 0;" ::: "memory")

__device__ __forceinline__ uint32_t pk2(float a, float b) {
    __nv_bfloat162 t(__float2bfloat16(a), __float2bfloat16(b));
    return *(uint32_t*)&t;
}
__device__ __forceinline__ void split4(const float* v, uint2& hi, uint2& lo) {
    __nv_bfloat16 h[4]; float r[4];
#pragma unroll
    for (int u = 0; u < 4; u++) { h[u] = __float2bfloat16(v[u]); r[u] = v[u] - __bfloat162float(h[u]); }
    __nv_bfloat162 h01(h[0], h[1]), h23(h[2], h[3]);
    hi.x = *(uint32_t*)&h01; hi.y = *(uint32_t*)&h23;
    lo.x = pk2(r[0], r[1]);  lo.y = pk2(r[2], r[3]);
}

// ---------------- combined weight transpose + split ----------------
__global__ void wsplit8_kernel(const float* W0, const float* W1, const float* W2, const float* W3,
                               const float* W4, const float* W5, const float* W6, const float* W7,
                               __nv_bfloat16* __restrict__ Th, __nv_bfloat16* __restrict__ Tl)
{
    __shared__ float t[32][33];
    int slot = blockIdx.z;
    const float* W = (slot == 0) ? W0 : (slot == 1) ? W1 : (slot == 2) ? W2 : (slot == 3) ? W3 :
                     (slot == 4) ? W4 : (slot == 5) ? W5 : (slot == 6) ? W6 : W7;
    int N = (slot == 7) ? 1024 : 512;
    int n0 = blockIdx.x * 32, k0 = blockIdx.y * 32;
    if (n0 >= N) return;
    __nv_bfloat16* th = Th + (size_t)slot * WSLOT;
    __nv_bfloat16* tl = Tl + (size_t)slot * WSLOT;
    int tx = threadIdx.x, ty = threadIdx.y;
    for (int i = ty; i < 32; i += 8) t[i][tx] = W[(size_t)(k0 + i) * N + n0 + tx];
    __syncthreads();
    for (int i = ty; i < 32; i += 8) {
        float v = t[tx][i];
        __nv_bfloat16 h = __float2bfloat16(v);
        size_t o = (size_t)(n0 + i) * 512 + k0 + tx;
        th[o] = h; tl[o] = __float2bfloat16(v - __bfloat162float(h));
    }
}

__global__ void mcvt_kernel(const float* __restrict__ m, __nv_bfloat16* __restrict__ mh,
                            __nv_bfloat16* __restrict__ ml)
{
    int i = (blockIdx.x * blockDim.x + threadIdx.x) * 4;
    if (i >= B_DIM * L_DIM * C_DIM) return;
    float4 v4 = *(const float4*)&m[i];
    float v[4] = { v4.x, v4.y, v4.z, v4.w };
    uint2 hi, lo;
    split4(v, hi, lo);
    *(uint2*)&mh[i] = hi;
    *(uint2*)&ml[i] = lo;
}

// ---------------- pooling (avg + max merged) ----------------
__global__ void pool_all_kernel(const float* __restrict__ x, float* __restrict__ P0,
                                __nv_bfloat16* __restrict__ Ph, __nv_bfloat16* __restrict__ Pl)
{
    int tok = blockIdx.x, b = blockIdx.y, c = threadIdx.x;
    float v;
    if (tok < 987) {
        int t = tok, n;
        if      (t < 441) { n = 21; }
        else if (t < 697) { n = 16; t -= 441; }
        else if (t < 866) { n = 13; t -= 697; }
        else              { n = 11; t -= 866; }
        int p = t / n, q = t - p * n;
        int hs = (p * 64) / n, he = ((p + 1) * 64 + n - 1) / n;
        int ws = (q * 64) / n, we = ((q + 1) * 64 + n - 1) / n;
        float s = 0.f;
        for (int h = hs; h < he; h++) {
            const float* xr = x + (((size_t)b * 4096) + (size_t)h * 64) * C_DIM + c;
            for (int w = ws; w < we; w++) s += xr[(size_t)w * C_DIM];
        }
        v = s / (float)((he - hs) * (we - ws));
    } else {
        int t = tok - 987;
        int p = t >> 4, q = t & 15;
        float mx = -1e30f;
        for (int h = p * 4; h < p * 4 + 4; h++) {
            const float* xr = x + (((size_t)b * 4096) + (size_t)h * 64) * C_DIM + c;
            for (int w = q * 4; w < q * 4 + 4; w++) mx = fmaxf(mx, xr[(size_t)w * C_DIM]);
        }
        v = mx;
    }
    size_t o = ((size_t)b * NP + tok) * C_DIM + c;
    P0[o] = v;
    __nv_bfloat16 h16 = __float2bfloat16(v);
    Ph[o] = h16; Pl[o] = __float2bfloat16(v - __bfloat162float(h16));
}

// =====================================================================
// GEMM mainloop (bf16x3, 128x128 tile, K=512); 2 blocks/SM
// =====================================================================
#define STG0    4096
#define STG_SZ  40960
#define TG_SMEM (4096 + 2 * 40960)
#define CPITCH  136

// cgemm: conv-res (0..4) + Wq (5, pre-scaled, hi-only out). grid = (4, 143).
__global__ __launch_bounds__(256, 2) void cgemm_kernel(
    const __nv_bfloat16* __restrict__ P0h, const __nv_bfloat16* __restrict__ P0l,
    const __nv_bfloat16* __restrict__ mh,  const __nv_bfloat16* __restrict__ ml,
    const __nv_bfloat16* __restrict__ Wth, const __nv_bfloat16* __restrict__ Wtl,
    const float* bp0, const float* bp1, const float* bp2, const float* bp3, const float* bp4,
    const float* __restrict__ P0, float* __restrict__ P1,
    __nv_bfloat16* __restrict__ Qh)
{
    extern __shared__ char sm_raw[];
    const __nv_bfloat16** aptrs = (const __nv_bfloat16**)(sm_raw + 16);
    uint32_t sb = smem_u32(sm_raw);

    int tid = threadIdx.x;
    int ti = blockIdx.y;
    int branch, tstart;
    if      (ti < 28) { branch = 0; tstart = 0;  }
    else if (ti < 44) { branch = 1; tstart = 28; }
    else if (ti < 55) { branch = 2; tstart = 44; }
    else if (ti < 63) { branch = 3; tstart = 55; }
    else if (ti < 79) { branch = 4; tstart = 63; }
    else              { branch = 5; tstart = 79; }
    const int npx_t[6]  = { 441, 256, 169, 121, 256, 0 };
    const int toff_t[6] = { 0, 441, 697, 866, 987, 0 };
    int npx = npx_t[branch], toffc = toff_t[branch];
    int M = (branch < 5) ? 8 * npx : 8192;
    int brow = (ti - tstart) * 128;
    int bcol = blockIdx.x * 128;
    const float* bias = (branch == 0) ? bp0 : (branch == 1) ? bp1 : (branch == 2) ? bp2 :
                        (branch == 3) ? bp3 : (branch == 4) ? bp4 : nullptr;
    const __nv_bfloat16* Bh = Wth + (size_t)branch * WSLOT;
    const __nv_bfloat16* Bl = Wtl + (size_t)branch * WSLOT;

    if (tid < 128) {
        int arow = brow + tid;
        if (arow >= M) arow = M - 1;
        const __nv_bfloat16 *ph, *pl;
        if (branch < 5) {
            int b = arow / npx, t = arow - (arow / npx) * npx;
            size_t o = ((size_t)b * NP + toffc + t) * 512;
            ph = P0h + o; pl = P0l + o;
        } else {
            size_t o = (size_t)arow * 512;
            ph = mh + o; pl = ml + o;
        }
        aptrs[tid] = ph; aptrs[128 + tid] = pl;
    }
    __syncthreads();

    int wid = tid >> 5;
    int wm = wid & 1, wn = wid >> 1;

    wmma::fragment<wmma::accumulator, 16, 16, 16, float> acc[4][2];
#pragma unroll
    for (int mi = 0; mi < 4; mi++)
#pragma unroll
        for (int ni = 0; ni < 2; ni++)
            wmma::fill_fragment(acc[mi][ni], 0.f);

    {
        uint32_t st = sb + STG0;
#pragma unroll
        for (int w = 0; w < 8; w++) {
            int ci = tid + w * 256;
            int region = ci >> 9, idx = ci & 511;
            int row = idx >> 2, ch = idx & 3;
            const __nv_bfloat16* src;
            if (region < 2) src = aptrs[region * 128 + row] + ch * 8;
            else            src = ((region == 2) ? Bh : Bl) + (size_t)(bcol + row) * 512 + ch * 8;
            cp16(st + region * 10240 + row * 80 + ch * 16, src);
        }
        CP_COMMIT();
    }

    for (int j = 0; j < 16; j++) {
        if (j + 1 < 16) {
            uint32_t st = sb + STG0 + ((j + 1) & 1) * STG_SZ;
            int koff = (j + 1) * 32;
#pragma unroll
            for (int w = 0; w < 8; w++) {
                int ci = tid + w * 256;
                int region = ci >> 9, idx = ci & 511;
                int row = idx >> 2, ch = idx & 3;
                const __nv_bfloat16* src;
                if (region < 2) src = aptrs[region * 128 + row] + koff + ch * 8;
                else            src = ((region == 2) ? Bh : Bl) + (size_t)(bcol + row) * 512 + koff + ch * 8;
                cp16(st + region * 10240 + row * 80 + ch * 16, src);
            }
            CP_COMMIT();
            CP_WAIT1();
        } else {
            CP_WAIT0();
        }
        __syncthreads();

        const __nv_bfloat16* st = (const __nv_bfloat16*)(sm_raw + STG0 + (j & 1) * STG_SZ);
        const __nv_bfloat16* As_h = st;
        const __nv_bfloat16* As_l = st + 5120;
        const __nv_bfloat16* Bs_h = st + 10240;
        const __nv_bfloat16* Bs_l = st + 15360;

#pragma unroll
        for (int kk = 0; kk < 2; kk++) {
            wmma::fragment<wmma::matrix_a, 16, 16, 16, __nv_bfloat16, wmma::row_major> fah[4], fal[4];
            wmma::fragment<wmma::matrix_b, 16, 16, 16, __nv_bfloat16, wmma::col_major> fbh[2], fbl[2];
#pragma unroll
            for (int mi = 0; mi < 4; mi++) {
                int r = wm * 64 + mi * 16;
                wmma::load_matrix_sync(fah[mi], As_h + r * 40 + kk * 16, 40);
                wmma::load_matrix_sync(fal[mi], As_l + r * 40 + kk * 16, 40);
            }
#pragma unroll
            for (int ni = 0; ni < 2; ni++) {
                int c = wn * 32 + ni * 16;
                wmma::load_matrix_sync(fbh[ni], Bs_h + c * 40 + kk * 16, 40);
                wmma::load_matrix_sync(fbl[ni], Bs_l + c * 40 + kk * 16, 40);
            }
#pragma unroll
            for (int mi = 0; mi < 4; mi++)
#pragma unroll
                for (int ni = 0; ni < 2; ni++) {
                    wmma::mma_sync(acc[mi][ni], fah[mi], fbh[ni], acc[mi][ni]);
                    wmma::mma_sync(acc[mi][ni], fah[mi], fbl[ni], acc[mi][ni]);
                    wmma::mma_sync(acc[mi][ni], fal[mi], fbh[ni], acc[mi][ni]);
                }
        }
        __syncthreads();
    }

    float* Cs = (float*)(sm_raw + STG0);
#pragma unroll
    for (int mi = 0; mi < 4; mi++)
#pragma unroll
        for (int ni = 0; ni < 2; ni++)
            wmma::store_matrix_sync(Cs + (wm * 64 + mi * 16) * CPITCH + wn * 32 + ni * 16,
                                    acc[mi][ni], CPITCH, wmma::mem_row_major);
    __syncthreads();

    int lane = tid & 31, wrow = tid >> 5;
    for (int rr = wrow; rr < 128; rr += 8) {
        int r = brow + rr;
        if (r >= M) continue;
        int col0 = lane * 4;
        float4 o = *(float4*)&Cs[rr * CPITCH + col0];
        int col = bcol + col0;
        if (branch < 5) {
            o.x += bias[col];     o.y += bias[col + 1];
            o.z += bias[col + 2]; o.w += bias[col + 3];
            int b = r / npx, t = r - (r / npx) * npx;
            size_t g = ((size_t)b * NP + toffc + t) * 512;
            float4 rv = *(const float4*)&P0[g + col];
            o.x += rv.x; o.y += rv.y; o.z += rv.z; o.w += rv.w;
            *(float4*)&P1[g + col] = o;
        } else {
            size_t g = (size_t)r * 512 + col;
            __nv_bfloat162 h01(__float2bfloat16(o.x * QSCALE), __float2bfloat16(o.y * QSCALE));
            __nv_bfloat162 h23(__float2bfloat16(o.z * QSCALE), __float2bfloat16(o.w * QSCALE));
            uint2 hi;
            hi.x = *(uint32_t*)&h01; hi.y = *(uint32_t*)&h23;
            *(uint2*)&Qh[g] = hi;
        }
    }
}

// tgemm: generic (Wkv mode 2, Wp mode 0)
__global__ __launch_bounds__(256, 2) void tgemm_kernel(
    const __nv_bfloat16* __restrict__ Ah, const __nv_bfloat16* __restrict__ Al,
    const __nv_bfloat16* __restrict__ A2h, const __nv_bfloat16* __restrict__ A2l,
    const __nv_bfloat16* __restrict__ Bh, const __nv_bfloat16* __restrict__ Bl,
    const float* __restrict__ bias,
    float* __restrict__ Cout,
    __nv_bfloat16* __restrict__ outh, __nv_bfloat16* __restrict__ outl,
    int M, int N, int mode)
{
    extern __shared__ char sm_raw[];
    const __nv_bfloat16** aptrs = (const __nv_bfloat16**)(sm_raw + 16);
    uint32_t sb = smem_u32(sm_raw);

    int tid = threadIdx.x;
    int brow = blockIdx.y * 128, bcol = blockIdx.x * 128;

    if (tid < 128) {
        int arow = brow + tid;
        if (arow >= M) arow = M - 1;
        const __nv_bfloat16 *ph, *pl;
        if (mode == 0) {
            size_t o = (size_t)arow * 512; ph = Ah + o; pl = Al + o;
        } else {
            int b = arow / NTOK, t = arow - (arow / NTOK) * NTOK;
            if (t < NP) { size_t o = ((size_t)b * NP + t) * 512; ph = Ah + o; pl = Al + o; }
            else        { size_t o = ((size_t)b * L_DIM + (t - NP)) * 512; ph = A2h + o; pl = A2l + o; }
        }
        aptrs[tid] = ph; aptrs[128 + tid] = pl;
    }
    __syncthreads();

    int wid = tid >> 5;
    int wm = wid & 1, wn = wid >> 1;

    wmma::fragment<wmma::accumulator, 16, 16, 16, float> acc[4][2];
#pragma unroll
    for (int mi = 0; mi < 4; mi++)
#pragma unroll
        for (int ni = 0; ni < 2; ni++)
            wmma::fill_fragment(acc[mi][ni], 0.f);

    {
        uint32_t st = sb + STG0;
#pragma unroll
        for (int w = 0; w < 8; w++) {
            int ci = tid + w * 256;
            int region = ci >> 9, idx = ci & 511;
            int row = idx >> 2, ch = idx & 3;
            const __nv_bfloat16* src;
            if (region < 2) src = aptrs[region * 128 + row] + ch * 8;
            else            src = ((region == 2) ? Bh : Bl) + (size_t)(bcol + row) * 512 + ch * 8;
            cp16(st + region * 10240 + row * 80 + ch * 16, src);
        }
        CP_COMMIT();
    }

    for (int j = 0; j < 16; j++) {
        if (j + 1 < 16) {
            uint32_t st = sb + STG0 + ((j + 1) & 1) * STG_SZ;
            int koff = (j + 1) * 32;
#pragma unroll
            for (int w = 0; w < 8; w++) {
                int ci = tid + w * 256;
                int region = ci >> 9, idx = ci & 511;
                int row = idx >> 2, ch = idx & 3;
                const __nv_bfloat16* src;
                if (region < 2) src = aptrs[region * 128 + row] + koff + ch * 8;
                else            src = ((region == 2) ? Bh : Bl) + (size_t)(bcol + row) * 512 + koff + ch * 8;
                cp16(st + region * 10240 + row * 80 + ch * 16, src);
            }
            CP_COMMIT();
            CP_WAIT1();
        } else {
            CP_WAIT0();
        }
        __syncthreads();

        const __nv_bfloat16* st = (const __nv_bfloat16*)(sm_raw + STG0 + (j & 1) * STG_SZ);
        const __nv_bfloat16* As_h = st;
        const __nv_bfloat16* As_l = st + 5120;
        const __nv_bfloat16* Bs_h = st + 10240;
        const __nv_bfloat16* Bs_l = st + 15360;

#pragma unroll
        for (int kk = 0; kk < 2; kk++) {
            wmma::fragment<wmma::matrix_a, 16, 16, 16, __nv_bfloat16, wmma::row_major> fah[4], fal[4];
            wmma::fragment<wmma::matrix_b, 16, 16, 16, __nv_bfloat16, wmma::col_major> fbh[2], fbl[2];
#pragma unroll
            for (int mi = 0; mi < 4; mi++) {
                int r = wm * 64 + mi * 16;
                wmma::load_matrix_sync(fah[mi], As_h + r * 40 + kk * 16, 40);
                wmma::load_matrix_sync(fal[mi], As_l + r * 40 + kk * 16, 40);
            }
#pragma unroll
            for (int ni = 0; ni < 2; ni++) {
                int c = wn * 32 + ni * 16;
                wmma::load_matrix_sync(fbh[ni], Bs_h + c * 40 + kk * 16, 40);
                wmma::load_matrix_sync(fbl[ni], Bs_l + c * 40 + kk * 16, 40);
            }
#pragma unroll
            for (int mi = 0; mi < 4; mi++)
#pragma unroll
                for (int ni = 0; ni < 2; ni++) {
                    wmma::mma_sync(acc[mi][ni], fah[mi], fbh[ni], acc[mi][ni]);
                    wmma::mma_sync(acc[mi][ni], fah[mi], fbl[ni], acc[mi][ni]);
                    wmma::mma_sync(acc[mi][ni], fal[mi], fbh[ni], acc[mi][ni]);
                }
        }
        __syncthreads();
    }

    float* Cs = (float*)(sm_raw + STG0);
#pragma unroll
    for (int mi = 0; mi < 4; mi++)
#pragma unroll
        for (int ni = 0; ni < 2; ni++)
            wmma::store_matrix_sync(Cs + (wm * 64 + mi * 16) * CPITCH + wn * 32 + ni * 16,
                                    acc[mi][ni], CPITCH, wmma::mem_row_major);
    __syncthreads();

    int lane = tid & 31, wrow = tid >> 5;
    for (int rr = wrow; rr < 128; rr += 8) {
        int r = brow + rr;
        if (r >= M) continue;
        int col0 = lane * 4;
        float4 o = *(float4*)&Cs[rr * CPITCH + col0];
        int col = bcol + col0;
        if (bias) {
            o.x += bias[col];     o.y += bias[col + 1];
            o.z += bias[col + 2]; o.w += bias[col + 3];
        }
        if (outh) {
            size_t g = (size_t)r * N + col;
            float vv[4] = { o.x, o.y, o.z, o.w };
            uint2 hi, lo;
            split4(vv, hi, lo);
            *(uint2*)&outh[g] = hi;
            *(uint2*)&outl[g] = lo;
        } else {
            *(float4*)&Cout[(size_t)r * N + col] = o;
        }
    }
}

// ---------------- mx copy (SMEM-tiled transpose) ----------------
__global__ void mx_copy_kernel(const float* __restrict__ P1, float* __restrict__ out2)
{
    __shared__ float t[32][33];
    int b = blockIdx.z;
    int t0 = blockIdx.x * 32;
    int c0 = blockIdx.y * 32;
    int tx = threadIdx.x, ty = threadIdx.y;
    for (int i = ty; i < 32; i += 8)
        t[i][tx] = P1[(((size_t)b * NP) + OFF_MX + t0 + i) * 512 + c0 + tx];
    __syncthreads();
    for (int i = ty; i < 32; i += 8)
        out2[(((size_t)b * 512) + c0 + i) * 256 + t0 + tx] = t[tx][i];
}

// ---------------- layernorm -> bf16 hi/lo ----------------
__global__ void ln_kernel(const float* __restrict__ X, const float* __restrict__ g,
                          const float* __restrict__ be,
                          __nv_bfloat16* __restrict__ Yh, __nv_bfloat16* __restrict__ Yl)
{
    int row = blockIdx.x, tid = threadIdx.x;
    float4 v = ((const float4*)(X + (size_t)row * C_DIM))[tid];
    float s  = v.x + v.y + v.z + v.w;
    float s2 = v.x * v.x + v.y * v.y + v.z * v.z + v.w * v.w;
#pragma unroll
    for (int o = 16; o >= 1; o >>= 1) {
        s  += __shfl_xor_sync(0xffffffffu, s,  o);
        s2 += __shfl_xor_sync(0xffffffffu, s2, o);
    }
    __shared__ float ws[4], ws2[4];
    int wid = tid >> 5, lane = tid & 31;
    if (lane == 0) { ws[wid] = s; ws2[wid] = s2; }
    __syncthreads();
    float ts = ws[0] + ws[1] + ws[2] + ws[3], ts2 = ws2[0] + ws2[1] + ws2[2] + ws2[3];
    float mean = ts * (1.f / C_DIM);
    float var  = ts2 * (1.f / C_DIM) - mean * mean;
    float rstd = rsqrtf(var + LN_EPS);
    float4 gg = ((const float4*)g)[tid], bb = ((const float4*)be)[tid];
    float y[4] = { (v.x - mean) * rstd * gg.x + bb.x, (v.y - mean) * rstd * gg.y + bb.y,
                   (v.z - mean) * rstd * gg.z + bb.z, (v.w - mean) * rstd * gg.w + bb.w };
    size_t o = (size_t)row * C_DIM + tid * 4;
    uint2 hi, lo;
    split4(y, hi, lo);
    *(uint2*)&Yh[o] = hi;
    *(uint2*)&Yl[o] = lo;
}

// =====================================================================
// wmma flash attention: 64-q tile, 256 thr, fragment-resident O,
// S phase pure bf16 (Qh·Kh), PV phase bf16x3, 3 syncs/iter,
// exp2 softmax. SMEM = 82,176 B -> 2 blocks/SM.
// =====================================================================
#define QP 72
#define SP 68
#define ATT_SMEM (7 * 64 * QP * 2 + 64 * SP * 4 + 256)   // 64512 + 17408 + 256 = 82176

__global__ __launch_bounds__(256, 2) void attn_wmma_kernel(
    const __nv_bfloat16* __restrict__ Qh,
    const __nv_bfloat16* __restrict__ KVh, const __nv_bfloat16* __restrict__ KVl,
    __nv_bfloat16* __restrict__ Oh, __nv_bfloat16* __restrict__ Ol)
{
    extern __shared__ char smc[];
    __nv_bfloat16* sQh  = (__nv_bfloat16*)smc;
    __nv_bfloat16* sK_h[2] = { sQh + 64 * QP, sQh + 2 * 64 * QP };
    __nv_bfloat16* sVh  = sQh + 3 * 64 * QP;
    __nv_bfloat16* sVl  = sVh + 64 * QP;
    __nv_bfloat16* sPh  = sVl + 64 * QP;
    __nv_bfloat16* sPl  = sPh + 64 * QP;
    float* Ss = (float*)(sPl + 64 * QP);   // [64][68]
    float* alphaSm = Ss + 64 * SP;         // [64]

    int tid = threadIdx.x;
    int b = blockIdx.z, h = blockIdx.y, l0 = blockIdx.x * 64;
    int warp = tid >> 5;
    int wm = (warp & 1) * 32, wn = (warp >> 1) * 16;
    int ty = tid >> 4, tx = tid & 15;

    size_t kvbase = (size_t)b * NTOK * 1024 + h * 64;

    // rowmap init
    for (int i = tid; i < 64 * SP; i += 256) Ss[i] = (float)(i / SP);
    __syncthreads();
    wmma::fragment<wmma::accumulator, 16, 16, 16, float> of[2];
    int rowidx0[8];
    {
        wmma::load_matrix_sync(of[0], Ss + wm * SP + wn, SP, wmma::mem_row_major);
#pragma unroll
        for (int e = 0; e < 8; e++) rowidx0[e] = (int)of[0].x[e];
        wmma::fill_fragment(of[0], 0.f);
        wmma::fill_fragment(of[1], 0.f);
    }
    __syncthreads();

    // pre-loop: group {Q hi + K tile 0 (hi only)}
    {
#pragma unroll
        for (int w = 0; w < 2; w++) {
            int ci = tid + w * 256;              // 0..511
            int row = ci >> 3, ch = ci & 7;
            const __nv_bfloat16* src = Qh +
                (((size_t)b * L_DIM) + l0 + row) * 512 + h * 64 + ch * 8;
            cp16(smem_u32(sQh + row * QP + ch * 8), src);
        }
#pragma unroll
        for (int w = 0; w < 2; w++) {
            int ci = tid + w * 256;              // 0..511
            int row = ci >> 3, ch = ci & 7;
            const __nv_bfloat16* src = KVh + kvbase + (size_t)row * 1024 + ch * 8;
            cp16(smem_u32(sK_h[0] + row * QP + ch * 8), src);
        }
        CP_COMMIT();
    }

    float mrow[4] = { -1e30f, -1e30f, -1e30f, -1e30f };
    float lrow[4] = {};

    for (int kt = 0; kt < 36; kt++) {
        int kbase = kt * 64;
        int kb = kt & 1;
        CP_WAIT0();
        __syncthreads();

        // prefetch V(kt) hi/lo (group 1)
        {
#pragma unroll
            for (int w = 0; w < 4; w++) {
                int ci = tid + w * 256;
                int arr = ci >> 9, idx = ci & 511;
                int row = idx >> 3, ch = idx & 7;
                int kg = kbase + row;
                const __nv_bfloat16* src = (arr ? KVl : KVh) + kvbase
                    + (size_t)(kg < NTOK ? kg : 0) * 1024 + 512 + ch * 8;
                cp16z(smem_u32((arr ? sVl : sVh) + row * QP + ch * 8),
                      src, (kg < NTOK) ? 16 : 0);
            }
            CP_COMMIT();
        }
        // prefetch K(kt+1) hi only (group 2)
        if (kt + 1 < 36) {
            int nkb = (kt + 1) & 1;
#pragma unroll
            for (int w = 0; w < 2; w++) {
                int ci = tid + w * 256;
                int row = ci >> 3, ch = ci & 7;
                int kg = kbase + 64 + row;
                const __nv_bfloat16* src = KVh + kvbase
                    + (size_t)(kg < NTOK ? kg : 0) * 1024 + ch * 8;
                cp16z(smem_u32(sK_h[nkb] + row * QP + ch * 8),
                      src, (kg < NTOK) ? 16 : 0);
            }
            CP_COMMIT();
        }

        // ---- S = Qh Kh  [pure bf16] ----
        {
            wmma::fragment<wmma::accumulator, 16, 16, 16, float> sf[2];
            wmma::fill_fragment(sf[0], 0.f);
            wmma::fill_fragment(sf[1], 0.f);
#pragma unroll
            for (int k = 0; k < 4; k++) {
                wmma::fragment<wmma::matrix_b, 16, 16, 16, __nv_bfloat16, wmma::col_major> fbh;
                wmma::load_matrix_sync(fbh, sK_h[kb] + wn * QP + k * 16, QP);
#pragma unroll
                for (int mi = 0; mi < 2; mi++) {
                    wmma::fragment<wmma::matrix_a, 16, 16, 16, __nv_bfloat16, wmma::row_major> fah;
                    wmma::load_matrix_sync(fah, sQh + (wm + mi * 16) * QP + k * 16, QP);
                    wmma::mma_sync(sf[mi], fah, fbh, sf[mi]);
                }
            }
            wmma::store_matrix_sync(Ss + wm * SP + wn, sf[0], SP, wmma::mem_row_major);
            wmma::store_matrix_sync(Ss + (wm + 16) * SP + wn, sf[1], SP, wmma::mem_row_major);
        }
        __syncthreads();

        // ---- scalar online softmax (exp2 domain) ----
        float s[4][4], tmax[4];
#pragma unroll
        for (int i = 0; i < 4; i++) {
            float4 sv = *(const float4*)&Ss[(ty * 4 + i) * SP + tx * 4];
            s[i][0] = sv.x; s[i][1] = sv.y; s[i][2] = sv.z; s[i][3] = sv.w;
            tmax[i] = -1e30f;
#pragma unroll
            for (int j = 0; j < 4; j++) {
                int cg = kbase + tx * 4 + j;
                if (cg >= NTOK) s[i][j] = -1e30f;
                tmax[i] = fmaxf(tmax[i], s[i][j]);
            }
        }
#pragma unroll
        for (int i = 0; i < 4; i++)
#pragma unroll
            for (int o = 8; o >= 1; o >>= 1)
                tmax[i] = fmaxf(tmax[i], __shfl_xor_sync(0xffffffffu, tmax[i], o));
        float alpha[4], rsum[4];
#pragma unroll
        for (int i = 0; i < 4; i++) {
            float mnew = fmaxf(mrow[i], tmax[i]);
            alpha[i] = exp2f(mrow[i] - mnew);
            mrow[i] = mnew;
            float rs = 0.f;
#pragma unroll
            for (int j = 0; j < 4; j++) {
                float p = (s[i][j] > -1e29f) ? exp2f(s[i][j] - mnew) : 0.f;
                s[i][j] = p; rs += p;
            }
            rsum[i] = rs;
            lrow[i] = lrow[i] * alpha[i];
        }
#pragma unroll
        for (int i = 0; i < 4; i++) {
#pragma unroll
            for (int o = 8; o >= 1; o >>= 1)
                rsum[i] += __shfl_xor_sync(0xffffffffu, rsum[i], o);
            lrow[i] += rsum[i];
        }
        if (tx == 0) {
#pragma unroll
            for (int i = 0; i < 4; i++) alphaSm[ty * 4 + i] = alpha[i];
        }
#pragma unroll
        for (int i = 0; i < 4; i++) {
            int r = ty * 4 + i;
            uint2 hi, lo;
            split4(s[i], hi, lo);
            *(uint2*)&sPh[r * QP + tx * 4] = hi;
            *(uint2*)&sPl[r * QP + tx * 4] = lo;
        }
        if (kt + 1 < 36) { CP_WAIT1(); } else { CP_WAIT0(); }
        __syncthreads();

        // ---- rescale O, PV accumulate in place (bf16x3) ----
#pragma unroll
        for (int e = 0; e < 8; e++) {
            of[0].x[e] *= alphaSm[rowidx0[e]];
            of[1].x[e] *= alphaSm[rowidx0[e] + 16];
        }
        {
#pragma unroll
            for (int k = 0; k < 4; k++) {
                wmma::fragment<wmma::matrix_b, 16, 16, 16, __nv_bfloat16, wmma::row_major> fbh, fbl;
                wmma::load_matrix_sync(fbh, sVh + k * 16 * QP + wn, QP);
                wmma::load_matrix_sync(fbl, sVl + k * 16 * QP + wn, QP);
#pragma unroll
                for (int mi = 0; mi < 2; mi++) {
                    wmma::fragment<wmma::matrix_a, 16, 16, 16, __nv_bfloat16, wmma::row_major> fah, fal;
                    wmma::load_matrix_sync(fah, sPh + (wm + mi * 16) * QP + k * 16, QP);
                    wmma::load_matrix_sync(fal, sPl + (wm + mi * 16) * QP + k * 16, QP);
                    wmma::mma_sync(of[mi], fah, fbh, of[mi]);
                    wmma::mma_sync(of[mi], fah, fbl, of[mi]);
                    wmma::mma_sync(of[mi], fal, fbh, of[mi]);
                }
            }
        }
        // next iteration's top sync orders sV/sP reads before next V prefetch
    }

    // ---- epilogue ----
    __syncthreads();
#pragma unroll
    for (int mi = 0; mi < 2; mi++)
        wmma::store_matrix_sync(Ss + (wm + mi * 16) * SP + wn, of[mi], SP, wmma::mem_row_major);
    __syncthreads();
#pragma unroll
    for (int i = 0; i < 4; i++) {
        float inv = 1.f / lrow[i];
        int r = ty * 4 + i;
        size_t o = (((size_t)b * L_DIM) + l0 + r) * C_DIM + h * HD + tx * 4;
        float4 tv = *(const float4*)&Ss[r * SP + tx * 4];
        float vv[4] = { tv.x * inv, tv.y * inv, tv.z * inv, tv.w * inv };
        uint2 hi, lo;
        split4(vv, hi, lo);
        *(uint2*)&Oh[o] = hi;
        *(uint2*)&Ol[o] = lo;
    }
}

// ---------------- launch ----------------
extern "C" void kernel_launch(void* const* d_in, const int* in_sizes, int n_in,
                              void* d_out, int out_size)
{
    const float* x    = (const float*)d_in[0];
    const float* m    = (const float*)d_in[1];
    const float* wsrc5[5] = { (const float*)d_in[2], (const float*)d_in[4], (const float*)d_in[6],
                              (const float*)d_in[8], (const float*)d_in[10] };
    const float* bsrc5[5] = { (const float*)d_in[3], (const float*)d_in[5], (const float*)d_in[7],
                              (const float*)d_in[9], (const float*)d_in[11] };
    const float* ln_g = (const float*)d_in[12];
    const float* ln_b = (const float*)d_in[13];
    const float* Wq   = (const float*)d_in[14];
    const float* Wkv  = (const float*)d_in[15];
    const float* Wp   = (const float*)d_in[16];
    const float* bp   = (const float*)d_in[17];
    float* out  = (float*)d_out;
    float* out2 = (float*)d_out + (size_t)B_DIM * L_DIM * C_DIM;

    float *P0, *P1;
    __nv_bfloat16 *P0h, *P0l, *P2h, *P2l, *mh, *ml, *Qh, *KVh, *KVl, *Oh, *Ol, *Wth, *Wtl;
    cudaGetSymbolAddress((void**)&P0,  g_P0);
    cudaGetSymbolAddress((void**)&P1,  g_P1);
    cudaGetSymbolAddress((void**)&P0h, g_P0h);
    cudaGetSymbolAddress((void**)&P0l, g_P0l);
    cudaGetSymbolAddress((void**)&P2h, g_P2h);
    cudaGetSymbolAddress((void**)&P2l, g_P2l);
    cudaGetSymbolAddress((void**)&mh,  g_mh);
    cudaGetSymbolAddress((void**)&ml,  g_ml);
    cudaGetSymbolAddress((void**)&Qh,  g_Qh);
    cudaGetSymbolAddress((void**)&KVh, g_KVh);
    cudaGetSymbolAddress((void**)&KVl, g_KVl);
    cudaGetSymbolAddress((void**)&Oh,  g_Oh);
    cudaGetSymbolAddress((void**)&Ol,  g_Ol);
    cudaGetSymbolAddress((void**)&Wth, g_Wth);
    cudaGetSymbolAddress((void**)&Wtl, g_Wtl);

    cudaFuncSetAttribute(cgemm_kernel,     cudaFuncAttributeMaxDynamicSharedMemorySize, TG_SMEM);
    cudaFuncSetAttribute(tgemm_kernel,     cudaFuncAttributeMaxDynamicSharedMemorySize, TG_SMEM);
    cudaFuncSetAttribute(attn_wmma_kernel, cudaFuncAttributeMaxDynamicSharedMemorySize, ATT_SMEM);

    wsplit8_kernel<<<dim3(32, 16, 8), dim3(32, 8)>>>(
        wsrc5[0], wsrc5[1], wsrc5[2], wsrc5[3], wsrc5[4], Wq, Wp, Wkv, Wth, Wtl);
    mcvt_kernel<<<(B_DIM * L_DIM * C_DIM / 4 + 255) / 256, 256>>>(m, mh, ml);

    pool_all_kernel<<<dim3(NP, B_DIM), 512>>>(x, P0, P0h, P0l);

    cgemm_kernel<<<dim3(4, 143), 256, TG_SMEM>>>(
        P0h, P0l, mh, ml, Wth, Wtl,
        bsrc5[0], bsrc5[1], bsrc5[2], bsrc5[3], bsrc5[4],
        P0, P1, Qh);

    mx_copy_kernel<<<dim3(8, 16, B_DIM), dim3(32, 8)>>>(P1, out2);
    ln_kernel<<<B_DIM * NP, 128>>>(P1, ln_g, ln_b, P2h, P2l);

    tgemm_kernel<<<dim3(8, (B_DIM * NTOK + 127) / 128), 256, TG_SMEM>>>(
        P2h, P2l, mh, ml, Wth + 7 * (size_t)WSLOT, Wtl + 7 * (size_t)WSLOT,
        nullptr, nullptr, KVh, KVl, B_DIM * NTOK, 1024, 2);

    attn_wmma_kernel<<<dim3(L_DIM / 64, NH, B_DIM), 256, ATT_SMEM>>>(Qh, KVh, KVl, Oh, Ol);

    tgemm_kernel<<<dim3(4, 64), 256, TG_SMEM>>>(
        Oh, Ol, nullptr, nullptr, Wth + 6 * (size_t)WSLOT, Wtl + 6 * (size_t)WSLOT,
        bp, out, nullptr, nullptr, B_DIM * L_DIM, 512, 0);
}

// round 16
// speedup vs baseline: 1.4430x; 1.0990x over previous
#include <cuda_runtime.h>
#include <cuda_bf16.h>
#include <mma.h>
#include <math.h>
#include <cstdint>

using namespace nvcuda;

#define B_DIM 8
#define L_DIM 1024
#define C_DIM 512
#define NP    1243
#define NTOK  2267
#define NH    8
#define HD    64
#define LN_EPS 1e-5f
#define OFF_MX 987
#define QSCALE 0.18033688f   // 0.125 * log2(e)

// ---------------- scratch ----------------
__device__ __align__(128) float g_P0[B_DIM * NP * C_DIM];
__device__ __align__(128) float g_P1[B_DIM * NP * C_DIM];
__device__ __align__(128) __nv_bfloat16 g_P0h[B_DIM * NP * C_DIM],    g_P0l[B_DIM * NP * C_DIM];
__device__ __align__(128) __nv_bfloat16 g_P2h[B_DIM * NP * C_DIM],    g_P2l[B_DIM * NP * C_DIM];
__device__ __align__(128) __nv_bfloat16 g_mh [B_DIM * L_DIM * C_DIM], g_ml [B_DIM * L_DIM * C_DIM];
__device__ __align__(128) __nv_bfloat16 g_Qh [B_DIM * L_DIM * C_DIM];
__device__ __align__(128) __nv_bfloat16 g_KVh[B_DIM * NTOK * 2 * C_DIM], g_KVl[B_DIM * NTOK * 2 * C_DIM];
__device__ __align__(128) __nv_bfloat16 g_Oh [B_DIM * L_DIM * C_DIM], g_Ol [B_DIM * L_DIM * C_DIM];
#define WSLOT (512 * 512)
__device__ __align__(128) __nv_bfloat16 g_Wth[7 * WSLOT + 512 * 1024], g_Wtl[7 * WSLOT + 512 * 1024];

// ---------------- helpers ----------------
__device__ __forceinline__ uint32_t smem_u32(const void* p) {
    uint32_t a;
    asm("{ .reg .u64 t; cvta.to.shared.u64 t, %1; cvt.u32.u64 %0, t; }" : "=r"(a) : "l"(p));
    return a;
}
__device__ __forceinline__ void cp16(uint32_t dst, const void* src) {
    asm volatile("cp.async.cg.shared.global [%0], [%1], 16;" :: "r"(dst), "l"(src) : "memory");
}
__device__ __forceinline__ void cp16z(uint32_t dst, const void* src, int sz) {
    asm volatile("cp.async.cg.shared.global [%0], [%1], 16, %2;" :: "r"(dst), "l"(src), "r"(sz) : "memory");
}
#define CP_COMMIT() asm volatile("cp.async.commit_group;" ::: "memory")
#define CP_WAIT1()  asm volatile("cp.async.wait_group 1;" ::: "memory")
#define CP_WAIT0()  asm volatile("cp.async.wait_group 0;" ::: "memory")

__device__ __forceinline__ uint32_t pk2(float a, float b) {
    __nv_bfloat162 t(__float2bfloat16(a), __float2bfloat16(b));
    return *(uint32_t*)&t;
}
__device__ __forceinline__ void split4(const float* v, uint2& hi, uint2& lo) {
    __nv_bfloat16 h[4]; float r[4];
#pragma unroll
    for (int u = 0; u < 4; u++) { h[u] = __float2bfloat16(v[u]); r[u] = v[u] - __bfloat162float(h[u]); }
    __nv_bfloat162 h01(h[0], h[1]), h23(h[2], h[3]);
    hi.x = *(uint32_t*)&h01; hi.y = *(uint32_t*)&h23;
    lo.x = pk2(r[0], r[1]);  lo.y = pk2(r[2], r[3]);
}

// ---------------- combined weight transpose + split ----------------
__global__ void wsplit8_kernel(const float* W0, const float* W1, const float* W2, const float* W3,
                               const float* W4, const float* W5, const float* W6, const float* W7,
                               __nv_bfloat16* __restrict__ Th, __nv_bfloat16* __restrict__ Tl)
{
    __shared__ float t[32][33];
    int slot = blockIdx.z;
    const float* W = (slot == 0) ? W0 : (slot == 1) ? W1 : (slot == 2) ? W2 : (slot == 3) ? W3 :
                     (slot == 4) ? W4 : (slot == 5) ? W5 : (slot == 6) ? W6 : W7;
    int N = (slot == 7) ? 1024 : 512;
    int n0 = blockIdx.x * 32, k0 = blockIdx.y * 32;
    if (n0 >= N) return;
    __nv_bfloat16* th = Th + (size_t)slot * WSLOT;
    __nv_bfloat16* tl = Tl + (size_t)slot * WSLOT;
    int tx = threadIdx.x, ty = threadIdx.y;
    for (int i = ty; i < 32; i += 8) t[i][tx] = W[(size_t)(k0 + i) * N + n0 + tx];
    __syncthreads();
    for (int i = ty; i < 32; i += 8) {
        float v = t[tx][i];
        __nv_bfloat16 h = __float2bfloat16(v);
        size_t o = (size_t)(n0 + i) * 512 + k0 + tx;
        th[o] = h; tl[o] = __float2bfloat16(v - __bfloat162float(h));
    }
}

__global__ void mcvt_kernel(const float* __restrict__ m, __nv_bfloat16* __restrict__ mh,
                            __nv_bfloat16* __restrict__ ml)
{
    int i = (blockIdx.x * blockDim.x + threadIdx.x) * 4;
    if (i >= B_DIM * L_DIM * C_DIM) return;
    float4 v4 = *(const float4*)&m[i];
    float v[4] = { v4.x, v4.y, v4.z, v4.w };
    uint2 hi, lo;
    split4(v, hi, lo);
    *(uint2*)&mh[i] = hi;
    *(uint2*)&ml[i] = lo;
}

// ---------------- pooling (avg + max merged) ----------------
__global__ void pool_all_kernel(const float* __restrict__ x, float* __restrict__ P0,
                                __nv_bfloat16* __restrict__ Ph, __nv_bfloat16* __restrict__ Pl)
{
    int tok = blockIdx.x, b = blockIdx.y, c = threadIdx.x;
    float v;
    if (tok < 987) {
        int t = tok, n;
        if      (t < 441) { n = 21; }
        else if (t < 697) { n = 16; t -= 441; }
        else if (t < 866) { n = 13; t -= 697; }
        else              { n = 11; t -= 866; }
        int p = t / n, q = t - p * n;
        int hs = (p * 64) / n, he = ((p + 1) * 64 + n - 1) / n;
        int ws = (q * 64) / n, we = ((q + 1) * 64 + n - 1) / n;
        float s = 0.f;
        for (int h = hs; h < he; h++) {
            const float* xr = x + (((size_t)b * 4096) + (size_t)h * 64) * C_DIM + c;
            for (int w = ws; w < we; w++) s += xr[(size_t)w * C_DIM];
        }
        v = s / (float)((he - hs) * (we - ws));
    } else {
        int t = tok - 987;
        int p = t >> 4, q = t & 15;
        float mx = -1e30f;
        for (int h = p * 4; h < p * 4 + 4; h++) {
            const float* xr = x + (((size_t)b * 4096) + (size_t)h * 64) * C_DIM + c;
            for (int w = q * 4; w < q * 4 + 4; w++) mx = fmaxf(mx, xr[(size_t)w * C_DIM]);
        }
        v = mx;
    }
    size_t o = ((size_t)b * NP + tok) * C_DIM + c;
    P0[o] = v;
    __nv_bfloat16 h16 = __float2bfloat16(v);
    Ph[o] = h16; Pl[o] = __float2bfloat16(v - __bfloat162float(h16));
}

// =====================================================================
// GEMM mainloop (bf16x3 / bf16x2, 128x128 tile, K=512); 2 blocks/SM
// =====================================================================
#define STG0    4096
#define STG_SZ  40960
#define TG_SMEM (4096 + 2 * 40960)
#define CPITCH  136

// cgemm: conv-res (0..4, x3) + Wq (5, x2, pre-scaled, hi-only out).
__global__ __launch_bounds__(256, 2) void cgemm_kernel(
    const __nv_bfloat16* __restrict__ P0h, const __nv_bfloat16* __restrict__ P0l,
    const __nv_bfloat16* __restrict__ mh,  const __nv_bfloat16* __restrict__ ml,
    const __nv_bfloat16* __restrict__ Wth, const __nv_bfloat16* __restrict__ Wtl,
    const float* bp0, const float* bp1, const float* bp2, const float* bp3, const float* bp4,
    const float* __restrict__ P0, float* __restrict__ P1,
    __nv_bfloat16* __restrict__ Qh)
{
    extern __shared__ char sm_raw[];
    const __nv_bfloat16** aptrs = (const __nv_bfloat16**)(sm_raw + 16);
    uint32_t sb = smem_u32(sm_raw);

    int tid = threadIdx.x;
    int ti = blockIdx.y;
    int branch, tstart;
    if      (ti < 28) { branch = 0; tstart = 0;  }
    else if (ti < 44) { branch = 1; tstart = 28; }
    else if (ti < 55) { branch = 2; tstart = 44; }
    else if (ti < 63) { branch = 3; tstart = 55; }
    else if (ti < 79) { branch = 4; tstart = 63; }
    else              { branch = 5; tstart = 79; }
    const int npx_t[6]  = { 441, 256, 169, 121, 256, 0 };
    const int toff_t[6] = { 0, 441, 697, 866, 987, 0 };
    int npx = npx_t[branch], toffc = toff_t[branch];
    int M = (branch < 5) ? 8 * npx : 8192;
    int brow = (ti - tstart) * 128;
    int bcol = blockIdx.x * 128;
    bool useAl = (branch < 5);
    const float* bias = (branch == 0) ? bp0 : (branch == 1) ? bp1 : (branch == 2) ? bp2 :
                        (branch == 3) ? bp3 : (branch == 4) ? bp4 : nullptr;
    const __nv_bfloat16* Bh = Wth + (size_t)branch * WSLOT;
    const __nv_bfloat16* Bl = Wtl + (size_t)branch * WSLOT;

    if (tid < 128) {
        int arow = brow + tid;
        if (arow >= M) arow = M - 1;
        const __nv_bfloat16 *ph, *pl;
        if (branch < 5) {
            int b = arow / npx, t = arow - (arow / npx) * npx;
            size_t o = ((size_t)b * NP + toffc + t) * 512;
            ph = P0h + o; pl = P0l + o;
        } else {
            size_t o = (size_t)arow * 512;
            ph = mh + o; pl = ml + o;
        }
        aptrs[tid] = ph; aptrs[128 + tid] = pl;
    }
    __syncthreads();

    int wid = tid >> 5;
    int wm = wid & 1, wn = wid >> 1;

    wmma::fragment<wmma::accumulator, 16, 16, 16, float> acc[4][2];
#pragma unroll
    for (int mi = 0; mi < 4; mi++)
#pragma unroll
        for (int ni = 0; ni < 2; ni++)
            wmma::fill_fragment(acc[mi][ni], 0.f);

    {
        uint32_t st = sb + STG0;
#pragma unroll
        for (int w = 0; w < 8; w++) {
            int ci = tid + w * 256;
            int region = ci >> 9, idx = ci & 511;
            int row = idx >> 2, ch = idx & 3;
            const __nv_bfloat16* src;
            if (region < 2) src = aptrs[region * 128 + row] + ch * 8;
            else            src = ((region == 2) ? Bh : Bl) + (size_t)(bcol + row) * 512 + ch * 8;
            cp16(st + region * 10240 + row * 80 + ch * 16, src);
        }
        CP_COMMIT();
    }

    for (int j = 0; j < 16; j++) {
        if (j + 1 < 16) {
            uint32_t st = sb + STG0 + ((j + 1) & 1) * STG_SZ;
            int koff = (j + 1) * 32;
#pragma unroll
            for (int w = 0; w < 8; w++) {
                int ci = tid + w * 256;
                int region = ci >> 9, idx = ci & 511;
                int row = idx >> 2, ch = idx & 3;
                const __nv_bfloat16* src;
                if (region < 2) src = aptrs[region * 128 + row] + koff + ch * 8;
                else            src = ((region == 2) ? Bh : Bl) + (size_t)(bcol + row) * 512 + koff + ch * 8;
                cp16(st + region * 10240 + row * 80 + ch * 16, src);
            }
            CP_COMMIT();
            CP_WAIT1();
        } else {
            CP_WAIT0();
        }
        __syncthreads();

        const __nv_bfloat16* st = (const __nv_bfloat16*)(sm_raw + STG0 + (j & 1) * STG_SZ);
        const __nv_bfloat16* As_h = st;
        const __nv_bfloat16* As_l = st + 5120;
        const __nv_bfloat16* Bs_h = st + 10240;
        const __nv_bfloat16* Bs_l = st + 15360;

#pragma unroll
        for (int kk = 0; kk < 2; kk++) {
            wmma::fragment<wmma::matrix_a, 16, 16, 16, __nv_bfloat16, wmma::row_major> fah[4], fal[4];
            wmma::fragment<wmma::matrix_b, 16, 16, 16, __nv_bfloat16, wmma::col_major> fbh[2], fbl[2];
#pragma unroll
            for (int mi = 0; mi < 4; mi++) {
                int r = wm * 64 + mi * 16;
                wmma::load_matrix_sync(fah[mi], As_h + r * 40 + kk * 16, 40);
                if (useAl) wmma::load_matrix_sync(fal[mi], As_l + r * 40 + kk * 16, 40);
            }
#pragma unroll
            for (int ni = 0; ni < 2; ni++) {
                int c = wn * 32 + ni * 16;
                wmma::load_matrix_sync(fbh[ni], Bs_h + c * 40 + kk * 16, 40);
                wmma::load_matrix_sync(fbl[ni], Bs_l + c * 40 + kk * 16, 40);
            }
#pragma unroll
            for (int mi = 0; mi < 4; mi++)
#pragma unroll
                for (int ni = 0; ni < 2; ni++) {
                    wmma::mma_sync(acc[mi][ni], fah[mi], fbh[ni], acc[mi][ni]);
                    wmma::mma_sync(acc[mi][ni], fah[mi], fbl[ni], acc[mi][ni]);
                    if (useAl) wmma::mma_sync(acc[mi][ni], fal[mi], fbh[ni], acc[mi][ni]);
                }
        }
        __syncthreads();
    }

    float* Cs = (float*)(sm_raw + STG0);
#pragma unroll
    for (int mi = 0; mi < 4; mi++)
#pragma unroll
        for (int ni = 0; ni < 2; ni++)
            wmma::store_matrix_sync(Cs + (wm * 64 + mi * 16) * CPITCH + wn * 32 + ni * 16,
                                    acc[mi][ni], CPITCH, wmma::mem_row_major);
    __syncthreads();

    int lane = tid & 31, wrow = tid >> 5;
    for (int rr = wrow; rr < 128; rr += 8) {
        int r = brow + rr;
        if (r >= M) continue;
        int col0 = lane * 4;
        float4 o = *(float4*)&Cs[rr * CPITCH + col0];
        int col = bcol + col0;
        if (branch < 5) {
            o.x += bias[col];     o.y += bias[col + 1];
            o.z += bias[col + 2]; o.w += bias[col + 3];
            int b = r / npx, t = r - (r / npx) * npx;
            size_t g = ((size_t)b * NP + toffc + t) * 512;
            float4 rv = *(const float4*)&P0[g + col];
            o.x += rv.x; o.y += rv.y; o.z += rv.z; o.w += rv.w;
            *(float4*)&P1[g + col] = o;
        } else {
            size_t g = (size_t)r * 512 + col;
            __nv_bfloat162 h01(__float2bfloat16(o.x * QSCALE), __float2bfloat16(o.y * QSCALE));
            __nv_bfloat162 h23(__float2bfloat16(o.z * QSCALE), __float2bfloat16(o.w * QSCALE));
            uint2 hi;
            hi.x = *(uint32_t*)&h01; hi.y = *(uint32_t*)&h23;
            *(uint2*)&Qh[g] = hi;
        }
    }
}

// tgemm: generic (Wkv mode 2 — K-columns x2; Wp mode 0 — x3)
__global__ __launch_bounds__(256, 2) void tgemm_kernel(
    const __nv_bfloat16* __restrict__ Ah, const __nv_bfloat16* __restrict__ Al,
    const __nv_bfloat16* __restrict__ A2h, const __nv_bfloat16* __restrict__ A2l,
    const __nv_bfloat16* __restrict__ Bh, const __nv_bfloat16* __restrict__ Bl,
    const float* __restrict__ bias,
    float* __restrict__ Cout,
    __nv_bfloat16* __restrict__ outh, __nv_bfloat16* __restrict__ outl,
    int M, int N, int mode)
{
    extern __shared__ char sm_raw[];
    const __nv_bfloat16** aptrs = (const __nv_bfloat16**)(sm_raw + 16);
    uint32_t sb = smem_u32(sm_raw);

    int tid = threadIdx.x;
    int brow = blockIdx.y * 128, bcol = blockIdx.x * 128;
    bool useAl = !(mode == 2 && bcol < 512);   // K-columns of Wkv: drop Al term

    if (tid < 128) {
        int arow = brow + tid;
        if (arow >= M) arow = M - 1;
        const __nv_bfloat16 *ph, *pl;
        if (mode == 0) {
            size_t o = (size_t)arow * 512; ph = Ah + o; pl = Al + o;
        } else {
            int b = arow / NTOK, t = arow - (arow / NTOK) * NTOK;
            if (t < NP) { size_t o = ((size_t)b * NP + t) * 512; ph = Ah + o; pl = Al + o; }
            else        { size_t o = ((size_t)b * L_DIM + (t - NP)) * 512; ph = A2h + o; pl = A2l + o; }
        }
        aptrs[tid] = ph; aptrs[128 + tid] = pl;
    }
    __syncthreads();

    int wid = tid >> 5;
    int wm = wid & 1, wn = wid >> 1;

    wmma::fragment<wmma::accumulator, 16, 16, 16, float> acc[4][2];
#pragma unroll
    for (int mi = 0; mi < 4; mi++)
#pragma unroll
        for (int ni = 0; ni < 2; ni++)
            wmma::fill_fragment(acc[mi][ni], 0.f);

    {
        uint32_t st = sb + STG0;
#pragma unroll
        for (int w = 0; w < 8; w++) {
            int ci = tid + w * 256;
            int region = ci >> 9, idx = ci & 511;
            int row = idx >> 2, ch = idx & 3;
            const __nv_bfloat16* src;
            if (region < 2) src = aptrs[region * 128 + row] + ch * 8;
            else            src = ((region == 2) ? Bh : Bl) + (size_t)(bcol + row) * 512 + ch * 8;
            cp16(st + region * 10240 + row * 80 + ch * 16, src);
        }
        CP_COMMIT();
    }

    for (int j = 0; j < 16; j++) {
        if (j + 1 < 16) {
            uint32_t st = sb + STG0 + ((j + 1) & 1) * STG_SZ;
            int koff = (j + 1) * 32;
#pragma unroll
            for (int w = 0; w < 8; w++) {
                int ci = tid + w * 256;
                int region = ci >> 9, idx = ci & 511;
                int row = idx >> 2, ch = idx & 3;
                const __nv_bfloat16* src;
                if (region < 2) src = aptrs[region * 128 + row] + koff + ch * 8;
                else            src = ((region == 2) ? Bh : Bl) + (size_t)(bcol + row) * 512 + koff + ch * 8;
                cp16(st + region * 10240 + row * 80 + ch * 16, src);
            }
            CP_COMMIT();
            CP_WAIT1();
        } else {
            CP_WAIT0();
        }
        __syncthreads();

        const __nv_bfloat16* st = (const __nv_bfloat16*)(sm_raw + STG0 + (j & 1) * STG_SZ);
        const __nv_bfloat16* As_h = st;
        const __nv_bfloat16* As_l = st + 5120;
        const __nv_bfloat16* Bs_h = st + 10240;
        const __nv_bfloat16* Bs_l = st + 15360;

#pragma unroll
        for (int kk = 0; kk < 2; kk++) {
            wmma::fragment<wmma::matrix_a, 16, 16, 16, __nv_bfloat16, wmma::row_major> fah[4], fal[4];
            wmma::fragment<wmma::matrix_b, 16, 16, 16, __nv_bfloat16, wmma::col_major> fbh[2], fbl[2];
#pragma unroll
            for (int mi = 0; mi < 4; mi++) {
                int r = wm * 64 + mi * 16;
                wmma::load_matrix_sync(fah[mi], As_h + r * 40 + kk * 16, 40);
                if (useAl) wmma::load_matrix_sync(fal[mi], As_l + r * 40 + kk * 16, 40);
            }
#pragma unroll
            for (int ni = 0; ni < 2; ni++) {
                int c = wn * 32 + ni * 16;
                wmma::load_matrix_sync(fbh[ni], Bs_h + c * 40 + kk * 16, 40);
                wmma::load_matrix_sync(fbl[ni], Bs_l + c * 40 + kk * 16, 40);
            }
#pragma unroll
            for (int mi = 0; mi < 4; mi++)
#pragma unroll
                for (int ni = 0; ni < 2; ni++) {
                    wmma::mma_sync(acc[mi][ni], fah[mi], fbh[ni], acc[mi][ni]);
                    wmma::mma_sync(acc[mi][ni], fah[mi], fbl[ni], acc[mi][ni]);
                    if (useAl) wmma::mma_sync(acc[mi][ni], fal[mi], fbh[ni], acc[mi][ni]);
                }
        }
        __syncthreads();
    }

    float* Cs = (float*)(sm_raw + STG0);
#pragma unroll
    for (int mi = 0; mi < 4; mi++)
#pragma unroll
        for (int ni = 0; ni < 2; ni++)
            wmma::store_matrix_sync(Cs + (wm * 64 + mi * 16) * CPITCH + wn * 32 + ni * 16,
                                    acc[mi][ni], CPITCH, wmma::mem_row_major);
    __syncthreads();

    int lane = tid & 31, wrow = tid >> 5;
    for (int rr = wrow; rr < 128; rr += 8) {
        int r = brow + rr;
        if (r >= M) continue;
        int col0 = lane * 4;
        float4 o = *(float4*)&Cs[rr * CPITCH + col0];
        int col = bcol + col0;
        if (bias) {
            o.x += bias[col];     o.y += bias[col + 1];
            o.z += bias[col + 2]; o.w += bias[col + 3];
        }
        if (outh) {
            size_t g = (size_t)r * N + col;
            float vv[4] = { o.x, o.y, o.z, o.w };
            uint2 hi, lo;
            split4(vv, hi, lo);
            *(uint2*)&outh[g] = hi;
            *(uint2*)&outl[g] = lo;
        } else {
            *(float4*)&Cout[(size_t)r * N + col] = o;
        }
    }
}

// ---------------- mx copy (SMEM-tiled transpose) ----------------
__global__ void mx_copy_kernel(const float* __restrict__ P1, float* __restrict__ out2)
{
    __shared__ float t[32][33];
    int b = blockIdx.z;
    int t0 = blockIdx.x * 32;
    int c0 = blockIdx.y * 32;
    int tx = threadIdx.x, ty = threadIdx.y;
    for (int i = ty; i < 32; i += 8)
        t[i][tx] = P1[(((size_t)b * NP) + OFF_MX + t0 + i) * 512 + c0 + tx];
    __syncthreads();
    for (int i = ty; i < 32; i += 8)
        out2[(((size_t)b * 512) + c0 + i) * 256 + t0 + tx] = t[tx][i];
}

// ---------------- layernorm -> bf16 hi/lo ----------------
__global__ void ln_kernel(const float* __restrict__ X, const float* __restrict__ g,
                          const float* __restrict__ be,
                          __nv_bfloat16* __restrict__ Yh, __nv_bfloat16* __restrict__ Yl)
{
    int row = blockIdx.x, tid = threadIdx.x;
    float4 v = ((const float4*)(X + (size_t)row * C_DIM))[tid];
    float s  = v.x + v.y + v.z + v.w;
    float s2 = v.x * v.x + v.y * v.y + v.z * v.z + v.w * v.w;
#pragma unroll
    for (int o = 16; o >= 1; o >>= 1) {
        s  += __shfl_xor_sync(0xffffffffu, s,  o);
        s2 += __shfl_xor_sync(0xffffffffu, s2, o);
    }
    __shared__ float ws[4], ws2[4];
    int wid = tid >> 5, lane = tid & 31;
    if (lane == 0) { ws[wid] = s; ws2[wid] = s2; }
    __syncthreads();
    float ts = ws[0] + ws[1] + ws[2] + ws[3], ts2 = ws2[0] + ws2[1] + ws2[2] + ws2[3];
    float mean = ts * (1.f / C_DIM);
    float var  = ts2 * (1.f / C_DIM) - mean * mean;
    float rstd = rsqrtf(var + LN_EPS);
    float4 gg = ((const float4*)g)[tid], bb = ((const float4*)be)[tid];
    float y[4] = { (v.x - mean) * rstd * gg.x + bb.x, (v.y - mean) * rstd * gg.y + bb.y,
                   (v.z - mean) * rstd * gg.z + bb.z, (v.w - mean) * rstd * gg.w + bb.w };
    size_t o = (size_t)row * C_DIM + tid * 4;
    uint2 hi, lo;
    split4(y, hi, lo);
    *(uint2*)&Yh[o] = hi;
    *(uint2*)&Yl[o] = lo;
}

// =====================================================================
// wmma flash attention: 64-q tile, 256 thr, fragment-resident O,
// S pure bf16, PV bf16x3, NO online max (bounded exponents; fixed m=0),
// per-thread l accumulation reduced once at end. SMEM = 82,176 B.
// =====================================================================
#define QP 72
#define SP 68
#define ATT_SMEM (7 * 64 * QP * 2 + 64 * SP * 4 + 256)   // 82176

__global__ __launch_bounds__(256, 2) void attn_wmma_kernel(
    const __nv_bfloat16* __restrict__ Qh,
    const __nv_bfloat16* __restrict__ KVh, const __nv_bfloat16* __restrict__ KVl,
    __nv_bfloat16* __restrict__ Oh, __nv_bfloat16* __restrict__ Ol)
{
    extern __shared__ char smc[];
    __nv_bfloat16* sQh  = (__nv_bfloat16*)smc;
    __nv_bfloat16* sK_h[2] = { sQh + 64 * QP, sQh + 2 * 64 * QP };
    __nv_bfloat16* sVh  = sQh + 3 * 64 * QP;
    __nv_bfloat16* sVl  = sVh + 64 * QP;
    __nv_bfloat16* sPh  = sVl + 64 * QP;
    __nv_bfloat16* sPl  = sPh + 64 * QP;
    float* Ss = (float*)(sPl + 64 * QP);   // [64][68]

    int tid = threadIdx.x;
    int b = blockIdx.z, h = blockIdx.y, l0 = blockIdx.x * 64;
    int warp = tid >> 5;
    int wm = (warp & 1) * 32, wn = (warp >> 1) * 16;
    int ty = tid >> 4, tx = tid & 15;

    size_t kvbase = (size_t)b * NTOK * 1024 + h * 64;

    wmma::fragment<wmma::accumulator, 16, 16, 16, float> of[2];
    wmma::fill_fragment(of[0], 0.f);
    wmma::fill_fragment(of[1], 0.f);

    // pre-loop: group {Q hi + K tile 0 (hi only)}
    {
#pragma unroll
        for (int w = 0; w < 2; w++) {
            int ci = tid + w * 256;
            int row = ci >> 3, ch = ci & 7;
            const __nv_bfloat16* src = Qh +
                (((size_t)b * L_DIM) + l0 + row) * 512 + h * 64 + ch * 8;
            cp16(smem_u32(sQh + row * QP + ch * 8), src);
        }
#pragma unroll
        for (int w = 0; w < 2; w++) {
            int ci = tid + w * 256;
            int row = ci >> 3, ch = ci & 7;
            const __nv_bfloat16* src = KVh + kvbase + (size_t)row * 1024 + ch * 8;
            cp16(smem_u32(sK_h[0] + row * QP + ch * 8), src);
        }
        CP_COMMIT();
    }

    float lrow[4] = {};   // per-thread partial row sums (reduced at end)

    for (int kt = 0; kt < 36; kt++) {
        int kbase = kt * 64;
        int kb = kt & 1;
        CP_WAIT0();
        __syncthreads();

        // prefetch V(kt) hi/lo (group 1)
        {
#pragma unroll
            for (int w = 0; w < 4; w++) {
                int ci = tid + w * 256;
                int arr = ci >> 9, idx = ci & 511;
                int row = idx >> 3, ch = idx & 7;
                int kg = kbase + row;
                const __nv_bfloat16* src = (arr ? KVl : KVh) + kvbase
                    + (size_t)(kg < NTOK ? kg : 0) * 1024 + 512 + ch * 8;
                cp16z(smem_u32((arr ? sVl : sVh) + row * QP + ch * 8),
                      src, (kg < NTOK) ? 16 : 0);
            }
            CP_COMMIT();
        }
        // prefetch K(kt+1) hi only (group 2)
        if (kt + 1 < 36) {
            int nkb = (kt + 1) & 1;
#pragma unroll
            for (int w = 0; w < 2; w++) {
                int ci = tid + w * 256;
                int row = ci >> 3, ch = ci & 7;
                int kg = kbase + 64 + row;
                const __nv_bfloat16* src = KVh + kvbase
                    + (size_t)(kg < NTOK ? kg : 0) * 1024 + ch * 8;
                cp16z(smem_u32(sK_h[nkb] + row * QP + ch * 8),
                      src, (kg < NTOK) ? 16 : 0);
            }
            CP_COMMIT();
        }

        // ---- S = Qh Kh ----
        {
            wmma::fragment<wmma::accumulator, 16, 16, 16, float> sf[2];
            wmma::fill_fragment(sf[0], 0.f);
            wmma::fill_fragment(sf[1], 0.f);
#pragma unroll
            for (int k = 0; k < 4; k++) {
                wmma::fragment<wmma::matrix_b, 16, 16, 16, __nv_bfloat16, wmma::col_major> fbh;
                wmma::load_matrix_sync(fbh, sK_h[kb] + wn * QP + k * 16, QP);
#pragma unroll
                for (int mi = 0; mi < 2; mi++) {
                    wmma::fragment<wmma::matrix_a, 16, 16, 16, __nv_bfloat16, wmma::row_major> fah;
                    wmma::load_matrix_sync(fah, sQh + (wm + mi * 16) * QP + k * 16, QP);
                    wmma::mma_sync(sf[mi], fah, fbh, sf[mi]);
                }
            }
            wmma::store_matrix_sync(Ss + wm * SP + wn, sf[0], SP, wmma::mem_row_major);
            wmma::store_matrix_sync(Ss + (wm + 16) * SP + wn, sf[1], SP, wmma::mem_row_major);
        }
        __syncthreads();

        // ---- softmax numerator: p = exp2(s) (no max subtraction; bounded) ----
        bool full = (kbase + 64 <= NTOK);
#pragma unroll
        for (int i = 0; i < 4; i++) {
            int r = ty * 4 + i;
            float4 sv = *(const float4*)&Ss[r * SP + tx * 4];
            float p0, p1, p2, p3;
            if (full) {
                p0 = exp2f(sv.x); p1 = exp2f(sv.y); p2 = exp2f(sv.z); p3 = exp2f(sv.w);
            } else {
                int cg = kbase + tx * 4;
                p0 = (cg + 0 < NTOK) ? exp2f(sv.x) : 0.f;
                p1 = (cg + 1 < NTOK) ? exp2f(sv.y) : 0.f;
                p2 = (cg + 2 < NTOK) ? exp2f(sv.z) : 0.f;
                p3 = (cg + 3 < NTOK) ? exp2f(sv.w) : 0.f;
            }
            lrow[i] += p0 + p1 + p2 + p3;
            float pv[4] = { p0, p1, p2, p3 };
            uint2 hi, lo;
            split4(pv, hi, lo);
            *(uint2*)&sPh[r * QP + tx * 4] = hi;
            *(uint2*)&sPl[r * QP + tx * 4] = lo;
        }
        if (kt + 1 < 36) { CP_WAIT1(); } else { CP_WAIT0(); }
        __syncthreads();

        // ---- PV accumulate in place (bf16x3) ----
        {
#pragma unroll
            for (int k = 0; k < 4; k++) {
                wmma::fragment<wmma::matrix_b, 16, 16, 16, __nv_bfloat16, wmma::row_major> fbh, fbl;
                wmma::load_matrix_sync(fbh, sVh + k * 16 * QP + wn, QP);
                wmma::load_matrix_sync(fbl, sVl + k * 16 * QP + wn, QP);
#pragma unroll
                for (int mi = 0; mi < 2; mi++) {
                    wmma::fragment<wmma::matrix_a, 16, 16, 16, __nv_bfloat16, wmma::row_major> fah, fal;
                    wmma::load_matrix_sync(fah, sPh + (wm + mi * 16) * QP + k * 16, QP);
                    wmma::load_matrix_sync(fal, sPl + (wm + mi * 16) * QP + k * 16, QP);
                    wmma::mma_sync(of[mi], fah, fbh, of[mi]);
                    wmma::mma_sync(of[mi], fah, fbl, of[mi]);
                    wmma::mma_sync(of[mi], fal, fbh, of[mi]);
                }
            }
        }
        // next iteration's top sync orders sV/sP reads before next V prefetch
    }

    // ---- final row-sum reduction (once) ----
#pragma unroll
    for (int i = 0; i < 4; i++)
#pragma unroll
        for (int o = 8; o >= 1; o >>= 1)
            lrow[i] += __shfl_xor_sync(0xffffffffu, lrow[i], o);

    // ---- epilogue ----
    __syncthreads();
#pragma unroll
    for (int mi = 0; mi < 2; mi++)
        wmma::store_matrix_sync(Ss + (wm + mi * 16) * SP + wn, of[mi], SP, wmma::mem_row_major);
    __syncthreads();
#pragma unroll
    for (int i = 0; i < 4; i++) {
        float inv = 1.f / lrow[i];
        int r = ty * 4 + i;
        size_t o = (((size_t)b * L_DIM) + l0 + r) * C_DIM + h * HD + tx * 4;
        float4 tv = *(const float4*)&Ss[r * SP + tx * 4];
        float vv[4] = { tv.x * inv, tv.y * inv, tv.z * inv, tv.w * inv };
        uint2 hi, lo;
        split4(vv, hi, lo);
        *(uint2*)&Oh[o] = hi;
        *(uint2*)&Ol[o] = lo;
    }
}

// ---------------- launch ----------------
extern "C" void kernel_launch(void* const* d_in, const int* in_sizes, int n_in,
                              void* d_out, int out_size)
{
    const float* x    = (const float*)d_in[0];
    const float* m    = (const float*)d_in[1];
    const float* wsrc5[5] = { (const float*)d_in[2], (const float*)d_in[4], (const float*)d_in[6],
                              (const float*)d_in[8], (const float*)d_in[10] };
    const float* bsrc5[5] = { (const float*)d_in[3], (const float*)d_in[5], (const float*)d_in[7],
                              (const float*)d_in[9], (const float*)d_in[11] };
    const float* ln_g = (const float*)d_in[12];
    const float* ln_b = (const float*)d_in[13];
    const float* Wq   = (const float*)d_in[14];
    const float* Wkv  = (const float*)d_in[15];
    const float* Wp   = (const float*)d_in[16];
    const float* bp   = (const float*)d_in[17];
    float* out  = (float*)d_out;
    float* out2 = (float*)d_out + (size_t)B_DIM * L_DIM * C_DIM;

    float *P0, *P1;
    __nv_bfloat16 *P0h, *P0l, *P2h, *P2l, *mh, *ml, *Qh, *KVh, *KVl, *Oh, *Ol, *Wth, *Wtl;
    cudaGetSymbolAddress((void**)&P0,  g_P0);
    cudaGetSymbolAddress((void**)&P1,  g_P1);
    cudaGetSymbolAddress((void**)&P0h, g_P0h);
    cudaGetSymbolAddress((void**)&P0l, g_P0l);
    cudaGetSymbolAddress((void**)&P2h, g_P2h);
    cudaGetSymbolAddress((void**)&P2l, g_P2l);
    cudaGetSymbolAddress((void**)&mh,  g_mh);
    cudaGetSymbolAddress((void**)&ml,  g_ml);
    cudaGetSymbolAddress((void**)&Qh,  g_Qh);
    cudaGetSymbolAddress((void**)&KVh, g_KVh);
    cudaGetSymbolAddress((void**)&KVl, g_KVl);
    cudaGetSymbolAddress((void**)&Oh,  g_Oh);
    cudaGetSymbolAddress((void**)&Ol,  g_Ol);
    cudaGetSymbolAddress((void**)&Wth, g_Wth);
    cudaGetSymbolAddress((void**)&Wtl, g_Wtl);

    cudaFuncSetAttribute(cgemm_kernel,     cudaFuncAttributeMaxDynamicSharedMemorySize, TG_SMEM);
    cudaFuncSetAttribute(tgemm_kernel,     cudaFuncAttributeMaxDynamicSharedMemorySize, TG_SMEM);
    cudaFuncSetAttribute(attn_wmma_kernel, cudaFuncAttributeMaxDynamicSharedMemorySize, ATT_SMEM);

    wsplit8_kernel<<<dim3(32, 16, 8), dim3(32, 8)>>>(
        wsrc5[0], wsrc5[1], wsrc5[2], wsrc5[3], wsrc5[4], Wq, Wp, Wkv, Wth, Wtl);
    mcvt_kernel<<<(B_DIM * L_DIM * C_DIM / 4 + 255) / 256, 256>>>(m, mh, ml);

    pool_all_kernel<<<dim3(NP, B_DIM), 512>>>(x, P0, P0h, P0l);

    cgemm_kernel<<<dim3(4, 143), 256, TG_SMEM>>>(
        P0h, P0l, mh, ml, Wth, Wtl,
        bsrc5[0], bsrc5[1], bsrc5[2], bsrc5[3], bsrc5[4],
        P0, P1, Qh);

    mx_copy_kernel<<<dim3(8, 16, B_DIM), dim3(32, 8)>>>(P1, out2);
    ln_kernel<<<B_DIM * NP, 128>>>(P1, ln_g, ln_b, P2h, P2l);

    tgemm_kernel<<<dim3(8, (B_DIM * NTOK + 127) / 128), 256, TG_SMEM>>>(
        P2h, P2l, mh, ml, Wth + 7 * (size_t)WSLOT, Wtl + 7 * (size_t)WSLOT,
        nullptr, nullptr, KVh, KVl, B_DIM * NTOK, 1024, 2);

    attn_wmma_kernel<<<dim3(L_DIM / 64, NH, B_DIM), 256, ATT_SMEM>>>(Qh, KVh, KVl, Oh, Ol);

    tgemm_kernel<<<dim3(4, 64), 256, TG_SMEM>>>(
        Oh, Ol, nullptr, nullptr, Wth + 6 * (size_t)WSLOT, Wtl + 6 * (size_t)WSLOT,
        bp, out, nullptr, nullptr, B_DIM * L_DIM, 512, 0);
}

// round 17
// speedup vs baseline: 1.5503x; 1.0744x over previous
#include <cuda_runtime.h>
#include <cuda_bf16.h>
#include <mma.h>
#include <math.h>
#include <cstdint>

using namespace nvcuda;

#define B_DIM 8
#define L_DIM 1024
#define C_DIM 512
#define NP    1243
#define NTOK  2267
#define NH    8
#define HD    64
#define LN_EPS 1e-5f
#define OFF_MX 987
#define QSCALE 0.18033688f   // 0.125 * log2(e)

// ---------------- scratch ----------------
__device__ __align__(128) float g_P0[B_DIM * NP * C_DIM];
__device__ __align__(128) float g_P1[B_DIM * NP * C_DIM];
__device__ __align__(128) __nv_bfloat16 g_P0h[B_DIM * NP * C_DIM],    g_P0l[B_DIM * NP * C_DIM];
__device__ __align__(128) __nv_bfloat16 g_P2h[B_DIM * NP * C_DIM],    g_P2l[B_DIM * NP * C_DIM];
__device__ __align__(128) __nv_bfloat16 g_mh [B_DIM * L_DIM * C_DIM], g_ml [B_DIM * L_DIM * C_DIM];
__device__ __align__(128) __nv_bfloat16 g_Qh [B_DIM * L_DIM * C_DIM];
__device__ __align__(128) __nv_bfloat16 g_KVh[B_DIM * NTOK * 2 * C_DIM];
__device__ __align__(128) __nv_bfloat16 g_Oh [B_DIM * L_DIM * C_DIM], g_Ol [B_DIM * L_DIM * C_DIM];
#define WSLOT (512 * 512)
__device__ __align__(128) __nv_bfloat16 g_Wth[7 * WSLOT + 512 * 1024], g_Wtl[7 * WSLOT + 512 * 1024];

// ---------------- helpers ----------------
__device__ __forceinline__ uint32_t smem_u32(const void* p) {
    uint32_t a;
    asm("{ .reg .u64 t; cvta.to.shared.u64 t, %1; cvt.u32.u64 %0, t; }" : "=r"(a) : "l"(p));
    return a;
}
__device__ __forceinline__ void cp16(uint32_t dst, const void* src) {
    asm volatile("cp.async.cg.shared.global [%0], [%1], 16;" :: "r"(dst), "l"(src) : "memory");
}
__device__ __forceinline__ void cp16z(uint32_t dst, const void* src, int sz) {
    asm volatile("cp.async.cg.shared.global [%0], [%1], 16, %2;" :: "r"(dst), "l"(src), "r"(sz) : "memory");
}
#define CP_COMMIT() asm volatile("cp.async.commit_group;" ::: "memory")
#define CP_WAIT1()  asm volatile("cp.async.wait_group 1;" ::: "memory")
#define CP_WAIT0()  asm volatile("cp.async.wait_group 0;" ::: "memory")

__device__ __forceinline__ uint32_t pk2(float a, float b) {
    __nv_bfloat162 t(__float2bfloat16(a), __float2bfloat16(b));
    return *(uint32_t*)&t;
}
__device__ __forceinline__ void split4(const float* v, uint2& hi, uint2& lo) {
    __nv_bfloat16 h[4]; float r[4];
#pragma unroll
    for (int u = 0; u < 4; u++) { h[u] = __float2bfloat16(v[u]); r[u] = v[u] - __bfloat162float(h[u]); }
    __nv_bfloat162 h01(h[0], h[1]), h23(h[2], h[3]);
    hi.x = *(uint32_t*)&h01; hi.y = *(uint32_t*)&h23;
    lo.x = pk2(r[0], r[1]);  lo.y = pk2(r[2], r[3]);
}

// ---------------- combined weight transpose + split ----------------
__global__ void wsplit8_kernel(const float* W0, const float* W1, const float* W2, const float* W3,
                               const float* W4, const float* W5, const float* W6, const float* W7,
                               __nv_bfloat16* __restrict__ Th, __nv_bfloat16* __restrict__ Tl)
{
    __shared__ float t[32][33];
    int slot = blockIdx.z;
    const float* W = (slot == 0) ? W0 : (slot == 1) ? W1 : (slot == 2) ? W2 : (slot == 3) ? W3 :
                     (slot == 4) ? W4 : (slot == 5) ? W5 : (slot == 6) ? W6 : W7;
    int N = (slot == 7) ? 1024 : 512;
    int n0 = blockIdx.x * 32, k0 = blockIdx.y * 32;
    if (n0 >= N) return;
    __nv_bfloat16* th = Th + (size_t)slot * WSLOT;
    __nv_bfloat16* tl = Tl + (size_t)slot * WSLOT;
    int tx = threadIdx.x, ty = threadIdx.y;
    for (int i = ty; i < 32; i += 8) t[i][tx] = W[(size_t)(k0 + i) * N + n0 + tx];
    __syncthreads();
    for (int i = ty; i < 32; i += 8) {
        float v = t[tx][i];
        __nv_bfloat16 h = __float2bfloat16(v);
        size_t o = (size_t)(n0 + i) * 512 + k0 + tx;
        th[o] = h; tl[o] = __float2bfloat16(v - __bfloat162float(h));
    }
}

__global__ void mcvt_kernel(const float* __restrict__ m, __nv_bfloat16* __restrict__ mh,
                            __nv_bfloat16* __restrict__ ml)
{
    int i = (blockIdx.x * blockDim.x + threadIdx.x) * 4;
    if (i >= B_DIM * L_DIM * C_DIM) return;
    float4 v4 = *(const float4*)&m[i];
    float v[4] = { v4.x, v4.y, v4.z, v4.w };
    uint2 hi, lo;
    split4(v, hi, lo);
    *(uint2*)&mh[i] = hi;
    *(uint2*)&ml[i] = lo;
}

// ---------------- pooling (avg + max merged) ----------------
__global__ void pool_all_kernel(const float* __restrict__ x, float* __restrict__ P0,
                                __nv_bfloat16* __restrict__ Ph, __nv_bfloat16* __restrict__ Pl)
{
    int tok = blockIdx.x, b = blockIdx.y, c = threadIdx.x;
    float v;
    if (tok < 987) {
        int t = tok, n;
        if      (t < 441) { n = 21; }
        else if (t < 697) { n = 16; t -= 441; }
        else if (t < 866) { n = 13; t -= 697; }
        else              { n = 11; t -= 866; }
        int p = t / n, q = t - p * n;
        int hs = (p * 64) / n, he = ((p + 1) * 64 + n - 1) / n;
        int ws = (q * 64) / n, we = ((q + 1) * 64 + n - 1) / n;
        float s = 0.f;
        for (int h = hs; h < he; h++) {
            const float* xr = x + (((size_t)b * 4096) + (size_t)h * 64) * C_DIM + c;
            for (int w = ws; w < we; w++) s += xr[(size_t)w * C_DIM];
        }
        v = s / (float)((he - hs) * (we - ws));
    } else {
        int t = tok - 987;
        int p = t >> 4, q = t & 15;
        float mx = -1e30f;
        for (int h = p * 4; h < p * 4 + 4; h++) {
            const float* xr = x + (((size_t)b * 4096) + (size_t)h * 64) * C_DIM + c;
            for (int w = q * 4; w < q * 4 + 4; w++) mx = fmaxf(mx, xr[(size_t)w * C_DIM]);
        }
        v = mx;
    }
    size_t o = ((size_t)b * NP + tok) * C_DIM + c;
    P0[o] = v;
    __nv_bfloat16 h16 = __float2bfloat16(v);
    Ph[o] = h16; Pl[o] = __float2bfloat16(v - __bfloat162float(h16));
}

// =====================================================================
// GEMM mainloop (bf16x3 / bf16x2, 128x128 tile, K=512); 2 blocks/SM
// =====================================================================
#define STG0    4096
#define STG_SZ  40960
#define TG_SMEM (4096 + 2 * 40960)
#define CPITCH  136

// cgemm: conv-res (0..4, x3) + Wq (5, x2, pre-scaled, hi-only out).
__global__ __launch_bounds__(256, 2) void cgemm_kernel(
    const __nv_bfloat16* __restrict__ P0h, const __nv_bfloat16* __restrict__ P0l,
    const __nv_bfloat16* __restrict__ mh,  const __nv_bfloat16* __restrict__ ml,
    const __nv_bfloat16* __restrict__ Wth, const __nv_bfloat16* __restrict__ Wtl,
    const float* bp0, const float* bp1, const float* bp2, const float* bp3, const float* bp4,
    const float* __restrict__ P0, float* __restrict__ P1,
    __nv_bfloat16* __restrict__ Qh)
{
    extern __shared__ char sm_raw[];
    const __nv_bfloat16** aptrs = (const __nv_bfloat16**)(sm_raw + 16);
    uint32_t sb = smem_u32(sm_raw);

    int tid = threadIdx.x;
    int ti = blockIdx.y;
    int branch, tstart;
    if      (ti < 28) { branch = 0; tstart = 0;  }
    else if (ti < 44) { branch = 1; tstart = 28; }
    else if (ti < 55) { branch = 2; tstart = 44; }
    else if (ti < 63) { branch = 3; tstart = 55; }
    else if (ti < 79) { branch = 4; tstart = 63; }
    else              { branch = 5; tstart = 79; }
    const int npx_t[6]  = { 441, 256, 169, 121, 256, 0 };
    const int toff_t[6] = { 0, 441, 697, 866, 987, 0 };
    int npx = npx_t[branch], toffc = toff_t[branch];
    int M = (branch < 5) ? 8 * npx : 8192;
    int brow = (ti - tstart) * 128;
    int bcol = blockIdx.x * 128;
    bool useAl = (branch < 5);
    const float* bias = (branch == 0) ? bp0 : (branch == 1) ? bp1 : (branch == 2) ? bp2 :
                        (branch == 3) ? bp3 : (branch == 4) ? bp4 : nullptr;
    const __nv_bfloat16* Bh = Wth + (size_t)branch * WSLOT;
    const __nv_bfloat16* Bl = Wtl + (size_t)branch * WSLOT;

    if (tid < 128) {
        int arow = brow + tid;
        if (arow >= M) arow = M - 1;
        const __nv_bfloat16 *ph, *pl;
        if (branch < 5) {
            int b = arow / npx, t = arow - (arow / npx) * npx;
            size_t o = ((size_t)b * NP + toffc + t) * 512;
            ph = P0h + o; pl = P0l + o;
        } else {
            size_t o = (size_t)arow * 512;
            ph = mh + o; pl = ml + o;
        }
        aptrs[tid] = ph; aptrs[128 + tid] = pl;
    }
    __syncthreads();

    int wid = tid >> 5;
    int wm = wid & 1, wn = wid >> 1;

    wmma::fragment<wmma::accumulator, 16, 16, 16, float> acc[4][2];
#pragma unroll
    for (int mi = 0; mi < 4; mi++)
#pragma unroll
        for (int ni = 0; ni < 2; ni++)
            wmma::fill_fragment(acc[mi][ni], 0.f);

    {
        uint32_t st = sb + STG0;
#pragma unroll
        for (int w = 0; w < 8; w++) {
            int ci = tid + w * 256;
            int region = ci >> 9, idx = ci & 511;
            int row = idx >> 2, ch = idx & 3;
            const __nv_bfloat16* src;
            if (region < 2) src = aptrs[region * 128 + row] + ch * 8;
            else            src = ((region == 2) ? Bh : Bl) + (size_t)(bcol + row) * 512 + ch * 8;
            cp16(st + region * 10240 + row * 80 + ch * 16, src);
        }
        CP_COMMIT();
    }

    for (int j = 0; j < 16; j++) {
        if (j + 1 < 16) {
            uint32_t st = sb + STG0 + ((j + 1) & 1) * STG_SZ;
            int koff = (j + 1) * 32;
#pragma unroll
            for (int w = 0; w < 8; w++) {
                int ci = tid + w * 256;
                int region = ci >> 9, idx = ci & 511;
                int row = idx >> 2, ch = idx & 3;
                const __nv_bfloat16* src;
                if (region < 2) src = aptrs[region * 128 + row] + koff + ch * 8;
                else            src = ((region == 2) ? Bh : Bl) + (size_t)(bcol + row) * 512 + koff + ch * 8;
                cp16(st + region * 10240 + row * 80 + ch * 16, src);
            }
            CP_COMMIT();
            CP_WAIT1();
        } else {
            CP_WAIT0();
        }
        __syncthreads();

        const __nv_bfloat16* st = (const __nv_bfloat16*)(sm_raw + STG0 + (j & 1) * STG_SZ);
        const __nv_bfloat16* As_h = st;
        const __nv_bfloat16* As_l = st + 5120;
        const __nv_bfloat16* Bs_h = st + 10240;
        const __nv_bfloat16* Bs_l = st + 15360;

#pragma unroll
        for (int kk = 0; kk < 2; kk++) {
            wmma::fragment<wmma::matrix_a, 16, 16, 16, __nv_bfloat16, wmma::row_major> fah[4], fal[4];
            wmma::fragment<wmma::matrix_b, 16, 16, 16, __nv_bfloat16, wmma::col_major> fbh[2], fbl[2];
#pragma unroll
            for (int mi = 0; mi < 4; mi++) {
                int r = wm * 64 + mi * 16;
                wmma::load_matrix_sync(fah[mi], As_h + r * 40 + kk * 16, 40);
                if (useAl) wmma::load_matrix_sync(fal[mi], As_l + r * 40 + kk * 16, 40);
            }
#pragma unroll
            for (int ni = 0; ni < 2; ni++) {
                int c = wn * 32 + ni * 16;
                wmma::load_matrix_sync(fbh[ni], Bs_h + c * 40 + kk * 16, 40);
                wmma::load_matrix_sync(fbl[ni], Bs_l + c * 40 + kk * 16, 40);
            }
#pragma unroll
            for (int mi = 0; mi < 4; mi++)
#pragma unroll
                for (int ni = 0; ni < 2; ni++) {
                    wmma::mma_sync(acc[mi][ni], fah[mi], fbh[ni], acc[mi][ni]);
                    wmma::mma_sync(acc[mi][ni], fah[mi], fbl[ni], acc[mi][ni]);
                    if (useAl) wmma::mma_sync(acc[mi][ni], fal[mi], fbh[ni], acc[mi][ni]);
                }
        }
        __syncthreads();
    }

    float* Cs = (float*)(sm_raw + STG0);
#pragma unroll
    for (int mi = 0; mi < 4; mi++)
#pragma unroll
        for (int ni = 0; ni < 2; ni++)
            wmma::store_matrix_sync(Cs + (wm * 64 + mi * 16) * CPITCH + wn * 32 + ni * 16,
                                    acc[mi][ni], CPITCH, wmma::mem_row_major);
    __syncthreads();

    int lane = tid & 31, wrow = tid >> 5;
    for (int rr = wrow; rr < 128; rr += 8) {
        int r = brow + rr;
        if (r >= M) continue;
        int col0 = lane * 4;
        float4 o = *(float4*)&Cs[rr * CPITCH + col0];
        int col = bcol + col0;
        if (branch < 5) {
            o.x += bias[col];     o.y += bias[col + 1];
            o.z += bias[col + 2]; o.w += bias[col + 3];
            int b = r / npx, t = r - (r / npx) * npx;
            size_t g = ((size_t)b * NP + toffc + t) * 512;
            float4 rv = *(const float4*)&P0[g + col];
            o.x += rv.x; o.y += rv.y; o.z += rv.z; o.w += rv.w;
            *(float4*)&P1[g + col] = o;
        } else {
            size_t g = (size_t)r * 512 + col;
            __nv_bfloat162 h01(__float2bfloat16(o.x * QSCALE), __float2bfloat16(o.y * QSCALE));
            __nv_bfloat162 h23(__float2bfloat16(o.z * QSCALE), __float2bfloat16(o.w * QSCALE));
            uint2 hi;
            hi.x = *(uint32_t*)&h01; hi.y = *(uint32_t*)&h23;
            *(uint2*)&Qh[g] = hi;
        }
    }
}

// tgemm: generic (Wkv mode 2 — K-cols x2, hi-only out; Wp mode 0 — x3)
__global__ __launch_bounds__(256, 2) void tgemm_kernel(
    const __nv_bfloat16* __restrict__ Ah, const __nv_bfloat16* __restrict__ Al,
    const __nv_bfloat16* __restrict__ A2h, const __nv_bfloat16* __restrict__ A2l,
    const __nv_bfloat16* __restrict__ Bh, const __nv_bfloat16* __restrict__ Bl,
    const float* __restrict__ bias,
    float* __restrict__ Cout,
    __nv_bfloat16* __restrict__ outh, __nv_bfloat16* __restrict__ outl,
    int M, int N, int mode)
{
    extern __shared__ char sm_raw[];
    const __nv_bfloat16** aptrs = (const __nv_bfloat16**)(sm_raw + 16);
    uint32_t sb = smem_u32(sm_raw);

    int tid = threadIdx.x;
    int brow = blockIdx.y * 128, bcol = blockIdx.x * 128;
    bool useAl = !(mode == 2 && bcol < 512);   // K-columns of Wkv: drop Al term

    if (tid < 128) {
        int arow = brow + tid;
        if (arow >= M) arow = M - 1;
        const __nv_bfloat16 *ph, *pl;
        if (mode == 0) {
            size_t o = (size_t)arow * 512; ph = Ah + o; pl = Al + o;
        } else {
            int b = arow / NTOK, t = arow - (arow / NTOK) * NTOK;
            if (t < NP) { size_t o = ((size_t)b * NP + t) * 512; ph = Ah + o; pl = Al + o; }
            else        { size_t o = ((size_t)b * L_DIM + (t - NP)) * 512; ph = A2h + o; pl = A2l + o; }
        }
        aptrs[tid] = ph; aptrs[128 + tid] = pl;
    }
    __syncthreads();

    int wid = tid >> 5;
    int wm = wid & 1, wn = wid >> 1;

    wmma::fragment<wmma::accumulator, 16, 16, 16, float> acc[4][2];
#pragma unroll
    for (int mi = 0; mi < 4; mi++)
#pragma unroll
        for (int ni = 0; ni < 2; ni++)
            wmma::fill_fragment(acc[mi][ni], 0.f);

    {
        uint32_t st = sb + STG0;
#pragma unroll
        for (int w = 0; w < 8; w++) {
            int ci = tid + w * 256;
            int region = ci >> 9, idx = ci & 511;
            int row = idx >> 2, ch = idx & 3;
            const __nv_bfloat16* src;
            if (region < 2) src = aptrs[region * 128 + row] + ch * 8;
            else            src = ((region == 2) ? Bh : Bl) + (size_t)(bcol + row) * 512 + ch * 8;
            cp16(st + region * 10240 + row * 80 + ch * 16, src);
        }
        CP_COMMIT();
    }

    for (int j = 0; j < 16; j++) {
        if (j + 1 < 16) {
            uint32_t st = sb + STG0 + ((j + 1) & 1) * STG_SZ;
            int koff = (j + 1) * 32;
#pragma unroll
            for (int w = 0; w < 8; w++) {
                int ci = tid + w * 256;
                int region = ci >> 9, idx = ci & 511;
                int row = idx >> 2, ch = idx & 3;
                const __nv_bfloat16* src;
                if (region < 2) src = aptrs[region * 128 + row] + koff + ch * 8;
                else            src = ((region == 2) ? Bh : Bl) + (size_t)(bcol + row) * 512 + koff + ch * 8;
                cp16(st + region * 10240 + row * 80 + ch * 16, src);
            }
            CP_COMMIT();
            CP_WAIT1();
        } else {
            CP_WAIT0();
        }
        __syncthreads();

        const __nv_bfloat16* st = (const __nv_bfloat16*)(sm_raw + STG0 + (j & 1) * STG_SZ);
        const __nv_bfloat16* As_h = st;
        const __nv_bfloat16* As_l = st + 5120;
        const __nv_bfloat16* Bs_h = st + 10240;
        const __nv_bfloat16* Bs_l = st + 15360;

#pragma unroll
        for (int kk = 0; kk < 2; kk++) {
            wmma::fragment<wmma::matrix_a, 16, 16, 16, __nv_bfloat16, wmma::row_major> fah[4], fal[4];
            wmma::fragment<wmma::matrix_b, 16, 16, 16, __nv_bfloat16, wmma::col_major> fbh[2], fbl[2];
#pragma unroll
            for (int mi = 0; mi < 4; mi++) {
                int r = wm * 64 + mi * 16;
                wmma::load_matrix_sync(fah[mi], As_h + r * 40 + kk * 16, 40);
                if (useAl) wmma::load_matrix_sync(fal[mi], As_l + r * 40 + kk * 16, 40);
            }
#pragma unroll
            for (int ni = 0; ni < 2; ni++) {
                int c = wn * 32 + ni * 16;
                wmma::load_matrix_sync(fbh[ni], Bs_h + c * 40 + kk * 16, 40);
                wmma::load_matrix_sync(fbl[ni], Bs_l + c * 40 + kk * 16, 40);
            }
#pragma unroll
            for (int mi = 0; mi < 4; mi++)
#pragma unroll
                for (int ni = 0; ni < 2; ni++) {
                    wmma::mma_sync(acc[mi][ni], fah[mi], fbh[ni], acc[mi][ni]);
                    wmma::mma_sync(acc[mi][ni], fah[mi], fbl[ni], acc[mi][ni]);
                    if (useAl) wmma::mma_sync(acc[mi][ni], fal[mi], fbh[ni], acc[mi][ni]);
                }
        }
        __syncthreads();
    }

    float* Cs = (float*)(sm_raw + STG0);
#pragma unroll
    for (int mi = 0; mi < 4; mi++)
#pragma unroll
        for (int ni = 0; ni < 2; ni++)
            wmma::store_matrix_sync(Cs + (wm * 64 + mi * 16) * CPITCH + wn * 32 + ni * 16,
                                    acc[mi][ni], CPITCH, wmma::mem_row_major);
    __syncthreads();

    int lane = tid & 31, wrow = tid >> 5;
    for (int rr = wrow; rr < 128; rr += 8) {
        int r = brow + rr;
        if (r >= M) continue;
        int col0 = lane * 4;
        float4 o = *(float4*)&Cs[rr * CPITCH + col0];
        int col = bcol + col0;
        if (bias) {
            o.x += bias[col];     o.y += bias[col + 1];
            o.z += bias[col + 2]; o.w += bias[col + 3];
        }
        if (outh) {
            size_t g = (size_t)r * N + col;
            if (outl) {
                float vv[4] = { o.x, o.y, o.z, o.w };
                uint2 hi, lo;
                split4(vv, hi, lo);
                *(uint2*)&outh[g] = hi;
                *(uint2*)&outl[g] = lo;
            } else {
                __nv_bfloat162 h01(__float2bfloat16(o.x), __float2bfloat16(o.y));
                __nv_bfloat162 h23(__float2bfloat16(o.z), __float2bfloat16(o.w));
                uint2 hi;
                hi.x = *(uint32_t*)&h01; hi.y = *(uint32_t*)&h23;
                *(uint2*)&outh[g] = hi;
            }
        } else {
            *(float4*)&Cout[(size_t)r * N + col] = o;
        }
    }
}

// ---------------- mx copy (SMEM-tiled transpose) ----------------
__global__ void mx_copy_kernel(const float* __restrict__ P1, float* __restrict__ out2)
{
    __shared__ float t[32][33];
    int b = blockIdx.z;
    int t0 = blockIdx.x * 32;
    int c0 = blockIdx.y * 32;
    int tx = threadIdx.x, ty = threadIdx.y;
    for (int i = ty; i < 32; i += 8)
        t[i][tx] = P1[(((size_t)b * NP) + OFF_MX + t0 + i) * 512 + c0 + tx];
    __syncthreads();
    for (int i = ty; i < 32; i += 8)
        out2[(((size_t)b * 512) + c0 + i) * 256 + t0 + tx] = t[tx][i];
}

// ---------------- layernorm -> bf16 hi/lo ----------------
__global__ void ln_kernel(const float* __restrict__ X, const float* __restrict__ g,
                          const float* __restrict__ be,
                          __nv_bfloat16* __restrict__ Yh, __nv_bfloat16* __restrict__ Yl)
{
    int row = blockIdx.x, tid = threadIdx.x;
    float4 v = ((const float4*)(X + (size_t)row * C_DIM))[tid];
    float s  = v.x + v.y + v.z + v.w;
    float s2 = v.x * v.x + v.y * v.y + v.z * v.z + v.w * v.w;
#pragma unroll
    for (int o = 16; o >= 1; o >>= 1) {
        s  += __shfl_xor_sync(0xffffffffu, s,  o);
        s2 += __shfl_xor_sync(0xffffffffu, s2, o);
    }
    __shared__ float ws[4], ws2[4];
    int wid = tid >> 5, lane = tid & 31;
    if (lane == 0) { ws[wid] = s; ws2[wid] = s2; }
    __syncthreads();
    float ts = ws[0] + ws[1] + ws[2] + ws[3], ts2 = ws2[0] + ws2[1] + ws2[2] + ws2[3];
    float mean = ts * (1.f / C_DIM);
    float var  = ts2 * (1.f / C_DIM) - mean * mean;
    float rstd = rsqrtf(var + LN_EPS);
    float4 gg = ((const float4*)g)[tid], bb = ((const float4*)be)[tid];
    float y[4] = { (v.x - mean) * rstd * gg.x + bb.x, (v.y - mean) * rstd * gg.y + bb.y,
                   (v.z - mean) * rstd * gg.z + bb.z, (v.w - mean) * rstd * gg.w + bb.w };
    size_t o = (size_t)row * C_DIM + tid * 4;
    uint2 hi, lo;
    split4(y, hi, lo);
    *(uint2*)&Yh[o] = hi;
    *(uint2*)&Yl[o] = lo;
}

// =====================================================================
// wmma flash attention: 64-q tile, 256 thr, fragment-resident O,
// S pure bf16 (Qh·Kh), PV = (Ph+Pl)·Vh (V pure bf16), no online max,
// per-thread l reduced once at end. SMEM = 72,960 B -> 2 blocks/SM.
// =====================================================================
#define QP 72
#define SP 68
#define ATT_SMEM (6 * 64 * QP * 2 + 64 * SP * 4 + 256)   // 55296 + 17408 + 256 = 72960

__global__ __launch_bounds__(256, 2) void attn_wmma_kernel(
    const __nv_bfloat16* __restrict__ Qh,
    const __nv_bfloat16* __restrict__ KVh,
    __nv_bfloat16* __restrict__ Oh, __nv_bfloat16* __restrict__ Ol)
{
    extern __shared__ char smc[];
    __nv_bfloat16* sQh  = (__nv_bfloat16*)smc;
    __nv_bfloat16* sK_h[2] = { sQh + 64 * QP, sQh + 2 * 64 * QP };
    __nv_bfloat16* sVh  = sQh + 3 * 64 * QP;
    __nv_bfloat16* sPh  = sVh + 64 * QP;
    __nv_bfloat16* sPl  = sPh + 64 * QP;
    float* Ss = (float*)(sPl + 64 * QP);   // [64][68]

    int tid = threadIdx.x;
    int b = blockIdx.z, h = blockIdx.y, l0 = blockIdx.x * 64;
    int warp = tid >> 5;
    int wm = (warp & 1) * 32, wn = (warp >> 1) * 16;
    int ty = tid >> 4, tx = tid & 15;

    size_t kvbase = (size_t)b * NTOK * 1024 + h * 64;

    wmma::fragment<wmma::accumulator, 16, 16, 16, float> of[2];
    wmma::fill_fragment(of[0], 0.f);
    wmma::fill_fragment(of[1], 0.f);

    // pre-loop: group {Q hi + K tile 0 (hi only)}
    {
#pragma unroll
        for (int w = 0; w < 2; w++) {
            int ci = tid + w * 256;
            int row = ci >> 3, ch = ci & 7;
            const __nv_bfloat16* src = Qh +
                (((size_t)b * L_DIM) + l0 + row) * 512 + h * 64 + ch * 8;
            cp16(smem_u32(sQh + row * QP + ch * 8), src);
        }
#pragma unroll
        for (int w = 0; w < 2; w++) {
            int ci = tid + w * 256;
            int row = ci >> 3, ch = ci & 7;
            const __nv_bfloat16* src = KVh + kvbase + (size_t)row * 1024 + ch * 8;
            cp16(smem_u32(sK_h[0] + row * QP + ch * 8), src);
        }
        CP_COMMIT();
    }

    float lrow[4] = {};

    for (int kt = 0; kt < 36; kt++) {
        int kbase = kt * 64;
        int kb = kt & 1;
        CP_WAIT0();
        __syncthreads();

        // prefetch V(kt) hi only (group 1)
        {
#pragma unroll
            for (int w = 0; w < 2; w++) {
                int ci = tid + w * 256;
                int row = ci >> 3, ch = ci & 7;
                int kg = kbase + row;
                const __nv_bfloat16* src = KVh + kvbase
                    + (size_t)(kg < NTOK ? kg : 0) * 1024 + 512 + ch * 8;
                cp16z(smem_u32(sVh + row * QP + ch * 8),
                      src, (kg < NTOK) ? 16 : 0);
            }
            CP_COMMIT();
        }
        // prefetch K(kt+1) hi only (group 2)
        if (kt + 1 < 36) {
            int nkb = (kt + 1) & 1;
#pragma unroll
            for (int w = 0; w < 2; w++) {
                int ci = tid + w * 256;
                int row = ci >> 3, ch = ci & 7;
                int kg = kbase + 64 + row;
                const __nv_bfloat16* src = KVh + kvbase
                    + (size_t)(kg < NTOK ? kg : 0) * 1024 + ch * 8;
                cp16z(smem_u32(sK_h[nkb] + row * QP + ch * 8),
                      src, (kg < NTOK) ? 16 : 0);
            }
            CP_COMMIT();
        }

        // ---- S = Qh Kh ----
        {
            wmma::fragment<wmma::accumulator, 16, 16, 16, float> sf[2];
            wmma::fill_fragment(sf[0], 0.f);
            wmma::fill_fragment(sf[1], 0.f);
#pragma unroll
            for (int k = 0; k < 4; k++) {
                wmma::fragment<wmma::matrix_b, 16, 16, 16, __nv_bfloat16, wmma::col_major> fbh;
                wmma::load_matrix_sync(fbh, sK_h[kb] + wn * QP + k * 16, QP);
#pragma unroll
                for (int mi = 0; mi < 2; mi++) {
                    wmma::fragment<wmma::matrix_a, 16, 16, 16, __nv_bfloat16, wmma::row_major> fah;
                    wmma::load_matrix_sync(fah, sQh + (wm + mi * 16) * QP + k * 16, QP);
                    wmma::mma_sync(sf[mi], fah, fbh, sf[mi]);
                }
            }
            wmma::store_matrix_sync(Ss + wm * SP + wn, sf[0], SP, wmma::mem_row_major);
            wmma::store_matrix_sync(Ss + (wm + 16) * SP + wn, sf[1], SP, wmma::mem_row_major);
        }
        __syncthreads();

        // ---- softmax numerator: p = exp2(s), no max subtraction ----
        bool full = (kbase + 64 <= NTOK);
#pragma unroll
        for (int i = 0; i < 4; i++) {
            int r = ty * 4 + i;
            float4 sv = *(const float4*)&Ss[r * SP + tx * 4];
            float p0, p1, p2, p3;
            if (full) {
                p0 = exp2f(sv.x); p1 = exp2f(sv.y); p2 = exp2f(sv.z); p3 = exp2f(sv.w);
            } else {
                int cg = kbase + tx * 4;
                p0 = (cg + 0 < NTOK) ? exp2f(sv.x) : 0.f;
                p1 = (cg + 1 < NTOK) ? exp2f(sv.y) : 0.f;
                p2 = (cg + 2 < NTOK) ? exp2f(sv.z) : 0.f;
                p3 = (cg + 3 < NTOK) ? exp2f(sv.w) : 0.f;
            }
            lrow[i] += p0 + p1 + p2 + p3;
            float pv[4] = { p0, p1, p2, p3 };
            uint2 hi, lo;
            split4(pv, hi, lo);
            *(uint2*)&sPh[r * QP + tx * 4] = hi;
            *(uint2*)&sPl[r * QP + tx * 4] = lo;
        }
        if (kt + 1 < 36) { CP_WAIT1(); } else { CP_WAIT0(); }
        __syncthreads();

        // ---- PV accumulate in place: (Ph + Pl) · Vh ----
        {
#pragma unroll
            for (int k = 0; k < 4; k++) {
                wmma::fragment<wmma::matrix_b, 16, 16, 16, __nv_bfloat16, wmma::row_major> fbh;
                wmma::load_matrix_sync(fbh, sVh + k * 16 * QP + wn, QP);
#pragma unroll
                for (int mi = 0; mi < 2; mi++) {
                    wmma::fragment<wmma::matrix_a, 16, 16, 16, __nv_bfloat16, wmma::row_major> fah, fal;
                    wmma::load_matrix_sync(fah, sPh + (wm + mi * 16) * QP + k * 16, QP);
                    wmma::load_matrix_sync(fal, sPl + (wm + mi * 16) * QP + k * 16, QP);
                    wmma::mma_sync(of[mi], fah, fbh, of[mi]);
                    wmma::mma_sync(of[mi], fal, fbh, of[mi]);
                }
            }
        }
        // next iteration's top sync orders sV/sP reads before next V prefetch
    }

    // ---- final row-sum reduction (once) ----
#pragma unroll
    for (int i = 0; i < 4; i++)
#pragma unroll
        for (int o = 8; o >= 1; o >>= 1)
            lrow[i] += __shfl_xor_sync(0xffffffffu, lrow[i], o);

    // ---- epilogue ----
    __syncthreads();
#pragma unroll
    for (int mi = 0; mi < 2; mi++)
        wmma::store_matrix_sync(Ss + (wm + mi * 16) * SP + wn, of[mi], SP, wmma::mem_row_major);
    __syncthreads();
#pragma unroll
    for (int i = 0; i < 4; i++) {
        float inv = 1.f / lrow[i];
        int r = ty * 4 + i;
        size_t o = (((size_t)b * L_DIM) + l0 + r) * C_DIM + h * HD + tx * 4;
        float4 tv = *(const float4*)&Ss[r * SP + tx * 4];
        float vv[4] = { tv.x * inv, tv.y * inv, tv.z * inv, tv.w * inv };
        uint2 hi, lo;
        split4(vv, hi, lo);
        *(uint2*)&Oh[o] = hi;
        *(uint2*)&Ol[o] = lo;
    }
}

// ---------------- launch ----------------
extern "C" void kernel_launch(void* const* d_in, const int* in_sizes, int n_in,
                              void* d_out, int out_size)
{
    const float* x    = (const float*)d_in[0];
    const float* m    = (const float*)d_in[1];
    const float* wsrc5[5] = { (const float*)d_in[2], (const float*)d_in[4], (const float*)d_in[6],
                              (const float*)d_in[8], (const float*)d_in[10] };
    const float* bsrc5[5] = { (const float*)d_in[3], (const float*)d_in[5], (const float*)d_in[7],
                              (const float*)d_in[9], (const float*)d_in[11] };
    const float* ln_g = (const float*)d_in[12];
    const float* ln_b = (const float*)d_in[13];
    const float* Wq   = (const float*)d_in[14];
    const float* Wkv  = (const float*)d_in[15];
    const float* Wp   = (const float*)d_in[16];
    const float* bp   = (const float*)d_in[17];
    float* out  = (float*)d_out;
    float* out2 = (float*)d_out + (size_t)B_DIM * L_DIM * C_DIM;

    float *P0, *P1;
    __nv_bfloat16 *P0h, *P0l, *P2h, *P2l, *mh, *ml, *Qh, *KVh, *Oh, *Ol, *Wth, *Wtl;
    cudaGetSymbolAddress((void**)&P0,  g_P0);
    cudaGetSymbolAddress((void**)&P1,  g_P1);
    cudaGetSymbolAddress((void**)&P0h, g_P0h);
    cudaGetSymbolAddress((void**)&P0l, g_P0l);
    cudaGetSymbolAddress((void**)&P2h, g_P2h);
    cudaGetSymbolAddress((void**)&P2l, g_P2l);
    cudaGetSymbolAddress((void**)&mh,  g_mh);
    cudaGetSymbolAddress((void**)&ml,  g_ml);
    cudaGetSymbolAddress((void**)&Qh,  g_Qh);
    cudaGetSymbolAddress((void**)&KVh, g_KVh);
    cudaGetSymbolAddress((void**)&Oh,  g_Oh);
    cudaGetSymbolAddress((void**)&Ol,  g_Ol);
    cudaGetSymbolAddress((void**)&Wth, g_Wth);
    cudaGetSymbolAddress((void**)&Wtl, g_Wtl);

    cudaFuncSetAttribute(cgemm_kernel,     cudaFuncAttributeMaxDynamicSharedMemorySize, TG_SMEM);
    cudaFuncSetAttribute(tgemm_kernel,     cudaFuncAttributeMaxDynamicSharedMemorySize, TG_SMEM);
    cudaFuncSetAttribute(attn_wmma_kernel, cudaFuncAttributeMaxDynamicSharedMemorySize, ATT_SMEM);

    wsplit8_kernel<<<dim3(32, 16, 8), dim3(32, 8)>>>(
        wsrc5[0], wsrc5[1], wsrc5[2], wsrc5[3], wsrc5[4], Wq, Wp, Wkv, Wth, Wtl);
    mcvt_kernel<<<(B_DIM * L_DIM * C_DIM / 4 + 255) / 256, 256>>>(m, mh, ml);

    pool_all_kernel<<<dim3(NP, B_DIM), 512>>>(x, P0, P0h, P0l);

    cgemm_kernel<<<dim3(4, 143), 256, TG_SMEM>>>(
        P0h, P0l, mh, ml, Wth, Wtl,
        bsrc5[0], bsrc5[1], bsrc5[2], bsrc5[3], bsrc5[4],
        P0, P1, Qh);

    mx_copy_kernel<<<dim3(8, 16, B_DIM), dim3(32, 8)>>>(P1, out2);
    ln_kernel<<<B_DIM * NP, 128>>>(P1, ln_g, ln_b, P2h, P2l);

    // kv = [p; m] @ Wkv -> bf16 hi only (attention reads hi exclusively)
    tgemm_kernel<<<dim3(8, (B_DIM * NTOK + 127) / 128), 256, TG_SMEM>>>(
        P2h, P2l, mh, ml, Wth + 7 * (size_t)WSLOT, Wtl + 7 * (size_t)WSLOT,
        nullptr, nullptr, KVh, nullptr, B_DIM * NTOK, 1024, 2);

    attn_wmma_kernel<<<dim3(L_DIM / 64, NH, B_DIM), 256, ATT_SMEM>>>(Qh, KVh, Oh, Ol);

    tgemm_kernel<<<dim3(4, 64), 256, TG_SMEM>>>(
        Oh, Ol, nullptr, nullptr, Wth + 6 * (size_t)WSLOT, Wtl + 6 * (size_t)WSLOT,
        bp, out, nullptr, nullptr, B_DIM * L_DIM, 512, 0);
}